// round 11
// baseline (speedup 1.0000x reference)
#include <cuda_runtime.h>
#include <cuda_bf16.h>
#include <cuda_fp16.h>
#include <math.h>
#include <stdint.h>

// Model dims
#define BB   2
#define TT   1024
#define DD   1024
#define HH   16
#define HDIM 64
#define LL   8
#define VV   32000
#define MM   (BB*TT)   // 2048 tokens

typedef __nv_bfloat16 bf16;
typedef __nv_bfloat162 bf162;

// GEMM tiling
#define BN 128
#define BK 32
#define NSTAGE 3

// Attention tiling
#define AQ  128
#define AKT 64
#define LDV 72
#define NEGINF (-1e30f)

// fp32 scratch
__device__ float g_x  [MM * DD];
__device__ float g_qkv[MM * 3 * DD];
// 16-bit activation scratch
__device__ bf16 g_h_hi[MM * DD],     g_h_lo[MM * DD];
__device__ bf16 g_y_hi[MM * DD],     g_y_lo[MM * DD];
__device__ bf16 g_g_hi[MM * 4 * DD], g_g_lo[MM * 4 * DD];   // fp16 payload
// weight scratch
__device__ bf16 g_qkvw_hi[LL * 3 * DD * DD], g_qkvw_lo[LL * 3 * DD * DD];
__device__ bf16 g_projw_hi[LL * DD * DD],    g_projw_lo[LL * DD * DD];
__device__ bf16 g_fcw_hi [LL * 4 * DD * DD];                 // fp16 payload, single
__device__ bf16 g_fc2w_hi[LL * 4 * DD * DD];                 // fp16 payload, single
__device__ bf16 g_lmw_hi [VV * DD];                          // fp16 payload, single

// ---------------------------------------------------------------------------
// Small helpers
// ---------------------------------------------------------------------------
__device__ __forceinline__ void split2u(float x, float y, uint32_t& hi, uint32_t& lo) {
    bf162 hp, lp;
    hp.x = __float2bfloat16(x); hp.y = __float2bfloat16(y);
    lp.x = __float2bfloat16(x - __bfloat162float(hp.x));
    lp.y = __float2bfloat16(y - __bfloat162float(hp.y));
    hi = *(uint32_t*)&hp; lo = *(uint32_t*)&lp;
}

__device__ __forceinline__ void split2h(float x, float y, uint32_t& hi, uint32_t& lo) {
    __half2 hp, lp;
    hp.x = __float2half_rn(x); hp.y = __float2half_rn(y);
    lp.x = __float2half_rn(x - __half2float(hp.x));
    lp.y = __float2half_rn(y - __half2float(hp.y));
    hi = *(uint32_t*)&hp; lo = *(uint32_t*)&lp;
}

__device__ __forceinline__ void ldm_x4(uint32_t& r0, uint32_t& r1, uint32_t& r2, uint32_t& r3,
                                       uint32_t addr) {
    asm volatile("ldmatrix.sync.aligned.m8n8.x4.shared.b16 {%0,%1,%2,%3}, [%4];\n"
                 : "=r"(r0), "=r"(r1), "=r"(r2), "=r"(r3) : "r"(addr));
}

__device__ __forceinline__ void ldm_x4_t(uint32_t& r0, uint32_t& r1, uint32_t& r2, uint32_t& r3,
                                         uint32_t addr) {
    asm volatile("ldmatrix.sync.aligned.m8n8.x4.trans.shared.b16 {%0,%1,%2,%3}, [%4];\n"
                 : "=r"(r0), "=r"(r1), "=r"(r2), "=r"(r3) : "r"(addr));
}

__device__ __forceinline__ void mma16816(float* d, const uint32_t* a, const uint32_t* b) {
    asm volatile(
        "mma.sync.aligned.m16n8k16.row.col.f32.bf16.bf16.f32 "
        "{%0,%1,%2,%3}, {%4,%5,%6,%7}, {%8,%9}, {%0,%1,%2,%3};\n"
        : "+f"(d[0]), "+f"(d[1]), "+f"(d[2]), "+f"(d[3])
        : "r"(a[0]), "r"(a[1]), "r"(a[2]), "r"(a[3]), "r"(b[0]), "r"(b[1]));
}

__device__ __forceinline__ void mma16816h(float* d, const uint32_t* a, const uint32_t* b) {
    asm volatile(
        "mma.sync.aligned.m16n8k16.row.col.f32.f16.f16.f32 "
        "{%0,%1,%2,%3}, {%4,%5,%6,%7}, {%8,%9}, {%0,%1,%2,%3};\n"
        : "+f"(d[0]), "+f"(d[1]), "+f"(d[2]), "+f"(d[3])
        : "r"(a[0]), "r"(a[1]), "r"(a[2]), "r"(a[3]), "r"(b[0]), "r"(b[1]));
}

__device__ __forceinline__ void cp16(uint32_t dst, const void* src) {
    asm volatile("cp.async.cg.shared.global [%0], [%1], 16;\n" :: "r"(dst), "l"(src));
}

// swizzled byte offset within one Rx32(16-bit) tile: row r, 16B chunk c (0..3)
__device__ __forceinline__ uint32_t swz(int r, int c) {
    return (uint32_t)(r * 64 + ((c ^ ((r >> 1) & 3)) << 4));
}

// ---------------------------------------------------------------------------
// Fused weight split. Cases 0-1: bf16 hi/lo. Cases 2-4: fp16 single.
// ---------------------------------------------------------------------------
__global__ void wsplit_all(const float* s0, bf16* h0, bf16* l0, int n0,
                           const float* s1, bf16* h1, bf16* l1, int n1,
                           const float* s2, bf16* h2, int n2,
                           const float* s3, bf16* h3, int n3,
                           const float* s4, bf16* h4, int n4) {
    int i = (blockIdx.x * blockDim.x + threadIdx.x) * 4;
    if (blockIdx.y >= 2) {
        const float* src; __half* hi; int n;
        if (blockIdx.y == 2)      { src = s2; hi = (__half*)h2; n = n2; }
        else if (blockIdx.y == 3) { src = s3; hi = (__half*)h3; n = n3; }
        else                      { src = s4; hi = (__half*)h4; n = n4; }
        if (i >= n) return;
        float4 v = *(const float4*)(src + i);
        __half2 p0, p1;
        p0.x = __float2half_rn(v.x); p0.y = __float2half_rn(v.y);
        p1.x = __float2half_rn(v.z); p1.y = __float2half_rn(v.w);
        ((__half2*)(hi + i))[0] = p0;
        ((__half2*)(hi + i))[1] = p1;
        return;
    }
    const float* src; bf16* hi; bf16* lo; int n;
    if (blockIdx.y == 0) { src = s0; hi = h0; lo = l0; n = n0; }
    else                 { src = s1; hi = h1; lo = l1; n = n1; }
    if (i >= n) return;
    float4 v = *(const float4*)(src + i);
    uint32_t hh, ll;
    split2u(v.x, v.y, hh, ll);
    ((uint32_t*)(hi + i))[0] = hh; ((uint32_t*)(lo + i))[0] = ll;
    split2u(v.z, v.w, hh, ll);
    ((uint32_t*)(hi + i))[1] = hh; ((uint32_t*)(lo + i))[1] = ll;
}

// ---------------------------------------------------------------------------
// Embedding
// ---------------------------------------------------------------------------
__global__ void embed_kernel(const int* __restrict__ idx,
                             const float* __restrict__ wte,
                             const float* __restrict__ wpe,
                             float* __restrict__ x) {
    int token = blockIdx.x;
    int t = token % TT;
    int id = idx[token];
    const float4* src = (const float4*)(wte + (size_t)id * DD);
    const float4* pos = (const float4*)(wpe + (size_t)t * DD);
    float4* dst = (float4*)(x + (size_t)token * DD);
    for (int i = threadIdx.x; i < DD / 4; i += blockDim.x) {
        float4 a = src[i], b = pos[i];
        dst[i] = make_float4(a.x + b.x, a.y + b.y, a.z + b.z, a.w + b.w);
    }
}

// ---------------------------------------------------------------------------
// LayerNorm over D=1024 -> 16-bit hi/lo (bf16 when h16=0, fp16 when h16=1)
// ---------------------------------------------------------------------------
__global__ __launch_bounds__(256) void ln_split_kernel(const float* __restrict__ x,
                                                       const float* __restrict__ sc,
                                                       const float* __restrict__ bi,
                                                       bf16* __restrict__ ohi,
                                                       bf16* __restrict__ olo,
                                                       int h16) {
    int token = blockIdx.x;
    const float4* xp = (const float4*)(x + (size_t)token * DD);
    float4 v = xp[threadIdx.x];
    float s = v.x + v.y + v.z + v.w;
    float q = v.x * v.x + v.y * v.y + v.z * v.z + v.w * v.w;
#pragma unroll
    for (int o = 16; o; o >>= 1) {
        s += __shfl_xor_sync(0xffffffffu, s, o);
        q += __shfl_xor_sync(0xffffffffu, q, o);
    }
    __shared__ float ss[8], sq[8];
    int w = threadIdx.x >> 5, l = threadIdx.x & 31;
    if (l == 0) { ss[w] = s; sq[w] = q; }
    __syncthreads();
    if (w == 0) {
        s = (l < 8) ? ss[l] : 0.f;
        q = (l < 8) ? sq[l] : 0.f;
#pragma unroll
        for (int o = 4; o; o >>= 1) {
            s += __shfl_xor_sync(0xffffffffu, s, o);
            q += __shfl_xor_sync(0xffffffffu, q, o);
        }
        if (l == 0) { ss[0] = s; sq[0] = q; }
    }
    __syncthreads();
    float mu  = ss[0] * (1.f / DD);
    float var = sq[0] * (1.f / DD) - mu * mu;
    float inv = rsqrtf(var + 1e-5f);
    float4 sv = ((const float4*)sc)[threadIdx.x];
    float4 bv = ((const float4*)bi)[threadIdx.x];
    float r0 = (v.x - mu) * inv * sv.x + bv.x;
    float r1 = (v.y - mu) * inv * sv.y + bv.y;
    float r2 = (v.z - mu) * inv * sv.z + bv.z;
    float r3 = (v.w - mu) * inv * sv.w + bv.w;
    size_t o = (size_t)token * DD + threadIdx.x * 4;
    uint32_t hh, ll;
    if (h16) {
        split2h(r0, r1, hh, ll);
        ((uint32_t*)(ohi + o))[0] = hh; ((uint32_t*)(olo + o))[0] = ll;
        split2h(r2, r3, hh, ll);
        ((uint32_t*)(ohi + o))[1] = hh; ((uint32_t*)(olo + o))[1] = ll;
    } else {
        split2u(r0, r1, hh, ll);
        ((uint32_t*)(ohi + o))[0] = hh; ((uint32_t*)(olo + o))[0] = ll;
        split2u(r2, r3, hh, ll);
        ((uint32_t*)(ohi + o))[1] = hh; ((uint32_t*)(olo + o))[1] = ll;
    }
}

// ---------------------------------------------------------------------------
#define FLAG_BIAS  1
#define FLAG_RES   2
#define FLAG_GELU  4
#define FLAG_SPLIT 8   // write C as fp16 hi/lo

__device__ __forceinline__ float gelu_exact(float v) {
    return 0.5f * v * (1.f + erff(v * 0.70710678118654752f));
}

// ---------------------------------------------------------------------------
// bf16 3-pass GEMM NT (trunk): CTA (MF*32)x128, warp (MF*16)x32, BK=32.
// ---------------------------------------------------------------------------
template<int MF>
__global__ __launch_bounds__(256) void gemm3t(const bf16* __restrict__ Ah,
                                              const bf16* __restrict__ Al,
                                              const bf16* __restrict__ Bh,
                                              const bf16* __restrict__ Bl,
                                              const float* __restrict__ bias,
                                              const float* res,
                                              float* C,
                                              int M, int N, int K, int flags) {
    constexpr int BMT   = MF * 32;
    constexpr int TILEA = BMT * 64;
    constexpr int TILEBB = 8192;
    constexpr int BUFB  = 2 * TILEA + 2 * TILEBB;
    constexpr int NCHUNK = (2 * BMT * 4 + 2 * 512) / 256;

    extern __shared__ __align__(16) bf16 sm[];
    int tid = threadIdx.x;
    int warp = tid >> 5, lane = tid & 31;
    int bm = blockIdx.y * BMT, bn = blockIdx.x * BN;
    int wm = (warp >> 2) * (MF * 16);
    int wn = (warp & 3) * 32;

    uint32_t smbase = (uint32_t)__cvta_generic_to_shared(sm);

    float acc[MF][4][4];
#pragma unroll
    for (int i = 0; i < MF; i++)
#pragma unroll
        for (int j = 0; j < 4; j++)
#pragma unroll
            for (int r = 0; r < 4; r++) acc[i][j][r] = 0.f;

    int a_r = ((lane >> 3) & 1) * 8 + (lane & 7);
    int a_c = (lane >> 4) * 8;
    int b_r = (lane >> 4) * 8 + (lane & 7);
    int b_c = ((lane >> 3) & 1) * 8;

    const bf16* srcA[2] = { Ah, Al };
    const bf16* srcB[2] = { Bh, Bl };

    auto stage = [&](int s_idx, int buf) {
        int k0 = s_idx * BK;
        uint32_t bufoff = smbase + (uint32_t)(buf * BUFB);
#pragma unroll
        for (int i = 0; i < NCHUNK; i++) {
            int cid = tid + i * 256;
            if (cid < 2 * BMT * 4) {
                int arr = cid / (BMT * 4);
                int sub = cid - arr * (BMT * 4);
                int row = sub >> 2;
                int c = sub & 3;
                const bf16* src = srcA[arr] + (size_t)(bm + row) * K + k0 + c * 8;
                cp16(bufoff + (uint32_t)(arr * TILEA) + swz(row, c), src);
            } else {
                int cidB = cid - 2 * BMT * 4;
                int arr = cidB >> 9;
                int sub = cidB & 511;
                int row = sub >> 2;
                int c = sub & 3;
                const bf16* src = srcB[arr] + (size_t)(bn + row) * K + k0 + c * 8;
                cp16(bufoff + (uint32_t)(2 * TILEA + arr * TILEBB) + swz(row, c), src);
            }
        }
        asm volatile("cp.async.commit_group;\n");
    };

    int S = K / BK;
    stage(0, 0);
    stage(1, 1);

    for (int s = 0; s < S; s++) {
        int buf = s - (s / NSTAGE) * NSTAGE;
        if (s == S - 1) asm volatile("cp.async.wait_group 0;\n");
        else            asm volatile("cp.async.wait_group 1;\n");
        __syncthreads();
        if (s + 2 < S) stage(s + 2, (s + 2) % NSTAGE);

        uint32_t offAh = smbase + (uint32_t)(buf * BUFB);
        uint32_t offAl = offAh + TILEA;
        uint32_t offBh = offAl + TILEA;
        uint32_t offBl = offBh + TILEBB;

#pragma unroll
        for (int ks = 0; ks < BK; ks += 16) {
            uint32_t ah[MF][4], al[MF][4], bh[4][2], bl[4][2];
#pragma unroll
            for (int mf = 0; mf < MF; mf++) {
                int row = wm + mf * 16 + a_r;
                ldm_x4(ah[mf][0], ah[mf][1], ah[mf][2], ah[mf][3],
                       offAh + swz(row, (ks + a_c) >> 3));
            }
#pragma unroll
            for (int p = 0; p < 2; p++) {
                int row = wn + p * 16 + b_r;
                uint32_t r0, r1, r2, r3;
                ldm_x4(r0, r1, r2, r3, offBh + swz(row, (ks + b_c) >> 3));
                bh[2 * p][0] = r0; bh[2 * p][1] = r1;
                bh[2 * p + 1][0] = r2; bh[2 * p + 1][1] = r3;
            }
#pragma unroll
            for (int mf = 0; mf < MF; mf++)
#pragma unroll
                for (int nf = 0; nf < 4; nf++)
                    mma16816(acc[mf][nf], ah[mf], bh[nf]);

#pragma unroll
            for (int p = 0; p < 2; p++) {
                int row = wn + p * 16 + b_r;
                uint32_t r0, r1, r2, r3;
                ldm_x4(r0, r1, r2, r3, offBl + swz(row, (ks + b_c) >> 3));
                bl[2 * p][0] = r0; bl[2 * p][1] = r1;
                bl[2 * p + 1][0] = r2; bl[2 * p + 1][1] = r3;
            }
#pragma unroll
            for (int mf = 0; mf < MF; mf++)
#pragma unroll
                for (int nf = 0; nf < 4; nf++)
                    mma16816(acc[mf][nf], ah[mf], bl[nf]);

#pragma unroll
            for (int mf = 0; mf < MF; mf++) {
                int row = wm + mf * 16 + a_r;
                ldm_x4(al[mf][0], al[mf][1], al[mf][2], al[mf][3],
                       offAl + swz(row, (ks + a_c) >> 3));
            }
#pragma unroll
            for (int mf = 0; mf < MF; mf++)
#pragma unroll
                for (int nf = 0; nf < 4; nf++)
                    mma16816(acc[mf][nf], al[mf], bh[nf]);
        }
    }

    int gid = lane >> 2, tg = lane & 3;
#pragma unroll
    for (int mf = 0; mf < MF; mf++) {
#pragma unroll
        for (int half = 0; half < 2; half++) {
            int row = bm + wm + mf * 16 + half * 8 + gid;
#pragma unroll
            for (int nf = 0; nf < 4; nf++) {
                int col = bn + wn + nf * 8 + tg * 2;
                float2 o;
                o.x = acc[mf][nf][half * 2 + 0];
                o.y = acc[mf][nf][half * 2 + 1];
                if (flags & FLAG_BIAS) { o.x += bias[col]; o.y += bias[col + 1]; }
                if (flags & FLAG_RES) {
                    float2 r = *(const float2*)(res + (size_t)row * N + col);
                    o.x += r.x; o.y += r.y;
                }
                *(float2*)(C + (size_t)row * N + col) = o;
            }
        }
    }
}

// ---------------------------------------------------------------------------
// fp16 2-pass GEMM NT: D = Ah*Bh + Al*Bh  (A split fp16, B single fp16).
// Epilogue supports bias/res/gelu and fp16-split output.
// ---------------------------------------------------------------------------
template<int MF>
__global__ __launch_bounds__(256) void gemm2h(const __half* __restrict__ Ah,
                                              const __half* __restrict__ Al,
                                              const __half* __restrict__ Bh,
                                              const float* __restrict__ bias,
                                              const float* res,
                                              float* C, __half* Chi, __half* Clo,
                                              int M, int N, int K, int flags) {
    constexpr int BMT   = MF * 32;
    constexpr int TILEA = BMT * 64;
    constexpr int TILEBB = 8192;
    constexpr int BUFB  = 2 * TILEA + TILEBB;
    constexpr int NCHUNK = (2 * BMT * 4 + 512) / 256;

    extern __shared__ __align__(16) bf16 sm[];
    int tid = threadIdx.x;
    int warp = tid >> 5, lane = tid & 31;
    int bm = blockIdx.y * BMT, bn = blockIdx.x * BN;
    int wm = (warp >> 2) * (MF * 16);
    int wn = (warp & 3) * 32;

    uint32_t smbase = (uint32_t)__cvta_generic_to_shared(sm);

    float acc[MF][4][4];
#pragma unroll
    for (int i = 0; i < MF; i++)
#pragma unroll
        for (int j = 0; j < 4; j++)
#pragma unroll
            for (int r = 0; r < 4; r++) acc[i][j][r] = 0.f;

    int a_r = ((lane >> 3) & 1) * 8 + (lane & 7);
    int a_c = (lane >> 4) * 8;
    int b_r = (lane >> 4) * 8 + (lane & 7);
    int b_c = ((lane >> 3) & 1) * 8;

    const __half* srcA[2] = { Ah, Al };

    auto stage = [&](int s_idx, int buf) {
        int k0 = s_idx * BK;
        uint32_t bufoff = smbase + (uint32_t)(buf * BUFB);
#pragma unroll
        for (int i = 0; i < NCHUNK; i++) {
            int cid = tid + i * 256;
            if (cid < 2 * BMT * 4) {
                int arr = cid / (BMT * 4);
                int sub = cid - arr * (BMT * 4);
                int row = sub >> 2;
                int c = sub & 3;
                const __half* src = srcA[arr] + (size_t)(bm + row) * K + k0 + c * 8;
                cp16(bufoff + (uint32_t)(arr * TILEA) + swz(row, c), src);
            } else {
                int sub = cid - 2 * BMT * 4;
                int row = sub >> 2;
                int c = sub & 3;
                const __half* src = Bh + (size_t)(bn + row) * K + k0 + c * 8;
                cp16(bufoff + (uint32_t)(2 * TILEA) + swz(row, c), src);
            }
        }
        asm volatile("cp.async.commit_group;\n");
    };

    int S = K / BK;
    stage(0, 0);
    stage(1, 1);

    for (int s = 0; s < S; s++) {
        int buf = s - (s / NSTAGE) * NSTAGE;
        if (s == S - 1) asm volatile("cp.async.wait_group 0;\n");
        else            asm volatile("cp.async.wait_group 1;\n");
        __syncthreads();
        if (s + 2 < S) stage(s + 2, (s + 2) % NSTAGE);

        uint32_t offAh = smbase + (uint32_t)(buf * BUFB);
        uint32_t offAl = offAh + TILEA;
        uint32_t offB  = offAl + TILEA;

#pragma unroll
        for (int ks = 0; ks < BK; ks += 16) {
            uint32_t ah[MF][4], al[MF][4], bh[4][2];
#pragma unroll
            for (int mf = 0; mf < MF; mf++) {
                int row = wm + mf * 16 + a_r;
                ldm_x4(ah[mf][0], ah[mf][1], ah[mf][2], ah[mf][3],
                       offAh + swz(row, (ks + a_c) >> 3));
            }
#pragma unroll
            for (int p = 0; p < 2; p++) {
                int row = wn + p * 16 + b_r;
                uint32_t r0, r1, r2, r3;
                ldm_x4(r0, r1, r2, r3, offB + swz(row, (ks + b_c) >> 3));
                bh[2 * p][0] = r0; bh[2 * p][1] = r1;
                bh[2 * p + 1][0] = r2; bh[2 * p + 1][1] = r3;
            }
#pragma unroll
            for (int mf = 0; mf < MF; mf++)
#pragma unroll
                for (int nf = 0; nf < 4; nf++)
                    mma16816h(acc[mf][nf], ah[mf], bh[nf]);

#pragma unroll
            for (int mf = 0; mf < MF; mf++) {
                int row = wm + mf * 16 + a_r;
                ldm_x4(al[mf][0], al[mf][1], al[mf][2], al[mf][3],
                       offAl + swz(row, (ks + a_c) >> 3));
            }
#pragma unroll
            for (int mf = 0; mf < MF; mf++)
#pragma unroll
                for (int nf = 0; nf < 4; nf++)
                    mma16816h(acc[mf][nf], al[mf], bh[nf]);
        }
    }

    int gid = lane >> 2, tg = lane & 3;
#pragma unroll
    for (int mf = 0; mf < MF; mf++) {
#pragma unroll
        for (int half = 0; half < 2; half++) {
            int row = bm + wm + mf * 16 + half * 8 + gid;
#pragma unroll
            for (int nf = 0; nf < 4; nf++) {
                int col = bn + wn + nf * 8 + tg * 2;
                float2 o;
                o.x = acc[mf][nf][half * 2 + 0];
                o.y = acc[mf][nf][half * 2 + 1];
                if (flags & FLAG_BIAS) { o.x += bias[col]; o.y += bias[col + 1]; }
                if (flags & FLAG_GELU) { o.x = gelu_exact(o.x); o.y = gelu_exact(o.y); }
                if (flags & FLAG_RES) {
                    float2 r = *(const float2*)(res + (size_t)row * N + col);
                    o.x += r.x; o.y += r.y;
                }
                if (flags & FLAG_SPLIT) {
                    size_t off = (size_t)row * N + col;
                    uint32_t hh, ll;
                    split2h(o.x, o.y, hh, ll);
                    *(uint32_t*)(Chi + off) = hh;
                    *(uint32_t*)(Clo + off) = ll;
                } else {
                    *(float2*)(C + (size_t)row * N + col) = o;
                }
            }
        }
    }
}

// Dynamic smem sizes
#define GSM3_MF2 (NSTAGE * (2 * 64 * 64 + 2 * 8192))    // 73728
#define GSM2_MF2 (NSTAGE * (2 * 64 * 64 + 8192))        // 49152
#define GSM2_MF4 (NSTAGE * (2 * 128 * 64 + 8192))       // 73728

// ---------------------------------------------------------------------------
// Causal attention via mma.sync (flash-attention, bf16-split fp32-accurate).
// ---------------------------------------------------------------------------
__global__ __launch_bounds__(256) void attn_mma(const float* __restrict__ qkv,
                                                bf16* __restrict__ yhi,
                                                bf16* __restrict__ ylo) {
    int b = blockIdx.z, h = blockIdx.y;
    int bx = gridDim.x - 1 - blockIdx.x;
    int tid = threadIdx.x;
    int warp = tid >> 5, lane = tid & 31;
    int g = lane >> 2, t4 = lane & 3;
    int q0w = bx * AQ + warp * 16;

    __shared__ __align__(16) bf16 Kh_s[AKT * LDV];
    __shared__ __align__(16) bf16 Kl_s[AKT * LDV];
    __shared__ __align__(16) bf16 Vh_s[AKT * LDV];
    __shared__ __align__(16) bf16 Vl_s[AKT * LDV];
    uint32_t aKh = (uint32_t)__cvta_generic_to_shared(Kh_s);
    uint32_t aKl = (uint32_t)__cvta_generic_to_shared(Kl_s);
    uint32_t aVh = (uint32_t)__cvta_generic_to_shared(Vh_s);
    uint32_t aVl = (uint32_t)__cvta_generic_to_shared(Vl_s);

    uint32_t qh[4][4], ql[4][4];
    {
        const float* qbase = qkv + (size_t)(b * TT) * (3 * DD) + h * HDIM;
        const float* r0p = qbase + (size_t)(q0w + g) * (3 * DD);
        const float* r1p = qbase + (size_t)(q0w + g + 8) * (3 * DD);
#pragma unroll
        for (int c = 0; c < 4; c++) {
            float2 v00 = *(const float2*)(r0p + c * 16 + 2 * t4);
            float2 v10 = *(const float2*)(r1p + c * 16 + 2 * t4);
            float2 v01 = *(const float2*)(r0p + c * 16 + 2 * t4 + 8);
            float2 v11 = *(const float2*)(r1p + c * 16 + 2 * t4 + 8);
            split2u(v00.x * 0.125f, v00.y * 0.125f, qh[c][0], ql[c][0]);
            split2u(v10.x * 0.125f, v10.y * 0.125f, qh[c][1], ql[c][1]);
            split2u(v01.x * 0.125f, v01.y * 0.125f, qh[c][2], ql[c][2]);
            split2u(v11.x * 0.125f, v11.y * 0.125f, qh[c][3], ql[c][3]);
        }
    }

    float O[8][4];
#pragma unroll
    for (int j = 0; j < 8; j++)
#pragma unroll
        for (int r = 0; r < 4; r++) O[j][r] = 0.f;
    float m0 = NEGINF, m1 = NEGINF, l0 = 0.f, l1 = 0.f;

    int b_r = (lane >> 4) * 8 + (lane & 7);
    int b_c = ((lane >> 3) & 1) * 8;
    int v_r = (lane & 7) + ((lane >> 3) & 1) * 8;
    int v_c = (lane >> 4) * 8;

    const float* kb = qkv + (size_t)(b * TT) * (3 * DD) + DD + h * HDIM;
    const float* vb = kb + DD;

    int ntiles = bx * 2 + 2;
    for (int tile = 0; tile < ntiles; tile++) {
        int kt = tile * AKT;
        __syncthreads();
#pragma unroll
        for (int i = 0; i < 8; i++) {
            int cid = tid + i * 256;
            int kk = cid >> 5;
            int d2 = (cid & 31) * 2;
            const float* kr = kb + (size_t)(kt + kk) * (3 * DD) + d2;
            const float* vr = vb + (size_t)(kt + kk) * (3 * DD) + d2;
            float2 kv = *(const float2*)kr;
            float2 vv = *(const float2*)vr;
            uint32_t hh, ll;
            split2u(kv.x, kv.y, hh, ll);
            *(uint32_t*)(Kh_s + kk * LDV + d2) = hh;
            *(uint32_t*)(Kl_s + kk * LDV + d2) = ll;
            split2u(vv.x, vv.y, hh, ll);
            *(uint32_t*)(Vh_s + kk * LDV + d2) = hh;
            *(uint32_t*)(Vl_s + kk * LDV + d2) = ll;
        }
        __syncthreads();

        if (kt > q0w + 15) continue;

        float S[8][4];
#pragma unroll
        for (int j = 0; j < 8; j++)
#pragma unroll
            for (int r = 0; r < 4; r++) S[j][r] = 0.f;

#pragma unroll
        for (int c = 0; c < 4; c++) {
            uint32_t kf[8][2];
#pragma unroll
            for (int p = 0; p < 4; p++) {
                uint32_t r0, r1, r2, r3;
                ldm_x4(r0, r1, r2, r3, aKh + (uint32_t)((16 * p + b_r) * LDV + 16 * c + b_c) * 2);
                kf[2 * p][0] = r0; kf[2 * p][1] = r1;
                kf[2 * p + 1][0] = r2; kf[2 * p + 1][1] = r3;
            }
#pragma unroll
            for (int j = 0; j < 8; j++) mma16816(S[j], qh[c], kf[j]);
#pragma unroll
            for (int j = 0; j < 8; j++) mma16816(S[j], ql[c], kf[j]);
#pragma unroll
            for (int p = 0; p < 4; p++) {
                uint32_t r0, r1, r2, r3;
                ldm_x4(r0, r1, r2, r3, aKl + (uint32_t)((16 * p + b_r) * LDV + 16 * c + b_c) * 2);
                kf[2 * p][0] = r0; kf[2 * p][1] = r1;
                kf[2 * p + 1][0] = r2; kf[2 * p + 1][1] = r3;
            }
#pragma unroll
            for (int j = 0; j < 8; j++) mma16816(S[j], qh[c], kf[j]);
        }

        if (kt + AKT - 1 > q0w) {
            int row0 = q0w + g, row1 = q0w + g + 8;
#pragma unroll
            for (int j = 0; j < 8; j++) {
                int col = kt + 8 * j + 2 * t4;
                if (col > row0)     S[j][0] = NEGINF;
                if (col + 1 > row0) S[j][1] = NEGINF;
                if (col > row1)     S[j][2] = NEGINF;
                if (col + 1 > row1) S[j][3] = NEGINF;
            }
        }

        float mx0 = NEGINF, mx1 = NEGINF;
#pragma unroll
        for (int j = 0; j < 8; j++) {
            mx0 = fmaxf(mx0, fmaxf(S[j][0], S[j][1]));
            mx1 = fmaxf(mx1, fmaxf(S[j][2], S[j][3]));
        }
        mx0 = fmaxf(mx0, __shfl_xor_sync(0xffffffffu, mx0, 1));
        mx0 = fmaxf(mx0, __shfl_xor_sync(0xffffffffu, mx0, 2));
        mx1 = fmaxf(mx1, __shfl_xor_sync(0xffffffffu, mx1, 1));
        mx1 = fmaxf(mx1, __shfl_xor_sync(0xffffffffu, mx1, 2));
        float m0n = fmaxf(m0, mx0), m1n = fmaxf(m1, mx1);
        float c0 = __expf(m0 - m0n), c1 = __expf(m1 - m1n);
        float s0 = 0.f, s1 = 0.f;
#pragma unroll
        for (int j = 0; j < 8; j++) {
            S[j][0] = __expf(S[j][0] - m0n);
            S[j][1] = __expf(S[j][1] - m0n);
            S[j][2] = __expf(S[j][2] - m1n);
            S[j][3] = __expf(S[j][3] - m1n);
            s0 += S[j][0] + S[j][1];
            s1 += S[j][2] + S[j][3];
        }
        s0 += __shfl_xor_sync(0xffffffffu, s0, 1);
        s0 += __shfl_xor_sync(0xffffffffu, s0, 2);
        s1 += __shfl_xor_sync(0xffffffffu, s1, 1);
        s1 += __shfl_xor_sync(0xffffffffu, s1, 2);
        l0 = l0 * c0 + s0;
        l1 = l1 * c1 + s1;
        m0 = m0n; m1 = m1n;
#pragma unroll
        for (int j = 0; j < 8; j++) {
            O[j][0] *= c0; O[j][1] *= c0;
            O[j][2] *= c1; O[j][3] *= c1;
        }

#pragma unroll
        for (int kk = 0; kk < 4; kk++) {
            uint32_t ph[4], pl[4];
            split2u(S[2 * kk][0],     S[2 * kk][1],     ph[0], pl[0]);
            split2u(S[2 * kk][2],     S[2 * kk][3],     ph[1], pl[1]);
            split2u(S[2 * kk + 1][0], S[2 * kk + 1][1], ph[2], pl[2]);
            split2u(S[2 * kk + 1][2], S[2 * kk + 1][3], ph[3], pl[3]);

            uint32_t vf[8][2];
#pragma unroll
            for (int ds = 0; ds < 4; ds++) {
                uint32_t r0, r1, r2, r3;
                ldm_x4_t(r0, r1, r2, r3, aVh + (uint32_t)((16 * kk + v_r) * LDV + 16 * ds + v_c) * 2);
                vf[2 * ds][0] = r0; vf[2 * ds][1] = r1;
                vf[2 * ds + 1][0] = r2; vf[2 * ds + 1][1] = r3;
            }
#pragma unroll
            for (int j = 0; j < 8; j++) mma16816(O[j], ph, vf[j]);
#pragma unroll
            for (int j = 0; j < 8; j++) mma16816(O[j], pl, vf[j]);
#pragma unroll
            for (int ds = 0; ds < 4; ds++) {
                uint32_t r0, r1, r2, r3;
                ldm_x4_t(r0, r1, r2, r3, aVl + (uint32_t)((16 * kk + v_r) * LDV + 16 * ds + v_c) * 2);
                vf[2 * ds][0] = r0; vf[2 * ds][1] = r1;
                vf[2 * ds + 1][0] = r2; vf[2 * ds + 1][1] = r3;
            }
#pragma unroll
            for (int j = 0; j < 8; j++) mma16816(O[j], ph, vf[j]);
        }
    }

    float i0 = 1.f / l0, i1 = 1.f / l1;
    size_t off0 = (size_t)(b * TT + q0w + g) * DD + h * HDIM + 2 * t4;
    size_t off1 = (size_t)(b * TT + q0w + g + 8) * DD + h * HDIM + 2 * t4;
#pragma unroll
    for (int j = 0; j < 8; j++) {
        uint32_t hh, ll;
        split2u(O[j][0] * i0, O[j][1] * i0, hh, ll);
        *(uint32_t*)(yhi + off0 + 8 * j) = hh;
        *(uint32_t*)(ylo + off0 + 8 * j) = ll;
        split2u(O[j][2] * i1, O[j][3] * i1, hh, ll);
        *(uint32_t*)(yhi + off1 + 8 * j) = hh;
        *(uint32_t*)(ylo + off1 + 8 * j) = ll;
    }
}

// ---------------------------------------------------------------------------
// Host launcher
// ---------------------------------------------------------------------------
extern "C" void kernel_launch(void* const* d_in, const int* in_sizes, int n_in,
                              void* d_out, int out_size) {
    const int*   idx    = (const int*)  d_in[0];
    const float* wte    = (const float*)d_in[1];
    const float* wpe    = (const float*)d_in[2];
    const float* ln1_s  = (const float*)d_in[3];
    const float* ln1_b  = (const float*)d_in[4];
    const float* qkv_w  = (const float*)d_in[5];
    const float* proj_w = (const float*)d_in[6];
    const float* ln2_s  = (const float*)d_in[7];
    const float* ln2_b  = (const float*)d_in[8];
    const float* fc_w   = (const float*)d_in[9];
    const float* fc_b   = (const float*)d_in[10];
    const float* fc2_w  = (const float*)d_in[11];
    const float* fc2_b  = (const float*)d_in[12];
    const float* lnf_s  = (const float*)d_in[13];
    const float* lnf_b  = (const float*)d_in[14];
    const float* lm_w   = (const float*)d_in[15];
    float* out = (float*)d_out;

    float *x, *qkv;
    bf16 *h_hi, *h_lo, *y_hi, *y_lo, *gg_hi, *gg_lo;
    bf16 *qw_hi, *qw_lo, *pw_hi, *pw_lo, *fw_hi, *f2_hi, *lw_hi;
    cudaGetSymbolAddress((void**)&x,     g_x);
    cudaGetSymbolAddress((void**)&qkv,   g_qkv);
    cudaGetSymbolAddress((void**)&h_hi,  g_h_hi);   cudaGetSymbolAddress((void**)&h_lo,  g_h_lo);
    cudaGetSymbolAddress((void**)&y_hi,  g_y_hi);   cudaGetSymbolAddress((void**)&y_lo,  g_y_lo);
    cudaGetSymbolAddress((void**)&gg_hi, g_g_hi);   cudaGetSymbolAddress((void**)&gg_lo, g_g_lo);
    cudaGetSymbolAddress((void**)&qw_hi, g_qkvw_hi); cudaGetSymbolAddress((void**)&qw_lo, g_qkvw_lo);
    cudaGetSymbolAddress((void**)&pw_hi, g_projw_hi); cudaGetSymbolAddress((void**)&pw_lo, g_projw_lo);
    cudaGetSymbolAddress((void**)&fw_hi, g_fcw_hi);
    cudaGetSymbolAddress((void**)&f2_hi, g_fc2w_hi);
    cudaGetSymbolAddress((void**)&lw_hi, g_lmw_hi);

    cudaFuncSetAttribute(gemm3t<2>, cudaFuncAttributeMaxDynamicSharedMemorySize, GSM3_MF2);
    cudaFuncSetAttribute(gemm2h<2>, cudaFuncAttributeMaxDynamicSharedMemorySize, GSM2_MF2);
    cudaFuncSetAttribute(gemm2h<4>, cudaFuncAttributeMaxDynamicSharedMemorySize, GSM2_MF4);

    embed_kernel<<<MM, 256>>>(idx, wte, wpe, x);

    {
        int nq = LL * 3 * DD * DD, np = LL * DD * DD;
        int nf = LL * 4 * DD * DD, n2 = LL * 4 * DD * DD, nl = VV * DD;
        int maxn = nf;
        dim3 grid((maxn / 4 + 255) / 256, 5);
        wsplit_all<<<grid, 256>>>(qkv_w,  qw_hi, qw_lo, nq,
                                  proj_w, pw_hi, pw_lo, np,
                                  fc_w,   fw_hi, nf,
                                  fc2_w,  f2_hi, n2,
                                  lm_w,   lw_hi, nl);
    }

    for (int l = 0; l < LL; l++) {
        bf16* qwh = qw_hi + (size_t)l * 3 * DD * DD;  bf16* qwl = qw_lo + (size_t)l * 3 * DD * DD;
        bf16* pwh = pw_hi + (size_t)l * DD * DD;      bf16* pwl = pw_lo + (size_t)l * DD * DD;
        const __half* fwh = (const __half*)(fw_hi + (size_t)l * 4 * DD * DD);
        const __half* f2h = (const __half*)(f2_hi + (size_t)l * 4 * DD * DD);
        const float* fb  = fc_b  + (size_t)l * 4 * DD;
        const float* f2b = fc2_b + (size_t)l * DD;

        ln_split_kernel<<<MM, 256>>>(x, ln1_s + l * DD, ln1_b + l * DD, h_hi, h_lo, 0);
        // qkv: bf16 3-pass, MF=2, grid 24x32 = 768
        gemm3t<2><<<dim3(3 * DD / BN, MM / 64), 256, GSM3_MF2>>>(h_hi, h_lo, qwh, qwl,
            nullptr, nullptr, qkv, MM, 3 * DD, DD, 0);
        attn_mma<<<dim3(TT / AQ, HH, BB), 256>>>(qkv, y_hi, y_lo);
        // proj: bf16 3-pass, MF=2, grid 8x32 = 256
        gemm3t<2><<<dim3(DD / BN, MM / 64), 256, GSM3_MF2>>>(y_hi, y_lo, pwh, pwl,
            nullptr, x, x, MM, DD, DD, FLAG_RES);
        // ln2 -> fp16 hi/lo (consumed by fp16 fc)
        ln_split_kernel<<<MM, 256>>>(x, ln2_s + l * DD, ln2_b + l * DD, h_hi, h_lo, 1);
        // fc: fp16 2-pass, MF=4, grid 32x16 = 512; epilogue gelu + fp16 split out
        gemm2h<4><<<dim3(4 * DD / BN, MM / 128), 256, GSM2_MF4>>>(
            (const __half*)h_hi, (const __half*)h_lo, fwh,
            fb, nullptr, nullptr, (__half*)gg_hi, (__half*)gg_lo,
            MM, 4 * DD, DD, FLAG_BIAS | FLAG_GELU | FLAG_SPLIT);
        // fc2: fp16 2-pass, MF=2, grid 8x32 = 256
        gemm2h<2><<<dim3(DD / BN, MM / 64), 256, GSM2_MF2>>>(
            (const __half*)gg_hi, (const __half*)gg_lo, f2h,
            f2b, x, x, nullptr, nullptr, MM, DD, 4 * DD, FLAG_BIAS | FLAG_RES);
    }

    // lnf -> fp16 hi/lo
    ln_split_kernel<<<MM, 256>>>(x, lnf_s, lnf_b, h_hi, h_lo, 1);
    // lm: fp16 2-pass, MF=4, grid 250x16 = 4000
    gemm2h<4><<<dim3(VV / BN, MM / 128), 256, GSM2_MF4>>>(
        (const __half*)h_hi, (const __half*)h_lo, (const __half*)lw_hi,
        nullptr, nullptr, out, nullptr, nullptr, MM, VV, DD, 0);
}

// round 13
// speedup vs baseline: 1.5502x; 1.5502x over previous
#include <cuda_runtime.h>
#include <cuda_bf16.h>
#include <cuda_fp16.h>
#include <math.h>
#include <stdint.h>

// Model dims
#define BB   2
#define TT   1024
#define DD   1024
#define HH   16
#define HDIM 64
#define LL   8
#define VV   32000
#define MM   (BB*TT)   // 2048 tokens

typedef __nv_bfloat16 bf16;
typedef __nv_bfloat162 bf162;

// GEMM tiling
#define BN 128
#define BK 32
#define NSTAGE 3

// Attention tiling
#define AQ  128
#define AKT 64
#define LDV 72
#define NEGINF (-1e30f)

// fp32 scratch
__device__ float g_x[MM * DD];
__device__ float g_q[MM * DD];                                // q (fp32)
// K/V pre-split bf16 hi/lo (written by qkv GEMM epilogue)
__device__ bf16 g_k_hi[MM * DD], g_k_lo[MM * DD];
__device__ bf16 g_v_hi[MM * DD], g_v_lo[MM * DD];
// 16-bit activation scratch
__device__ bf16 g_h_hi[MM * DD],     g_h_lo[MM * DD];
__device__ bf16 g_y_hi[MM * DD],     g_y_lo[MM * DD];
__device__ bf16 g_g_hi[MM * 4 * DD], g_g_lo[MM * 4 * DD];     // fp16 payload
// weight scratch
__device__ bf16 g_qkvw_hi[LL * 3 * DD * DD], g_qkvw_lo[LL * 3 * DD * DD];
__device__ bf16 g_projw_hi[LL * DD * DD],    g_projw_lo[LL * DD * DD];
__device__ bf16 g_fcw_hi [LL * 4 * DD * DD];                  // fp16, single
__device__ bf16 g_fc2w_hi[LL * 4 * DD * DD];                  // fp16, single
__device__ bf16 g_lmw_hi [VV * DD];                           // fp16, single

// ---------------------------------------------------------------------------
// Small helpers
// ---------------------------------------------------------------------------
__device__ __forceinline__ void split2u(float x, float y, uint32_t& hi, uint32_t& lo) {
    bf162 hp, lp;
    hp.x = __float2bfloat16(x); hp.y = __float2bfloat16(y);
    lp.x = __float2bfloat16(x - __bfloat162float(hp.x));
    lp.y = __float2bfloat16(y - __bfloat162float(hp.y));
    hi = *(uint32_t*)&hp; lo = *(uint32_t*)&lp;
}

__device__ __forceinline__ void split2h(float x, float y, uint32_t& hi, uint32_t& lo) {
    __half2 hp, lp;
    hp.x = __float2half_rn(x); hp.y = __float2half_rn(y);
    lp.x = __float2half_rn(x - __half2float(hp.x));
    lp.y = __float2half_rn(y - __half2float(hp.y));
    hi = *(uint32_t*)&hp; lo = *(uint32_t*)&lp;
}

__device__ __forceinline__ void ldm_x4(uint32_t& r0, uint32_t& r1, uint32_t& r2, uint32_t& r3,
                                       uint32_t addr) {
    asm volatile("ldmatrix.sync.aligned.m8n8.x4.shared.b16 {%0,%1,%2,%3}, [%4];\n"
                 : "=r"(r0), "=r"(r1), "=r"(r2), "=r"(r3) : "r"(addr));
}

__device__ __forceinline__ void ldm_x4_t(uint32_t& r0, uint32_t& r1, uint32_t& r2, uint32_t& r3,
                                         uint32_t addr) {
    asm volatile("ldmatrix.sync.aligned.m8n8.x4.trans.shared.b16 {%0,%1,%2,%3}, [%4];\n"
                 : "=r"(r0), "=r"(r1), "=r"(r2), "=r"(r3) : "r"(addr));
}

__device__ __forceinline__ void mma16816(float* d, const uint32_t* a, const uint32_t* b) {
    asm volatile(
        "mma.sync.aligned.m16n8k16.row.col.f32.bf16.bf16.f32 "
        "{%0,%1,%2,%3}, {%4,%5,%6,%7}, {%8,%9}, {%0,%1,%2,%3};\n"
        : "+f"(d[0]), "+f"(d[1]), "+f"(d[2]), "+f"(d[3])
        : "r"(a[0]), "r"(a[1]), "r"(a[2]), "r"(a[3]), "r"(b[0]), "r"(b[1]));
}

__device__ __forceinline__ void mma16816h(float* d, const uint32_t* a, const uint32_t* b) {
    asm volatile(
        "mma.sync.aligned.m16n8k16.row.col.f32.f16.f16.f32 "
        "{%0,%1,%2,%3}, {%4,%5,%6,%7}, {%8,%9}, {%0,%1,%2,%3};\n"
        : "+f"(d[0]), "+f"(d[1]), "+f"(d[2]), "+f"(d[3])
        : "r"(a[0]), "r"(a[1]), "r"(a[2]), "r"(a[3]), "r"(b[0]), "r"(b[1]));
}

__device__ __forceinline__ void cp16(uint32_t dst, const void* src) {
    asm volatile("cp.async.cg.shared.global [%0], [%1], 16;\n" :: "r"(dst), "l"(src));
}

// swizzled byte offset within one Rx32(16-bit) tile: row r, 16B chunk c (0..3)
__device__ __forceinline__ uint32_t swz(int r, int c) {
    return (uint32_t)(r * 64 + ((c ^ ((r >> 1) & 3)) << 4));
}

// ---------------------------------------------------------------------------
// Fused weight split. Cases 0-1: bf16 hi/lo. Cases 2-4: fp16 single.
// ---------------------------------------------------------------------------
__global__ void wsplit_all(const float* s0, bf16* h0, bf16* l0, int n0,
                           const float* s1, bf16* h1, bf16* l1, int n1,
                           const float* s2, bf16* h2, int n2,
                           const float* s3, bf16* h3, int n3,
                           const float* s4, bf16* h4, int n4) {
    int i = (blockIdx.x * blockDim.x + threadIdx.x) * 4;
    if (blockIdx.y >= 2) {
        const float* src; __half* hi; int n;
        if (blockIdx.y == 2)      { src = s2; hi = (__half*)h2; n = n2; }
        else if (blockIdx.y == 3) { src = s3; hi = (__half*)h3; n = n3; }
        else                      { src = s4; hi = (__half*)h4; n = n4; }
        if (i >= n) return;
        float4 v = *(const float4*)(src + i);
        __half2 p0, p1;
        p0.x = __float2half_rn(v.x); p0.y = __float2half_rn(v.y);
        p1.x = __float2half_rn(v.z); p1.y = __float2half_rn(v.w);
        ((__half2*)(hi + i))[0] = p0;
        ((__half2*)(hi + i))[1] = p1;
        return;
    }
    const float* src; bf16* hi; bf16* lo; int n;
    if (blockIdx.y == 0) { src = s0; hi = h0; lo = l0; n = n0; }
    else                 { src = s1; hi = h1; lo = l1; n = n1; }
    if (i >= n) return;
    float4 v = *(const float4*)(src + i);
    uint32_t hh, ll;
    split2u(v.x, v.y, hh, ll);
    ((uint32_t*)(hi + i))[0] = hh; ((uint32_t*)(lo + i))[0] = ll;
    split2u(v.z, v.w, hh, ll);
    ((uint32_t*)(hi + i))[1] = hh; ((uint32_t*)(lo + i))[1] = ll;
}

// ---------------------------------------------------------------------------
// Embedding
// ---------------------------------------------------------------------------
__global__ void embed_kernel(const int* __restrict__ idx,
                             const float* __restrict__ wte,
                             const float* __restrict__ wpe,
                             float* __restrict__ x) {
    int token = blockIdx.x;
    int t = token % TT;
    int id = idx[token];
    const float4* src = (const float4*)(wte + (size_t)id * DD);
    const float4* pos = (const float4*)(wpe + (size_t)t * DD);
    float4* dst = (float4*)(x + (size_t)token * DD);
    for (int i = threadIdx.x; i < DD / 4; i += blockDim.x) {
        float4 a = src[i], b = pos[i];
        dst[i] = make_float4(a.x + b.x, a.y + b.y, a.z + b.z, a.w + b.w);
    }
}

// ---------------------------------------------------------------------------
// LayerNorm over D=1024 -> 16-bit hi/lo (bf16 when h16=0, fp16 when h16=1)
// ---------------------------------------------------------------------------
__global__ __launch_bounds__(256) void ln_split_kernel(const float* __restrict__ x,
                                                       const float* __restrict__ sc,
                                                       const float* __restrict__ bi,
                                                       bf16* __restrict__ ohi,
                                                       bf16* __restrict__ olo,
                                                       int h16) {
    int token = blockIdx.x;
    const float4* xp = (const float4*)(x + (size_t)token * DD);
    float4 v = xp[threadIdx.x];
    float s = v.x + v.y + v.z + v.w;
    float q = v.x * v.x + v.y * v.y + v.z * v.z + v.w * v.w;
#pragma unroll
    for (int o = 16; o; o >>= 1) {
        s += __shfl_xor_sync(0xffffffffu, s, o);
        q += __shfl_xor_sync(0xffffffffu, q, o);
    }
    __shared__ float ss[8], sq[8];
    int w = threadIdx.x >> 5, l = threadIdx.x & 31;
    if (l == 0) { ss[w] = s; sq[w] = q; }
    __syncthreads();
    if (w == 0) {
        s = (l < 8) ? ss[l] : 0.f;
        q = (l < 8) ? sq[l] : 0.f;
#pragma unroll
        for (int o = 4; o; o >>= 1) {
            s += __shfl_xor_sync(0xffffffffu, s, o);
            q += __shfl_xor_sync(0xffffffffu, q, o);
        }
        if (l == 0) { ss[0] = s; sq[0] = q; }
    }
    __syncthreads();
    float mu  = ss[0] * (1.f / DD);
    float var = sq[0] * (1.f / DD) - mu * mu;
    float inv = rsqrtf(var + 1e-5f);
    float4 sv = ((const float4*)sc)[threadIdx.x];
    float4 bv = ((const float4*)bi)[threadIdx.x];
    float r0 = (v.x - mu) * inv * sv.x + bv.x;
    float r1 = (v.y - mu) * inv * sv.y + bv.y;
    float r2 = (v.z - mu) * inv * sv.z + bv.z;
    float r3 = (v.w - mu) * inv * sv.w + bv.w;
    size_t o = (size_t)token * DD + threadIdx.x * 4;
    uint32_t hh, ll;
    if (h16) {
        split2h(r0, r1, hh, ll);
        ((uint32_t*)(ohi + o))[0] = hh; ((uint32_t*)(olo + o))[0] = ll;
        split2h(r2, r3, hh, ll);
        ((uint32_t*)(ohi + o))[1] = hh; ((uint32_t*)(olo + o))[1] = ll;
    } else {
        split2u(r0, r1, hh, ll);
        ((uint32_t*)(ohi + o))[0] = hh; ((uint32_t*)(olo + o))[0] = ll;
        split2u(r2, r3, hh, ll);
        ((uint32_t*)(ohi + o))[1] = hh; ((uint32_t*)(olo + o))[1] = ll;
    }
}

// ---------------------------------------------------------------------------
#define FLAG_BIAS  1
#define FLAG_RES   2
#define FLAG_GELU  4
#define FLAG_SPLIT 8   // write C as fp16 hi/lo
#define FLAG_QKV   16  // qkv epilogue: q fp32, k/v bf16 hi/lo (stride DD each)

__device__ __forceinline__ float gelu_exact(float v) {
    return 0.5f * v * (1.f + erff(v * 0.70710678118654752f));
}

// ---------------------------------------------------------------------------
// bf16 3-pass GEMM NT (trunk): CTA (MF*32)x128, warp (MF*16)x32, BK=32.
// ---------------------------------------------------------------------------
template<int MF>
__global__ __launch_bounds__(256) void gemm3t(const bf16* __restrict__ Ah,
                                              const bf16* __restrict__ Al,
                                              const bf16* __restrict__ Bh,
                                              const bf16* __restrict__ Bl,
                                              const float* res,
                                              float* C,
                                              bf16* Khi, bf16* Klo,
                                              bf16* Vhi, bf16* Vlo,
                                              int M, int N, int K, int flags) {
    constexpr int BMT   = MF * 32;
    constexpr int TILEA = BMT * 64;
    constexpr int TILEBB = 8192;
    constexpr int BUFB  = 2 * TILEA + 2 * TILEBB;
    constexpr int NCHUNK = (2 * BMT * 4 + 2 * 512) / 256;

    extern __shared__ __align__(16) bf16 sm[];
    int tid = threadIdx.x;
    int warp = tid >> 5, lane = tid & 31;
    int bm = blockIdx.y * BMT, bn = blockIdx.x * BN;
    int wm = (warp >> 2) * (MF * 16);
    int wn = (warp & 3) * 32;

    uint32_t smbase = (uint32_t)__cvta_generic_to_shared(sm);

    float acc[MF][4][4];
#pragma unroll
    for (int i = 0; i < MF; i++)
#pragma unroll
        for (int j = 0; j < 4; j++)
#pragma unroll
            for (int r = 0; r < 4; r++) acc[i][j][r] = 0.f;

    int a_r = ((lane >> 3) & 1) * 8 + (lane & 7);
    int a_c = (lane >> 4) * 8;
    int b_r = (lane >> 4) * 8 + (lane & 7);
    int b_c = ((lane >> 3) & 1) * 8;

    const bf16* srcA[2] = { Ah, Al };
    const bf16* srcB[2] = { Bh, Bl };

    auto stage = [&](int s_idx, int buf) {
        int k0 = s_idx * BK;
        uint32_t bufoff = smbase + (uint32_t)(buf * BUFB);
#pragma unroll
        for (int i = 0; i < NCHUNK; i++) {
            int cid = tid + i * 256;
            if (cid < 2 * BMT * 4) {
                int arr = cid / (BMT * 4);
                int sub = cid - arr * (BMT * 4);
                int row = sub >> 2;
                int c = sub & 3;
                const bf16* src = srcA[arr] + (size_t)(bm + row) * K + k0 + c * 8;
                cp16(bufoff + (uint32_t)(arr * TILEA) + swz(row, c), src);
            } else {
                int cidB = cid - 2 * BMT * 4;
                int arr = cidB >> 9;
                int sub = cidB & 511;
                int row = sub >> 2;
                int c = sub & 3;
                const bf16* src = srcB[arr] + (size_t)(bn + row) * K + k0 + c * 8;
                cp16(bufoff + (uint32_t)(2 * TILEA + arr * TILEBB) + swz(row, c), src);
            }
        }
        asm volatile("cp.async.commit_group;\n");
    };

    int S = K / BK;
    stage(0, 0);
    stage(1, 1);

    for (int s = 0; s < S; s++) {
        int buf = s - (s / NSTAGE) * NSTAGE;
        if (s == S - 1) asm volatile("cp.async.wait_group 0;\n");
        else            asm volatile("cp.async.wait_group 1;\n");
        __syncthreads();
        if (s + 2 < S) stage(s + 2, (s + 2) % NSTAGE);

        uint32_t offAh = smbase + (uint32_t)(buf * BUFB);
        uint32_t offAl = offAh + TILEA;
        uint32_t offBh = offAl + TILEA;
        uint32_t offBl = offBh + TILEBB;

#pragma unroll
        for (int ks = 0; ks < BK; ks += 16) {
            uint32_t ah[MF][4], al[MF][4], bh[4][2], bl[4][2];
#pragma unroll
            for (int mf = 0; mf < MF; mf++) {
                int row = wm + mf * 16 + a_r;
                ldm_x4(ah[mf][0], ah[mf][1], ah[mf][2], ah[mf][3],
                       offAh + swz(row, (ks + a_c) >> 3));
            }
#pragma unroll
            for (int p = 0; p < 2; p++) {
                int row = wn + p * 16 + b_r;
                uint32_t r0, r1, r2, r3;
                ldm_x4(r0, r1, r2, r3, offBh + swz(row, (ks + b_c) >> 3));
                bh[2 * p][0] = r0; bh[2 * p][1] = r1;
                bh[2 * p + 1][0] = r2; bh[2 * p + 1][1] = r3;
            }
#pragma unroll
            for (int mf = 0; mf < MF; mf++)
#pragma unroll
                for (int nf = 0; nf < 4; nf++)
                    mma16816(acc[mf][nf], ah[mf], bh[nf]);

#pragma unroll
            for (int p = 0; p < 2; p++) {
                int row = wn + p * 16 + b_r;
                uint32_t r0, r1, r2, r3;
                ldm_x4(r0, r1, r2, r3, offBl + swz(row, (ks + b_c) >> 3));
                bl[2 * p][0] = r0; bl[2 * p][1] = r1;
                bl[2 * p + 1][0] = r2; bl[2 * p + 1][1] = r3;
            }
#pragma unroll
            for (int mf = 0; mf < MF; mf++)
#pragma unroll
                for (int nf = 0; nf < 4; nf++)
                    mma16816(acc[mf][nf], ah[mf], bl[nf]);

#pragma unroll
            for (int mf = 0; mf < MF; mf++) {
                int row = wm + mf * 16 + a_r;
                ldm_x4(al[mf][0], al[mf][1], al[mf][2], al[mf][3],
                       offAl + swz(row, (ks + a_c) >> 3));
            }
#pragma unroll
            for (int mf = 0; mf < MF; mf++)
#pragma unroll
                for (int nf = 0; nf < 4; nf++)
                    mma16816(acc[mf][nf], al[mf], bh[nf]);
        }
    }

    int gid = lane >> 2, tg = lane & 3;
#pragma unroll
    for (int mf = 0; mf < MF; mf++) {
#pragma unroll
        for (int half = 0; half < 2; half++) {
            int row = bm + wm + mf * 16 + half * 8 + gid;
#pragma unroll
            for (int nf = 0; nf < 4; nf++) {
                int col = bn + wn + nf * 8 + tg * 2;
                float2 o;
                o.x = acc[mf][nf][half * 2 + 0];
                o.y = acc[mf][nf][half * 2 + 1];
                if (flags & FLAG_QKV) {
                    // q fp32 [0,DD); k hi/lo [DD,2DD); v hi/lo [2DD,3DD)
                    if (col < DD) {
                        *(float2*)(C + (size_t)row * DD + col) = o;
                    } else if (col < 2 * DD) {
                        size_t off = (size_t)row * DD + (col - DD);
                        uint32_t hh, ll;
                        split2u(o.x, o.y, hh, ll);
                        *(uint32_t*)(Khi + off) = hh;
                        *(uint32_t*)(Klo + off) = ll;
                    } else {
                        size_t off = (size_t)row * DD + (col - 2 * DD);
                        uint32_t hh, ll;
                        split2u(o.x, o.y, hh, ll);
                        *(uint32_t*)(Vhi + off) = hh;
                        *(uint32_t*)(Vlo + off) = ll;
                    }
                } else {
                    if (flags & FLAG_RES) {
                        float2 r = *(const float2*)(res + (size_t)row * N + col);
                        o.x += r.x; o.y += r.y;
                    }
                    *(float2*)(C + (size_t)row * N + col) = o;
                }
            }
        }
    }
}

// ---------------------------------------------------------------------------
// fp16 2-pass GEMM NT: D = Ah*Bh + Al*Bh  (A split fp16, B single fp16).
// ---------------------------------------------------------------------------
template<int MF>
__global__ __launch_bounds__(256) void gemm2h(const __half* __restrict__ Ah,
                                              const __half* __restrict__ Al,
                                              const __half* __restrict__ Bh,
                                              const float* __restrict__ bias,
                                              const float* res,
                                              float* C, __half* Chi, __half* Clo,
                                              int M, int N, int K, int flags) {
    constexpr int BMT   = MF * 32;
    constexpr int TILEA = BMT * 64;
    constexpr int TILEBB = 8192;
    constexpr int BUFB  = 2 * TILEA + TILEBB;
    constexpr int NCHUNK = (2 * BMT * 4 + 512) / 256;

    extern __shared__ __align__(16) bf16 sm[];
    int tid = threadIdx.x;
    int warp = tid >> 5, lane = tid & 31;
    int bm = blockIdx.y * BMT, bn = blockIdx.x * BN;
    int wm = (warp >> 2) * (MF * 16);
    int wn = (warp & 3) * 32;

    uint32_t smbase = (uint32_t)__cvta_generic_to_shared(sm);

    float acc[MF][4][4];
#pragma unroll
    for (int i = 0; i < MF; i++)
#pragma unroll
        for (int j = 0; j < 4; j++)
#pragma unroll
            for (int r = 0; r < 4; r++) acc[i][j][r] = 0.f;

    int a_r = ((lane >> 3) & 1) * 8 + (lane & 7);
    int a_c = (lane >> 4) * 8;
    int b_r = (lane >> 4) * 8 + (lane & 7);
    int b_c = ((lane >> 3) & 1) * 8;

    const __half* srcA[2] = { Ah, Al };

    auto stage = [&](int s_idx, int buf) {
        int k0 = s_idx * BK;
        uint32_t bufoff = smbase + (uint32_t)(buf * BUFB);
#pragma unroll
        for (int i = 0; i < NCHUNK; i++) {
            int cid = tid + i * 256;
            if (cid < 2 * BMT * 4) {
                int arr = cid / (BMT * 4);
                int sub = cid - arr * (BMT * 4);
                int row = sub >> 2;
                int c = sub & 3;
                const __half* src = srcA[arr] + (size_t)(bm + row) * K + k0 + c * 8;
                cp16(bufoff + (uint32_t)(arr * TILEA) + swz(row, c), src);
            } else {
                int sub = cid - 2 * BMT * 4;
                int row = sub >> 2;
                int c = sub & 3;
                const __half* src = Bh + (size_t)(bn + row) * K + k0 + c * 8;
                cp16(bufoff + (uint32_t)(2 * TILEA) + swz(row, c), src);
            }
        }
        asm volatile("cp.async.commit_group;\n");
    };

    int S = K / BK;
    stage(0, 0);
    stage(1, 1);

    for (int s = 0; s < S; s++) {
        int buf = s - (s / NSTAGE) * NSTAGE;
        if (s == S - 1) asm volatile("cp.async.wait_group 0;\n");
        else            asm volatile("cp.async.wait_group 1;\n");
        __syncthreads();
        if (s + 2 < S) stage(s + 2, (s + 2) % NSTAGE);

        uint32_t offAh = smbase + (uint32_t)(buf * BUFB);
        uint32_t offAl = offAh + TILEA;
        uint32_t offB  = offAl + TILEA;

#pragma unroll
        for (int ks = 0; ks < BK; ks += 16) {
            uint32_t ah[MF][4], al[MF][4], bh[4][2];
#pragma unroll
            for (int mf = 0; mf < MF; mf++) {
                int row = wm + mf * 16 + a_r;
                ldm_x4(ah[mf][0], ah[mf][1], ah[mf][2], ah[mf][3],
                       offAh + swz(row, (ks + a_c) >> 3));
            }
#pragma unroll
            for (int p = 0; p < 2; p++) {
                int row = wn + p * 16 + b_r;
                uint32_t r0, r1, r2, r3;
                ldm_x4(r0, r1, r2, r3, offB + swz(row, (ks + b_c) >> 3));
                bh[2 * p][0] = r0; bh[2 * p][1] = r1;
                bh[2 * p + 1][0] = r2; bh[2 * p + 1][1] = r3;
            }
#pragma unroll
            for (int mf = 0; mf < MF; mf++)
#pragma unroll
                for (int nf = 0; nf < 4; nf++)
                    mma16816h(acc[mf][nf], ah[mf], bh[nf]);

#pragma unroll
            for (int mf = 0; mf < MF; mf++) {
                int row = wm + mf * 16 + a_r;
                ldm_x4(al[mf][0], al[mf][1], al[mf][2], al[mf][3],
                       offAl + swz(row, (ks + a_c) >> 3));
            }
#pragma unroll
            for (int mf = 0; mf < MF; mf++)
#pragma unroll
                for (int nf = 0; nf < 4; nf++)
                    mma16816h(acc[mf][nf], al[mf], bh[nf]);
        }
    }

    int gid = lane >> 2, tg = lane & 3;
#pragma unroll
    for (int mf = 0; mf < MF; mf++) {
#pragma unroll
        for (int half = 0; half < 2; half++) {
            int row = bm + wm + mf * 16 + half * 8 + gid;
#pragma unroll
            for (int nf = 0; nf < 4; nf++) {
                int col = bn + wn + nf * 8 + tg * 2;
                float2 o;
                o.x = acc[mf][nf][half * 2 + 0];
                o.y = acc[mf][nf][half * 2 + 1];
                if (flags & FLAG_BIAS) { o.x += bias[col]; o.y += bias[col + 1]; }
                if (flags & FLAG_GELU) { o.x = gelu_exact(o.x); o.y = gelu_exact(o.y); }
                if (flags & FLAG_RES) {
                    float2 r = *(const float2*)(res + (size_t)row * N + col);
                    o.x += r.x; o.y += r.y;
                }
                if (flags & FLAG_SPLIT) {
                    size_t off = (size_t)row * N + col;
                    uint32_t hh, ll;
                    split2h(o.x, o.y, hh, ll);
                    *(uint32_t*)(Chi + off) = hh;
                    *(uint32_t*)(Clo + off) = ll;
                } else {
                    *(float2*)(C + (size_t)row * N + col) = o;
                }
            }
        }
    }
}

// Dynamic smem sizes
#define GSM3_MF2 (NSTAGE * (2 * 64 * 64 + 2 * 8192))    // 73728
#define GSM2_MF2 (NSTAGE * (2 * 64 * 64 + 8192))        // 49152
#define GSM2_MF4 (NSTAGE * (2 * 128 * 64 + 8192))       // 73728

// ---------------------------------------------------------------------------
// Causal attention via mma.sync. K/V pre-split in HBM -> pure cp.async staging.
// ---------------------------------------------------------------------------
__global__ __launch_bounds__(256) void attn_mma(const float* __restrict__ qarr,
                                                const bf16* __restrict__ khi,
                                                const bf16* __restrict__ klo,
                                                const bf16* __restrict__ vhi,
                                                const bf16* __restrict__ vlo,
                                                bf16* __restrict__ yhi,
                                                bf16* __restrict__ ylo) {
    int b = blockIdx.z, h = blockIdx.y;
    int bx = gridDim.x - 1 - blockIdx.x;
    int tid = threadIdx.x;
    int warp = tid >> 5, lane = tid & 31;
    int g = lane >> 2, t4 = lane & 3;
    int q0w = bx * AQ + warp * 16;

    __shared__ __align__(16) bf16 Kh_s[AKT * LDV];
    __shared__ __align__(16) bf16 Kl_s[AKT * LDV];
    __shared__ __align__(16) bf16 Vh_s[AKT * LDV];
    __shared__ __align__(16) bf16 Vl_s[AKT * LDV];
    uint32_t aKh = (uint32_t)__cvta_generic_to_shared(Kh_s);
    uint32_t aKl = (uint32_t)__cvta_generic_to_shared(Kl_s);
    uint32_t aVh = (uint32_t)__cvta_generic_to_shared(Vh_s);
    uint32_t aVl = (uint32_t)__cvta_generic_to_shared(Vl_s);
    uint32_t abase[4] = { aKh, aKl, aVh, aVl };

    // Q a-frags (scaled by 1/8), bf16 hi/lo
    uint32_t qh[4][4], ql[4][4];
    {
        const float* qbase = qarr + (size_t)(b * TT) * DD + h * HDIM;
        const float* r0p = qbase + (size_t)(q0w + g) * DD;
        const float* r1p = qbase + (size_t)(q0w + g + 8) * DD;
#pragma unroll
        for (int c = 0; c < 4; c++) {
            float2 v00 = *(const float2*)(r0p + c * 16 + 2 * t4);
            float2 v10 = *(const float2*)(r1p + c * 16 + 2 * t4);
            float2 v01 = *(const float2*)(r0p + c * 16 + 2 * t4 + 8);
            float2 v11 = *(const float2*)(r1p + c * 16 + 2 * t4 + 8);
            split2u(v00.x * 0.125f, v00.y * 0.125f, qh[c][0], ql[c][0]);
            split2u(v10.x * 0.125f, v10.y * 0.125f, qh[c][1], ql[c][1]);
            split2u(v01.x * 0.125f, v01.y * 0.125f, qh[c][2], ql[c][2]);
            split2u(v11.x * 0.125f, v11.y * 0.125f, qh[c][3], ql[c][3]);
        }
    }

    float O[8][4];
#pragma unroll
    for (int j = 0; j < 8; j++)
#pragma unroll
        for (int r = 0; r < 4; r++) O[j][r] = 0.f;
    float m0 = NEGINF, m1 = NEGINF, l0 = 0.f, l1 = 0.f;

    int b_r = (lane >> 4) * 8 + (lane & 7);
    int b_c = ((lane >> 3) & 1) * 8;
    int v_r = (lane & 7) + ((lane >> 3) & 1) * 8;
    int v_c = (lane >> 4) * 8;

    const bf16* gsrc[4] = {
        khi + (size_t)(b * TT) * DD + h * HDIM,
        klo + (size_t)(b * TT) * DD + h * HDIM,
        vhi + (size_t)(b * TT) * DD + h * HDIM,
        vlo + (size_t)(b * TT) * DD + h * HDIM
    };

    int ntiles = bx * 2 + 2;
    for (int tile = 0; tile < ntiles; tile++) {
        int kt = tile * AKT;
        __syncthreads();   // all warps done reading previous tile
        // stage K/V tile: pure cp.async, 8x16B per thread (2048 chunks)
#pragma unroll
        for (int i = 0; i < 8; i++) {
            int cid = tid + i * 256;       // 0..2047
            int arr = cid >> 9;            // 512 chunks per array
            int sub = cid & 511;
            int kk = sub >> 3;             // key row 0..63
            int c8 = sub & 7;              // 16B chunk 0..7
            const bf16* src = gsrc[arr] + (size_t)(kt + kk) * DD + c8 * 8;
            cp16(abase[arr] + (uint32_t)(kk * LDV + c8 * 8) * 2, src);
        }
        asm volatile("cp.async.commit_group;\n" ::: "memory");
        asm volatile("cp.async.wait_group 0;\n" ::: "memory");
        __syncthreads();

        if (kt > q0w + 15) continue;

        float S[8][4];
#pragma unroll
        for (int j = 0; j < 8; j++)
#pragma unroll
            for (int r = 0; r < 4; r++) S[j][r] = 0.f;

#pragma unroll
        for (int c = 0; c < 4; c++) {
            uint32_t kf[8][2];
#pragma unroll
            for (int p = 0; p < 4; p++) {
                uint32_t r0, r1, r2, r3;
                ldm_x4(r0, r1, r2, r3, aKh + (uint32_t)((16 * p + b_r) * LDV + 16 * c + b_c) * 2);
                kf[2 * p][0] = r0; kf[2 * p][1] = r1;
                kf[2 * p + 1][0] = r2; kf[2 * p + 1][1] = r3;
            }
#pragma unroll
            for (int j = 0; j < 8; j++) mma16816(S[j], qh[c], kf[j]);
#pragma unroll
            for (int j = 0; j < 8; j++) mma16816(S[j], ql[c], kf[j]);
#pragma unroll
            for (int p = 0; p < 4; p++) {
                uint32_t r0, r1, r2, r3;
                ldm_x4(r0, r1, r2, r3, aKl + (uint32_t)((16 * p + b_r) * LDV + 16 * c + b_c) * 2);
                kf[2 * p][0] = r0; kf[2 * p][1] = r1;
                kf[2 * p + 1][0] = r2; kf[2 * p + 1][1] = r3;
            }
#pragma unroll
            for (int j = 0; j < 8; j++) mma16816(S[j], qh[c], kf[j]);
        }

        if (kt + AKT - 1 > q0w) {
            int row0 = q0w + g, row1 = q0w + g + 8;
#pragma unroll
            for (int j = 0; j < 8; j++) {
                int col = kt + 8 * j + 2 * t4;
                if (col > row0)     S[j][0] = NEGINF;
                if (col + 1 > row0) S[j][1] = NEGINF;
                if (col > row1)     S[j][2] = NEGINF;
                if (col + 1 > row1) S[j][3] = NEGINF;
            }
        }

        float mx0 = NEGINF, mx1 = NEGINF;
#pragma unroll
        for (int j = 0; j < 8; j++) {
            mx0 = fmaxf(mx0, fmaxf(S[j][0], S[j][1]));
            mx1 = fmaxf(mx1, fmaxf(S[j][2], S[j][3]));
        }
        mx0 = fmaxf(mx0, __shfl_xor_sync(0xffffffffu, mx0, 1));
        mx0 = fmaxf(mx0, __shfl_xor_sync(0xffffffffu, mx0, 2));
        mx1 = fmaxf(mx1, __shfl_xor_sync(0xffffffffu, mx1, 1));
        mx1 = fmaxf(mx1, __shfl_xor_sync(0xffffffffu, mx1, 2));
        float m0n = fmaxf(m0, mx0), m1n = fmaxf(m1, mx1);
        float c0 = __expf(m0 - m0n), c1 = __expf(m1 - m1n);
        float s0 = 0.f, s1 = 0.f;
#pragma unroll
        for (int j = 0; j < 8; j++) {
            S[j][0] = __expf(S[j][0] - m0n);
            S[j][1] = __expf(S[j][1] - m0n);
            S[j][2] = __expf(S[j][2] - m1n);
            S[j][3] = __expf(S[j][3] - m1n);
            s0 += S[j][0] + S[j][1];
            s1 += S[j][2] + S[j][3];
        }
        s0 += __shfl_xor_sync(0xffffffffu, s0, 1);
        s0 += __shfl_xor_sync(0xffffffffu, s0, 2);
        s1 += __shfl_xor_sync(0xffffffffu, s1, 1);
        s1 += __shfl_xor_sync(0xffffffffu, s1, 2);
        l0 = l0 * c0 + s0;
        l1 = l1 * c1 + s1;
        m0 = m0n; m1 = m1n;
#pragma unroll
        for (int j = 0; j < 8; j++) {
            O[j][0] *= c0; O[j][1] *= c0;
            O[j][2] *= c1; O[j][3] *= c1;
        }

#pragma unroll
        for (int kk = 0; kk < 4; kk++) {
            uint32_t ph[4], pl[4];
            split2u(S[2 * kk][0],     S[2 * kk][1],     ph[0], pl[0]);
            split2u(S[2 * kk][2],     S[2 * kk][3],     ph[1], pl[1]);
            split2u(S[2 * kk + 1][0], S[2 * kk + 1][1], ph[2], pl[2]);
            split2u(S[2 * kk + 1][2], S[2 * kk + 1][3], ph[3], pl[3]);

            uint32_t vf[8][2];
#pragma unroll
            for (int ds = 0; ds < 4; ds++) {
                uint32_t r0, r1, r2, r3;
                ldm_x4_t(r0, r1, r2, r3, aVh + (uint32_t)((16 * kk + v_r) * LDV + 16 * ds + v_c) * 2);
                vf[2 * ds][0] = r0; vf[2 * ds][1] = r1;
                vf[2 * ds + 1][0] = r2; vf[2 * ds + 1][1] = r3;
            }
#pragma unroll
            for (int j = 0; j < 8; j++) mma16816(O[j], ph, vf[j]);
#pragma unroll
            for (int j = 0; j < 8; j++) mma16816(O[j], pl, vf[j]);
#pragma unroll
            for (int ds = 0; ds < 4; ds++) {
                uint32_t r0, r1, r2, r3;
                ldm_x4_t(r0, r1, r2, r3, aVl + (uint32_t)((16 * kk + v_r) * LDV + 16 * ds + v_c) * 2);
                vf[2 * ds][0] = r0; vf[2 * ds][1] = r1;
                vf[2 * ds + 1][0] = r2; vf[2 * ds + 1][1] = r3;
            }
#pragma unroll
            for (int j = 0; j < 8; j++) mma16816(O[j], ph, vf[j]);
        }
    }

    float i0 = 1.f / l0, i1 = 1.f / l1;
    size_t off0 = (size_t)(b * TT + q0w + g) * DD + h * HDIM + 2 * t4;
    size_t off1 = (size_t)(b * TT + q0w + g + 8) * DD + h * HDIM + 2 * t4;
#pragma unroll
    for (int j = 0; j < 8; j++) {
        uint32_t hh, ll;
        split2u(O[j][0] * i0, O[j][1] * i0, hh, ll);
        *(uint32_t*)(yhi + off0 + 8 * j) = hh;
        *(uint32_t*)(ylo + off0 + 8 * j) = ll;
        split2u(O[j][2] * i1, O[j][3] * i1, hh, ll);
        *(uint32_t*)(yhi + off1 + 8 * j) = hh;
        *(uint32_t*)(ylo + off1 + 8 * j) = ll;
    }
}

// ---------------------------------------------------------------------------
// Host launcher
// ---------------------------------------------------------------------------
extern "C" void kernel_launch(void* const* d_in, const int* in_sizes, int n_in,
                              void* d_out, int out_size) {
    const int*   idx    = (const int*)  d_in[0];
    const float* wte    = (const float*)d_in[1];
    const float* wpe    = (const float*)d_in[2];
    const float* ln1_s  = (const float*)d_in[3];
    const float* ln1_b  = (const float*)d_in[4];
    const float* qkv_w  = (const float*)d_in[5];
    const float* proj_w = (const float*)d_in[6];
    const float* ln2_s  = (const float*)d_in[7];
    const float* ln2_b  = (const float*)d_in[8];
    const float* fc_w   = (const float*)d_in[9];
    const float* fc_b   = (const float*)d_in[10];
    const float* fc2_w  = (const float*)d_in[11];
    const float* fc2_b  = (const float*)d_in[12];
    const float* lnf_s  = (const float*)d_in[13];
    const float* lnf_b  = (const float*)d_in[14];
    const float* lm_w   = (const float*)d_in[15];
    float* out = (float*)d_out;

    float *x, *qarr;
    bf16 *k_hi, *k_lo, *v_hi, *v_lo;
    bf16 *h_hi, *h_lo, *y_hi, *y_lo, *gg_hi, *gg_lo;
    bf16 *qw_hi, *qw_lo, *pw_hi, *pw_lo, *fw_hi, *f2_hi, *lw_hi;
    cudaGetSymbolAddress((void**)&x,     g_x);
    cudaGetSymbolAddress((void**)&qarr,  g_q);
    cudaGetSymbolAddress((void**)&k_hi,  g_k_hi);   cudaGetSymbolAddress((void**)&k_lo,  g_k_lo);
    cudaGetSymbolAddress((void**)&v_hi,  g_v_hi);   cudaGetSymbolAddress((void**)&v_lo,  g_v_lo);
    cudaGetSymbolAddress((void**)&h_hi,  g_h_hi);   cudaGetSymbolAddress((void**)&h_lo,  g_h_lo);
    cudaGetSymbolAddress((void**)&y_hi,  g_y_hi);   cudaGetSymbolAddress((void**)&y_lo,  g_y_lo);
    cudaGetSymbolAddress((void**)&gg_hi, g_g_hi);   cudaGetSymbolAddress((void**)&gg_lo, g_g_lo);
    cudaGetSymbolAddress((void**)&qw_hi, g_qkvw_hi); cudaGetSymbolAddress((void**)&qw_lo, g_qkvw_lo);
    cudaGetSymbolAddress((void**)&pw_hi, g_projw_hi); cudaGetSymbolAddress((void**)&pw_lo, g_projw_lo);
    cudaGetSymbolAddress((void**)&fw_hi, g_fcw_hi);
    cudaGetSymbolAddress((void**)&f2_hi, g_fc2w_hi);
    cudaGetSymbolAddress((void**)&lw_hi, g_lmw_hi);

    cudaFuncSetAttribute(gemm3t<2>, cudaFuncAttributeMaxDynamicSharedMemorySize, GSM3_MF2);
    cudaFuncSetAttribute(gemm2h<2>, cudaFuncAttributeMaxDynamicSharedMemorySize, GSM2_MF2);
    cudaFuncSetAttribute(gemm2h<4>, cudaFuncAttributeMaxDynamicSharedMemorySize, GSM2_MF4);

    embed_kernel<<<MM, 256>>>(idx, wte, wpe, x);

    {
        int nq = LL * 3 * DD * DD, np = LL * DD * DD;
        int nf = LL * 4 * DD * DD, n2 = LL * 4 * DD * DD, nl = VV * DD;
        int maxn = nf;
        dim3 grid((maxn / 4 + 255) / 256, 5);
        wsplit_all<<<grid, 256>>>(qkv_w,  qw_hi, qw_lo, nq,
                                  proj_w, pw_hi, pw_lo, np,
                                  fc_w,   fw_hi, nf,
                                  fc2_w,  f2_hi, n2,
                                  lm_w,   lw_hi, nl);
    }

    for (int l = 0; l < LL; l++) {
        bf16* qwh = qw_hi + (size_t)l * 3 * DD * DD;  bf16* qwl = qw_lo + (size_t)l * 3 * DD * DD;
        bf16* pwh = pw_hi + (size_t)l * DD * DD;      bf16* pwl = pw_lo + (size_t)l * DD * DD;
        const __half* fwh = (const __half*)(fw_hi + (size_t)l * 4 * DD * DD);
        const __half* f2h = (const __half*)(f2_hi + (size_t)l * 4 * DD * DD);
        const float* fb  = fc_b  + (size_t)l * 4 * DD;
        const float* f2b = fc2_b + (size_t)l * DD;

        ln_split_kernel<<<MM, 256>>>(x, ln1_s + l * DD, ln1_b + l * DD, h_hi, h_lo, 0);
        // qkv: bf16 3-pass, MF=2, grid 24x32 = 768. Epilogue: q fp32, K/V bf16 hi/lo.
        gemm3t<2><<<dim3(3 * DD / BN, MM / 64), 256, GSM3_MF2>>>(h_hi, h_lo, qwh, qwl,
            nullptr, qarr, k_hi, k_lo, v_hi, v_lo, MM, 3 * DD, DD, FLAG_QKV);
        attn_mma<<<dim3(TT / AQ, HH, BB), 256>>>(qarr, k_hi, k_lo, v_hi, v_lo, y_hi, y_lo);
        // proj: bf16 3-pass, MF=2, grid 8x32 = 256
        gemm3t<2><<<dim3(DD / BN, MM / 64), 256, GSM3_MF2>>>(y_hi, y_lo, pwh, pwl,
            x, x, nullptr, nullptr, nullptr, nullptr, MM, DD, DD, FLAG_RES);
        // ln2 -> fp16 hi/lo
        ln_split_kernel<<<MM, 256>>>(x, ln2_s + l * DD, ln2_b + l * DD, h_hi, h_lo, 1);
        // fc: fp16 2-pass, MF=4, grid 32x16 = 512; gelu + fp16 split out
        gemm2h<4><<<dim3(4 * DD / BN, MM / 128), 256, GSM2_MF4>>>(
            (const __half*)h_hi, (const __half*)h_lo, fwh,
            fb, nullptr, nullptr, (__half*)gg_hi, (__half*)gg_lo,
            MM, 4 * DD, DD, FLAG_BIAS | FLAG_GELU | FLAG_SPLIT);
        // fc2: fp16 2-pass, MF=2, grid 8x32 = 256
        gemm2h<2><<<dim3(DD / BN, MM / 64), 256, GSM2_MF2>>>(
            (const __half*)gg_hi, (const __half*)gg_lo, f2h,
            f2b, x, x, nullptr, nullptr, MM, DD, 4 * DD, FLAG_BIAS | FLAG_RES);
    }

    // lnf -> fp16 hi/lo
    ln_split_kernel<<<MM, 256>>>(x, lnf_s, lnf_b, h_hi, h_lo, 1);
    // lm: fp16 2-pass, MF=4, grid 250x16 = 4000
    gemm2h<4><<<dim3(VV / BN, MM / 128), 256, GSM2_MF4>>>(
        (const __half*)h_hi, (const __half*)h_lo, (const __half*)lw_hi,
        nullptr, nullptr, out, nullptr, nullptr, MM, VV, DD, 0);
}

// round 14
// speedup vs baseline: 1.6556x; 1.0680x over previous
#include <cuda_runtime.h>
#include <cuda_bf16.h>
#include <cuda_fp16.h>
#include <math.h>
#include <stdint.h>

// Model dims
#define BB   2
#define TT   1024
#define DD   1024
#define HH   16
#define HDIM 64
#define LL   8
#define VV   32000
#define MM   (BB*TT)   // 2048 tokens

typedef __nv_bfloat16 bf16;
typedef __nv_bfloat162 bf162;

// GEMM tiling
#define BN 128
#define BK 32
#define NSTAGE 3

// Attention tiling
#define AQ  128
#define AKT 64
#define LDV 72
#define NEGINF (-1e30f)

// fp32 scratch
__device__ float g_x[MM * DD];
__device__ float g_q[MM * DD];                                // q (fp32)
// K/V pre-split bf16 hi/lo (written by qkv GEMM epilogue)
__device__ bf16 g_k_hi[MM * DD], g_k_lo[MM * DD];
__device__ bf16 g_v_hi[MM * DD], g_v_lo[MM * DD];
// fp16 activation scratch (hi/lo pairs)
__device__ bf16 g_h_hi[MM * DD],     g_h_lo[MM * DD];
__device__ bf16 g_y_hi[MM * DD],     g_y_lo[MM * DD];
__device__ bf16 g_g_hi[MM * 4 * DD], g_g_lo[MM * 4 * DD];
// weights: all single fp16
__device__ bf16 g_qkvw[LL * 3 * DD * DD];
__device__ bf16 g_projw[LL * DD * DD];
__device__ bf16 g_fcw [LL * 4 * DD * DD];
__device__ bf16 g_fc2w[LL * 4 * DD * DD];
__device__ bf16 g_lmw [VV * DD];

// ---------------------------------------------------------------------------
// Small helpers
// ---------------------------------------------------------------------------
__device__ __forceinline__ void split2u(float x, float y, uint32_t& hi, uint32_t& lo) {
    bf162 hp, lp;
    hp.x = __float2bfloat16(x); hp.y = __float2bfloat16(y);
    lp.x = __float2bfloat16(x - __bfloat162float(hp.x));
    lp.y = __float2bfloat16(y - __bfloat162float(hp.y));
    hi = *(uint32_t*)&hp; lo = *(uint32_t*)&lp;
}

__device__ __forceinline__ void split2h(float x, float y, uint32_t& hi, uint32_t& lo) {
    __half2 hp, lp;
    hp.x = __float2half_rn(x); hp.y = __float2half_rn(y);
    lp.x = __float2half_rn(x - __half2float(hp.x));
    lp.y = __float2half_rn(y - __half2float(hp.y));
    hi = *(uint32_t*)&hp; lo = *(uint32_t*)&lp;
}

__device__ __forceinline__ void ldm_x4(uint32_t& r0, uint32_t& r1, uint32_t& r2, uint32_t& r3,
                                       uint32_t addr) {
    asm volatile("ldmatrix.sync.aligned.m8n8.x4.shared.b16 {%0,%1,%2,%3}, [%4];\n"
                 : "=r"(r0), "=r"(r1), "=r"(r2), "=r"(r3) : "r"(addr));
}

__device__ __forceinline__ void ldm_x4_t(uint32_t& r0, uint32_t& r1, uint32_t& r2, uint32_t& r3,
                                         uint32_t addr) {
    asm volatile("ldmatrix.sync.aligned.m8n8.x4.trans.shared.b16 {%0,%1,%2,%3}, [%4];\n"
                 : "=r"(r0), "=r"(r1), "=r"(r2), "=r"(r3) : "r"(addr));
}

__device__ __forceinline__ void mma16816(float* d, const uint32_t* a, const uint32_t* b) {
    asm volatile(
        "mma.sync.aligned.m16n8k16.row.col.f32.bf16.bf16.f32 "
        "{%0,%1,%2,%3}, {%4,%5,%6,%7}, {%8,%9}, {%0,%1,%2,%3};\n"
        : "+f"(d[0]), "+f"(d[1]), "+f"(d[2]), "+f"(d[3])
        : "r"(a[0]), "r"(a[1]), "r"(a[2]), "r"(a[3]), "r"(b[0]), "r"(b[1]));
}

__device__ __forceinline__ void mma16816h(float* d, const uint32_t* a, const uint32_t* b) {
    asm volatile(
        "mma.sync.aligned.m16n8k16.row.col.f32.f16.f16.f32 "
        "{%0,%1,%2,%3}, {%4,%5,%6,%7}, {%8,%9}, {%0,%1,%2,%3};\n"
        : "+f"(d[0]), "+f"(d[1]), "+f"(d[2]), "+f"(d[3])
        : "r"(a[0]), "r"(a[1]), "r"(a[2]), "r"(a[3]), "r"(b[0]), "r"(b[1]));
}

__device__ __forceinline__ void cp16(uint32_t dst, const void* src) {
    asm volatile("cp.async.cg.shared.global [%0], [%1], 16;\n" :: "r"(dst), "l"(src));
}

// swizzled byte offset within one Rx32(16-bit) tile: row r, 16B chunk c (0..3)
__device__ __forceinline__ uint32_t swz(int r, int c) {
    return (uint32_t)(r * 64 + ((c ^ ((r >> 1) & 3)) << 4));
}

// ---------------------------------------------------------------------------
// Fused weight cast: all 5 arrays fp32 -> fp16 single
// ---------------------------------------------------------------------------
__global__ void wsplit_all(const float* s0, bf16* d0, int n0,
                           const float* s1, bf16* d1, int n1,
                           const float* s2, bf16* d2, int n2,
                           const float* s3, bf16* d3, int n3,
                           const float* s4, bf16* d4, int n4) {
    const float* src; __half* dst; int n;
    switch (blockIdx.y) {
        case 0: src = s0; dst = (__half*)d0; n = n0; break;
        case 1: src = s1; dst = (__half*)d1; n = n1; break;
        case 2: src = s2; dst = (__half*)d2; n = n2; break;
        case 3: src = s3; dst = (__half*)d3; n = n3; break;
        default: src = s4; dst = (__half*)d4; n = n4; break;
    }
    int i = (blockIdx.x * blockDim.x + threadIdx.x) * 4;
    if (i >= n) return;
    float4 v = *(const float4*)(src + i);
    __half2 p0, p1;
    p0.x = __float2half_rn(v.x); p0.y = __float2half_rn(v.y);
    p1.x = __float2half_rn(v.z); p1.y = __float2half_rn(v.w);
    ((__half2*)(dst + i))[0] = p0;
    ((__half2*)(dst + i))[1] = p1;
}

// ---------------------------------------------------------------------------
// Embedding
// ---------------------------------------------------------------------------
__global__ void embed_kernel(const int* __restrict__ idx,
                             const float* __restrict__ wte,
                             const float* __restrict__ wpe,
                             float* __restrict__ x) {
    int token = blockIdx.x;
    int t = token % TT;
    int id = idx[token];
    const float4* src = (const float4*)(wte + (size_t)id * DD);
    const float4* pos = (const float4*)(wpe + (size_t)t * DD);
    float4* dst = (float4*)(x + (size_t)token * DD);
    for (int i = threadIdx.x; i < DD / 4; i += blockDim.x) {
        float4 a = src[i], b = pos[i];
        dst[i] = make_float4(a.x + b.x, a.y + b.y, a.z + b.z, a.w + b.w);
    }
}

// ---------------------------------------------------------------------------
// LayerNorm over D=1024 -> fp16 hi/lo
// ---------------------------------------------------------------------------
__global__ __launch_bounds__(256) void ln_split_kernel(const float* __restrict__ x,
                                                       const float* __restrict__ sc,
                                                       const float* __restrict__ bi,
                                                       bf16* __restrict__ ohi,
                                                       bf16* __restrict__ olo) {
    int token = blockIdx.x;
    const float4* xp = (const float4*)(x + (size_t)token * DD);
    float4 v = xp[threadIdx.x];
    float s = v.x + v.y + v.z + v.w;
    float q = v.x * v.x + v.y * v.y + v.z * v.z + v.w * v.w;
#pragma unroll
    for (int o = 16; o; o >>= 1) {
        s += __shfl_xor_sync(0xffffffffu, s, o);
        q += __shfl_xor_sync(0xffffffffu, q, o);
    }
    __shared__ float ss[8], sq[8];
    int w = threadIdx.x >> 5, l = threadIdx.x & 31;
    if (l == 0) { ss[w] = s; sq[w] = q; }
    __syncthreads();
    if (w == 0) {
        s = (l < 8) ? ss[l] : 0.f;
        q = (l < 8) ? sq[l] : 0.f;
#pragma unroll
        for (int o = 4; o; o >>= 1) {
            s += __shfl_xor_sync(0xffffffffu, s, o);
            q += __shfl_xor_sync(0xffffffffu, q, o);
        }
        if (l == 0) { ss[0] = s; sq[0] = q; }
    }
    __syncthreads();
    float mu  = ss[0] * (1.f / DD);
    float var = sq[0] * (1.f / DD) - mu * mu;
    float inv = rsqrtf(var + 1e-5f);
    float4 sv = ((const float4*)sc)[threadIdx.x];
    float4 bv = ((const float4*)bi)[threadIdx.x];
    float r0 = (v.x - mu) * inv * sv.x + bv.x;
    float r1 = (v.y - mu) * inv * sv.y + bv.y;
    float r2 = (v.z - mu) * inv * sv.z + bv.z;
    float r3 = (v.w - mu) * inv * sv.w + bv.w;
    size_t o = (size_t)token * DD + threadIdx.x * 4;
    uint32_t hh, ll;
    split2h(r0, r1, hh, ll);
    ((uint32_t*)(ohi + o))[0] = hh; ((uint32_t*)(olo + o))[0] = ll;
    split2h(r2, r3, hh, ll);
    ((uint32_t*)(ohi + o))[1] = hh; ((uint32_t*)(olo + o))[1] = ll;
}

// ---------------------------------------------------------------------------
#define FLAG_BIAS  1
#define FLAG_RES   2
#define FLAG_GELU  4
#define FLAG_SPLIT 8   // write C as fp16 hi/lo
#define FLAG_QKV   16  // qkv epilogue: q fp32, k/v bf16 hi/lo (stride DD each)

__device__ __forceinline__ float gelu_exact(float v) {
    return 0.5f * v * (1.f + erff(v * 0.70710678118654752f));
}

// ---------------------------------------------------------------------------
// fp16 2-pass GEMM NT: D = Ah*Bh + Al*Bh  (A split fp16, B single fp16).
// CTA (MF*32)x128, warp (MF*16)x32, BK=32, 3-stage pipeline, swizzled smem.
// ---------------------------------------------------------------------------
template<int MF>
__global__ __launch_bounds__(256) void gemm2h(const __half* __restrict__ Ah,
                                              const __half* __restrict__ Al,
                                              const __half* __restrict__ Bh,
                                              const float* __restrict__ bias,
                                              const float* res,
                                              float* C, __half* Chi, __half* Clo,
                                              bf16* Khi, bf16* Klo,
                                              bf16* Vhi, bf16* Vlo,
                                              int M, int N, int K, int flags) {
    constexpr int BMT   = MF * 32;
    constexpr int TILEA = BMT * 64;
    constexpr int TILEBB = 8192;
    constexpr int BUFB  = 2 * TILEA + TILEBB;
    constexpr int NCHUNK = (2 * BMT * 4 + 512) / 256;

    extern __shared__ __align__(16) bf16 sm[];
    int tid = threadIdx.x;
    int warp = tid >> 5, lane = tid & 31;
    int bm = blockIdx.y * BMT, bn = blockIdx.x * BN;
    int wm = (warp >> 2) * (MF * 16);
    int wn = (warp & 3) * 32;

    uint32_t smbase = (uint32_t)__cvta_generic_to_shared(sm);

    float acc[MF][4][4];
#pragma unroll
    for (int i = 0; i < MF; i++)
#pragma unroll
        for (int j = 0; j < 4; j++)
#pragma unroll
            for (int r = 0; r < 4; r++) acc[i][j][r] = 0.f;

    int a_r = ((lane >> 3) & 1) * 8 + (lane & 7);
    int a_c = (lane >> 4) * 8;
    int b_r = (lane >> 4) * 8 + (lane & 7);
    int b_c = ((lane >> 3) & 1) * 8;

    const __half* srcA[2] = { Ah, Al };

    auto stage = [&](int s_idx, int buf) {
        int k0 = s_idx * BK;
        uint32_t bufoff = smbase + (uint32_t)(buf * BUFB);
#pragma unroll
        for (int i = 0; i < NCHUNK; i++) {
            int cid = tid + i * 256;
            if (cid < 2 * BMT * 4) {
                int arr = cid / (BMT * 4);
                int sub = cid - arr * (BMT * 4);
                int row = sub >> 2;
                int c = sub & 3;
                const __half* src = srcA[arr] + (size_t)(bm + row) * K + k0 + c * 8;
                cp16(bufoff + (uint32_t)(arr * TILEA) + swz(row, c), src);
            } else {
                int sub = cid - 2 * BMT * 4;
                int row = sub >> 2;
                int c = sub & 3;
                const __half* src = Bh + (size_t)(bn + row) * K + k0 + c * 8;
                cp16(bufoff + (uint32_t)(2 * TILEA) + swz(row, c), src);
            }
        }
        asm volatile("cp.async.commit_group;\n");
    };

    int S = K / BK;
    stage(0, 0);
    stage(1, 1);

    for (int s = 0; s < S; s++) {
        int buf = s - (s / NSTAGE) * NSTAGE;
        if (s == S - 1) asm volatile("cp.async.wait_group 0;\n");
        else            asm volatile("cp.async.wait_group 1;\n");
        __syncthreads();
        if (s + 2 < S) stage(s + 2, (s + 2) % NSTAGE);

        uint32_t offAh = smbase + (uint32_t)(buf * BUFB);
        uint32_t offAl = offAh + TILEA;
        uint32_t offB  = offAl + TILEA;

#pragma unroll
        for (int ks = 0; ks < BK; ks += 16) {
            uint32_t ah[MF][4], al[MF][4], bh[4][2];
#pragma unroll
            for (int mf = 0; mf < MF; mf++) {
                int row = wm + mf * 16 + a_r;
                ldm_x4(ah[mf][0], ah[mf][1], ah[mf][2], ah[mf][3],
                       offAh + swz(row, (ks + a_c) >> 3));
            }
#pragma unroll
            for (int p = 0; p < 2; p++) {
                int row = wn + p * 16 + b_r;
                uint32_t r0, r1, r2, r3;
                ldm_x4(r0, r1, r2, r3, offB + swz(row, (ks + b_c) >> 3));
                bh[2 * p][0] = r0; bh[2 * p][1] = r1;
                bh[2 * p + 1][0] = r2; bh[2 * p + 1][1] = r3;
            }
#pragma unroll
            for (int mf = 0; mf < MF; mf++)
#pragma unroll
                for (int nf = 0; nf < 4; nf++)
                    mma16816h(acc[mf][nf], ah[mf], bh[nf]);

#pragma unroll
            for (int mf = 0; mf < MF; mf++) {
                int row = wm + mf * 16 + a_r;
                ldm_x4(al[mf][0], al[mf][1], al[mf][2], al[mf][3],
                       offAl + swz(row, (ks + a_c) >> 3));
            }
#pragma unroll
            for (int mf = 0; mf < MF; mf++)
#pragma unroll
                for (int nf = 0; nf < 4; nf++)
                    mma16816h(acc[mf][nf], al[mf], bh[nf]);
        }
    }

    int gid = lane >> 2, tg = lane & 3;
#pragma unroll
    for (int mf = 0; mf < MF; mf++) {
#pragma unroll
        for (int half = 0; half < 2; half++) {
            int row = bm + wm + mf * 16 + half * 8 + gid;
#pragma unroll
            for (int nf = 0; nf < 4; nf++) {
                int col = bn + wn + nf * 8 + tg * 2;
                float2 o;
                o.x = acc[mf][nf][half * 2 + 0];
                o.y = acc[mf][nf][half * 2 + 1];
                if (flags & FLAG_QKV) {
                    // q fp32 [0,DD); k hi/lo [DD,2DD); v hi/lo [2DD,3DD)
                    if (col < DD) {
                        *(float2*)(C + (size_t)row * DD + col) = o;
                    } else if (col < 2 * DD) {
                        size_t off = (size_t)row * DD + (col - DD);
                        uint32_t hh, ll;
                        split2u(o.x, o.y, hh, ll);
                        *(uint32_t*)(Khi + off) = hh;
                        *(uint32_t*)(Klo + off) = ll;
                    } else {
                        size_t off = (size_t)row * DD + (col - 2 * DD);
                        uint32_t hh, ll;
                        split2u(o.x, o.y, hh, ll);
                        *(uint32_t*)(Vhi + off) = hh;
                        *(uint32_t*)(Vlo + off) = ll;
                    }
                    continue;
                }
                if (flags & FLAG_BIAS) { o.x += bias[col]; o.y += bias[col + 1]; }
                if (flags & FLAG_GELU) { o.x = gelu_exact(o.x); o.y = gelu_exact(o.y); }
                if (flags & FLAG_RES) {
                    float2 r = *(const float2*)(res + (size_t)row * N + col);
                    o.x += r.x; o.y += r.y;
                }
                if (flags & FLAG_SPLIT) {
                    size_t off = (size_t)row * N + col;
                    uint32_t hh, ll;
                    split2h(o.x, o.y, hh, ll);
                    *(uint32_t*)(Chi + off) = hh;
                    *(uint32_t*)(Clo + off) = ll;
                } else {
                    *(float2*)(C + (size_t)row * N + col) = o;
                }
            }
        }
    }
}

// Dynamic smem sizes
#define GSM2_MF2 (NSTAGE * (2 * 64 * 64 + 8192))        // 49152
#define GSM2_MF4 (NSTAGE * (2 * 128 * 64 + 8192))       // 73728

// ---------------------------------------------------------------------------
// Causal attention via mma.sync (bf16 3-pass internals, fp32-accurate).
// K/V pre-split bf16 hi/lo in HBM -> pure cp.async staging. y out fp16 hi/lo.
// ---------------------------------------------------------------------------
__global__ __launch_bounds__(256) void attn_mma(const float* __restrict__ qarr,
                                                const bf16* __restrict__ khi,
                                                const bf16* __restrict__ klo,
                                                const bf16* __restrict__ vhi,
                                                const bf16* __restrict__ vlo,
                                                bf16* __restrict__ yhi,
                                                bf16* __restrict__ ylo) {
    int b = blockIdx.z, h = blockIdx.y;
    int bx = gridDim.x - 1 - blockIdx.x;
    int tid = threadIdx.x;
    int warp = tid >> 5, lane = tid & 31;
    int g = lane >> 2, t4 = lane & 3;
    int q0w = bx * AQ + warp * 16;

    __shared__ __align__(16) bf16 Kh_s[AKT * LDV];
    __shared__ __align__(16) bf16 Kl_s[AKT * LDV];
    __shared__ __align__(16) bf16 Vh_s[AKT * LDV];
    __shared__ __align__(16) bf16 Vl_s[AKT * LDV];
    uint32_t aKh = (uint32_t)__cvta_generic_to_shared(Kh_s);
    uint32_t aKl = (uint32_t)__cvta_generic_to_shared(Kl_s);
    uint32_t aVh = (uint32_t)__cvta_generic_to_shared(Vh_s);
    uint32_t aVl = (uint32_t)__cvta_generic_to_shared(Vl_s);
    uint32_t abase[4] = { aKh, aKl, aVh, aVl };

    // Q a-frags (scaled by 1/8), bf16 hi/lo
    uint32_t qh[4][4], ql[4][4];
    {
        const float* qbase = qarr + (size_t)(b * TT) * DD + h * HDIM;
        const float* r0p = qbase + (size_t)(q0w + g) * DD;
        const float* r1p = qbase + (size_t)(q0w + g + 8) * DD;
#pragma unroll
        for (int c = 0; c < 4; c++) {
            float2 v00 = *(const float2*)(r0p + c * 16 + 2 * t4);
            float2 v10 = *(const float2*)(r1p + c * 16 + 2 * t4);
            float2 v01 = *(const float2*)(r0p + c * 16 + 2 * t4 + 8);
            float2 v11 = *(const float2*)(r1p + c * 16 + 2 * t4 + 8);
            split2u(v00.x * 0.125f, v00.y * 0.125f, qh[c][0], ql[c][0]);
            split2u(v10.x * 0.125f, v10.y * 0.125f, qh[c][1], ql[c][1]);
            split2u(v01.x * 0.125f, v01.y * 0.125f, qh[c][2], ql[c][2]);
            split2u(v11.x * 0.125f, v11.y * 0.125f, qh[c][3], ql[c][3]);
        }
    }

    float O[8][4];
#pragma unroll
    for (int j = 0; j < 8; j++)
#pragma unroll
        for (int r = 0; r < 4; r++) O[j][r] = 0.f;
    float m0 = NEGINF, m1 = NEGINF, l0 = 0.f, l1 = 0.f;

    int b_r = (lane >> 4) * 8 + (lane & 7);
    int b_c = ((lane >> 3) & 1) * 8;
    int v_r = (lane & 7) + ((lane >> 3) & 1) * 8;
    int v_c = (lane >> 4) * 8;

    const bf16* gsrc[4] = {
        khi + (size_t)(b * TT) * DD + h * HDIM,
        klo + (size_t)(b * TT) * DD + h * HDIM,
        vhi + (size_t)(b * TT) * DD + h * HDIM,
        vlo + (size_t)(b * TT) * DD + h * HDIM
    };

    int ntiles = bx * 2 + 2;
    for (int tile = 0; tile < ntiles; tile++) {
        int kt = tile * AKT;
        __syncthreads();
#pragma unroll
        for (int i = 0; i < 8; i++) {
            int cid = tid + i * 256;
            int arr = cid >> 9;
            int sub = cid & 511;
            int kk = sub >> 3;
            int c8 = sub & 7;
            const bf16* src = gsrc[arr] + (size_t)(kt + kk) * DD + c8 * 8;
            cp16(abase[arr] + (uint32_t)(kk * LDV + c8 * 8) * 2, src);
        }
        asm volatile("cp.async.commit_group;\n" ::: "memory");
        asm volatile("cp.async.wait_group 0;\n" ::: "memory");
        __syncthreads();

        if (kt > q0w + 15) continue;

        float S[8][4];
#pragma unroll
        for (int j = 0; j < 8; j++)
#pragma unroll
            for (int r = 0; r < 4; r++) S[j][r] = 0.f;

#pragma unroll
        for (int c = 0; c < 4; c++) {
            uint32_t kf[8][2];
#pragma unroll
            for (int p = 0; p < 4; p++) {
                uint32_t r0, r1, r2, r3;
                ldm_x4(r0, r1, r2, r3, aKh + (uint32_t)((16 * p + b_r) * LDV + 16 * c + b_c) * 2);
                kf[2 * p][0] = r0; kf[2 * p][1] = r1;
                kf[2 * p + 1][0] = r2; kf[2 * p + 1][1] = r3;
            }
#pragma unroll
            for (int j = 0; j < 8; j++) mma16816(S[j], qh[c], kf[j]);
#pragma unroll
            for (int j = 0; j < 8; j++) mma16816(S[j], ql[c], kf[j]);
#pragma unroll
            for (int p = 0; p < 4; p++) {
                uint32_t r0, r1, r2, r3;
                ldm_x4(r0, r1, r2, r3, aKl + (uint32_t)((16 * p + b_r) * LDV + 16 * c + b_c) * 2);
                kf[2 * p][0] = r0; kf[2 * p][1] = r1;
                kf[2 * p + 1][0] = r2; kf[2 * p + 1][1] = r3;
            }
#pragma unroll
            for (int j = 0; j < 8; j++) mma16816(S[j], qh[c], kf[j]);
        }

        if (kt + AKT - 1 > q0w) {
            int row0 = q0w + g, row1 = q0w + g + 8;
#pragma unroll
            for (int j = 0; j < 8; j++) {
                int col = kt + 8 * j + 2 * t4;
                if (col > row0)     S[j][0] = NEGINF;
                if (col + 1 > row0) S[j][1] = NEGINF;
                if (col > row1)     S[j][2] = NEGINF;
                if (col + 1 > row1) S[j][3] = NEGINF;
            }
        }

        float mx0 = NEGINF, mx1 = NEGINF;
#pragma unroll
        for (int j = 0; j < 8; j++) {
            mx0 = fmaxf(mx0, fmaxf(S[j][0], S[j][1]));
            mx1 = fmaxf(mx1, fmaxf(S[j][2], S[j][3]));
        }
        mx0 = fmaxf(mx0, __shfl_xor_sync(0xffffffffu, mx0, 1));
        mx0 = fmaxf(mx0, __shfl_xor_sync(0xffffffffu, mx0, 2));
        mx1 = fmaxf(mx1, __shfl_xor_sync(0xffffffffu, mx1, 1));
        mx1 = fmaxf(mx1, __shfl_xor_sync(0xffffffffu, mx1, 2));
        float m0n = fmaxf(m0, mx0), m1n = fmaxf(m1, mx1);
        float c0 = __expf(m0 - m0n), c1 = __expf(m1 - m1n);
        float s0 = 0.f, s1 = 0.f;
#pragma unroll
        for (int j = 0; j < 8; j++) {
            S[j][0] = __expf(S[j][0] - m0n);
            S[j][1] = __expf(S[j][1] - m0n);
            S[j][2] = __expf(S[j][2] - m1n);
            S[j][3] = __expf(S[j][3] - m1n);
            s0 += S[j][0] + S[j][1];
            s1 += S[j][2] + S[j][3];
        }
        s0 += __shfl_xor_sync(0xffffffffu, s0, 1);
        s0 += __shfl_xor_sync(0xffffffffu, s0, 2);
        s1 += __shfl_xor_sync(0xffffffffu, s1, 1);
        s1 += __shfl_xor_sync(0xffffffffu, s1, 2);
        l0 = l0 * c0 + s0;
        l1 = l1 * c1 + s1;
        m0 = m0n; m1 = m1n;
#pragma unroll
        for (int j = 0; j < 8; j++) {
            O[j][0] *= c0; O[j][1] *= c0;
            O[j][2] *= c1; O[j][3] *= c1;
        }

#pragma unroll
        for (int kk = 0; kk < 4; kk++) {
            uint32_t ph[4], pl[4];
            split2u(S[2 * kk][0],     S[2 * kk][1],     ph[0], pl[0]);
            split2u(S[2 * kk][2],     S[2 * kk][3],     ph[1], pl[1]);
            split2u(S[2 * kk + 1][0], S[2 * kk + 1][1], ph[2], pl[2]);
            split2u(S[2 * kk + 1][2], S[2 * kk + 1][3], ph[3], pl[3]);

            uint32_t vf[8][2];
#pragma unroll
            for (int ds = 0; ds < 4; ds++) {
                uint32_t r0, r1, r2, r3;
                ldm_x4_t(r0, r1, r2, r3, aVh + (uint32_t)((16 * kk + v_r) * LDV + 16 * ds + v_c) * 2);
                vf[2 * ds][0] = r0; vf[2 * ds][1] = r1;
                vf[2 * ds + 1][0] = r2; vf[2 * ds + 1][1] = r3;
            }
#pragma unroll
            for (int j = 0; j < 8; j++) mma16816(O[j], ph, vf[j]);
#pragma unroll
            for (int j = 0; j < 8; j++) mma16816(O[j], pl, vf[j]);
#pragma unroll
            for (int ds = 0; ds < 4; ds++) {
                uint32_t r0, r1, r2, r3;
                ldm_x4_t(r0, r1, r2, r3, aVl + (uint32_t)((16 * kk + v_r) * LDV + 16 * ds + v_c) * 2);
                vf[2 * ds][0] = r0; vf[2 * ds][1] = r1;
                vf[2 * ds + 1][0] = r2; vf[2 * ds + 1][1] = r3;
            }
#pragma unroll
            for (int j = 0; j < 8; j++) mma16816(O[j], ph, vf[j]);
        }
    }

    // epilogue: y as fp16 hi/lo (consumed by fp16 proj GEMM)
    float i0 = 1.f / l0, i1 = 1.f / l1;
    size_t off0 = (size_t)(b * TT + q0w + g) * DD + h * HDIM + 2 * t4;
    size_t off1 = (size_t)(b * TT + q0w + g + 8) * DD + h * HDIM + 2 * t4;
#pragma unroll
    for (int j = 0; j < 8; j++) {
        uint32_t hh, ll;
        split2h(O[j][0] * i0, O[j][1] * i0, hh, ll);
        *(uint32_t*)(yhi + off0 + 8 * j) = hh;
        *(uint32_t*)(ylo + off0 + 8 * j) = ll;
        split2h(O[j][2] * i1, O[j][3] * i1, hh, ll);
        *(uint32_t*)(yhi + off1 + 8 * j) = hh;
        *(uint32_t*)(ylo + off1 + 8 * j) = ll;
    }
}

// ---------------------------------------------------------------------------
// Host launcher
// ---------------------------------------------------------------------------
extern "C" void kernel_launch(void* const* d_in, const int* in_sizes, int n_in,
                              void* d_out, int out_size) {
    const int*   idx    = (const int*)  d_in[0];
    const float* wte    = (const float*)d_in[1];
    const float* wpe    = (const float*)d_in[2];
    const float* ln1_s  = (const float*)d_in[3];
    const float* ln1_b  = (const float*)d_in[4];
    const float* qkv_w  = (const float*)d_in[5];
    const float* proj_w = (const float*)d_in[6];
    const float* ln2_s  = (const float*)d_in[7];
    const float* ln2_b  = (const float*)d_in[8];
    const float* fc_w   = (const float*)d_in[9];
    const float* fc_b   = (const float*)d_in[10];
    const float* fc2_w  = (const float*)d_in[11];
    const float* fc2_b  = (const float*)d_in[12];
    const float* lnf_s  = (const float*)d_in[13];
    const float* lnf_b  = (const float*)d_in[14];
    const float* lm_w   = (const float*)d_in[15];
    float* out = (float*)d_out;

    float *x, *qarr;
    bf16 *k_hi, *k_lo, *v_hi, *v_lo;
    bf16 *h_hi, *h_lo, *y_hi, *y_lo, *gg_hi, *gg_lo;
    bf16 *qw, *pw, *fw, *f2w, *lw;
    cudaGetSymbolAddress((void**)&x,     g_x);
    cudaGetSymbolAddress((void**)&qarr,  g_q);
    cudaGetSymbolAddress((void**)&k_hi,  g_k_hi);   cudaGetSymbolAddress((void**)&k_lo,  g_k_lo);
    cudaGetSymbolAddress((void**)&v_hi,  g_v_hi);   cudaGetSymbolAddress((void**)&v_lo,  g_v_lo);
    cudaGetSymbolAddress((void**)&h_hi,  g_h_hi);   cudaGetSymbolAddress((void**)&h_lo,  g_h_lo);
    cudaGetSymbolAddress((void**)&y_hi,  g_y_hi);   cudaGetSymbolAddress((void**)&y_lo,  g_y_lo);
    cudaGetSymbolAddress((void**)&gg_hi, g_g_hi);   cudaGetSymbolAddress((void**)&gg_lo, g_g_lo);
    cudaGetSymbolAddress((void**)&qw,  g_qkvw);
    cudaGetSymbolAddress((void**)&pw,  g_projw);
    cudaGetSymbolAddress((void**)&fw,  g_fcw);
    cudaGetSymbolAddress((void**)&f2w, g_fc2w);
    cudaGetSymbolAddress((void**)&lw,  g_lmw);

    cudaFuncSetAttribute(gemm2h<2>, cudaFuncAttributeMaxDynamicSharedMemorySize, GSM2_MF2);
    cudaFuncSetAttribute(gemm2h<4>, cudaFuncAttributeMaxDynamicSharedMemorySize, GSM2_MF4);

    embed_kernel<<<MM, 256>>>(idx, wte, wpe, x);

    {
        int nq = LL * 3 * DD * DD, np = LL * DD * DD;
        int nf = LL * 4 * DD * DD, n2 = LL * 4 * DD * DD, nl = VV * DD;
        int maxn = nf;
        dim3 grid((maxn / 4 + 255) / 256, 5);
        wsplit_all<<<grid, 256>>>(qkv_w,  qw,  nq,
                                  proj_w, pw,  np,
                                  fc_w,   fw,  nf,
                                  fc2_w,  f2w, n2,
                                  lm_w,   lw,  nl);
    }

    for (int l = 0; l < LL; l++) {
        const __half* qwh = (const __half*)(qw  + (size_t)l * 3 * DD * DD);
        const __half* pwh = (const __half*)(pw  + (size_t)l * DD * DD);
        const __half* fwh = (const __half*)(fw  + (size_t)l * 4 * DD * DD);
        const __half* f2h = (const __half*)(f2w + (size_t)l * 4 * DD * DD);
        const float* fb  = fc_b  + (size_t)l * 4 * DD;
        const float* f2b = fc2_b + (size_t)l * DD;

        ln_split_kernel<<<MM, 256>>>(x, ln1_s + l * DD, ln1_b + l * DD, h_hi, h_lo);
        // qkv: fp16 2-pass, MF=2, grid 24x32 = 768. Epilogue: q fp32, K/V bf16 hi/lo.
        gemm2h<2><<<dim3(3 * DD / BN, MM / 64), 256, GSM2_MF2>>>(
            (const __half*)h_hi, (const __half*)h_lo, qwh,
            nullptr, nullptr, qarr, nullptr, nullptr,
            k_hi, k_lo, v_hi, v_lo, MM, 3 * DD, DD, FLAG_QKV);
        attn_mma<<<dim3(TT / AQ, HH, BB), 256>>>(qarr, k_hi, k_lo, v_hi, v_lo, y_hi, y_lo);
        // proj: fp16 2-pass, MF=2, grid 8x32 = 256
        gemm2h<2><<<dim3(DD / BN, MM / 64), 256, GSM2_MF2>>>(
            (const __half*)y_hi, (const __half*)y_lo, pwh,
            nullptr, x, x, nullptr, nullptr,
            nullptr, nullptr, nullptr, nullptr, MM, DD, DD, FLAG_RES);
        ln_split_kernel<<<MM, 256>>>(x, ln2_s + l * DD, ln2_b + l * DD, h_hi, h_lo);
        // fc: fp16 2-pass, MF=4, grid 32x16 = 512; gelu + fp16 split out
        gemm2h<4><<<dim3(4 * DD / BN, MM / 128), 256, GSM2_MF4>>>(
            (const __half*)h_hi, (const __half*)h_lo, fwh,
            fb, nullptr, nullptr, (__half*)gg_hi, (__half*)gg_lo,
            nullptr, nullptr, nullptr, nullptr,
            MM, 4 * DD, DD, FLAG_BIAS | FLAG_GELU | FLAG_SPLIT);
        // fc2: fp16 2-pass, MF=2, grid 8x32 = 256
        gemm2h<2><<<dim3(DD / BN, MM / 64), 256, GSM2_MF2>>>(
            (const __half*)gg_hi, (const __half*)gg_lo, f2h,
            f2b, x, x, nullptr, nullptr,
            nullptr, nullptr, nullptr, nullptr, MM, DD, 4 * DD, FLAG_BIAS | FLAG_RES);
    }

    // lnf -> fp16 hi/lo
    ln_split_kernel<<<MM, 256>>>(x, lnf_s, lnf_b, h_hi, h_lo);
    // lm: fp16 2-pass, MF=4, grid 250x16 = 4000
    gemm2h<4><<<dim3(VV / BN, MM / 128), 256, GSM2_MF4>>>(
        (const __half*)h_hi, (const __half*)h_lo, (const __half*)lw,
        nullptr, nullptr, out, nullptr, nullptr,
        nullptr, nullptr, nullptr, nullptr, MM, VV, DD, 0);
}

// round 15
// speedup vs baseline: 1.7024x; 1.0283x over previous
#include <cuda_runtime.h>
#include <cuda_bf16.h>
#include <cuda_fp16.h>
#include <math.h>
#include <stdint.h>

// Model dims
#define BB   2
#define TT   1024
#define DD   1024
#define HH   16
#define HDIM 64
#define LL   8
#define VV   32000
#define MM   (BB*TT)   // 2048 tokens

typedef __nv_bfloat16 bf16;
typedef __nv_bfloat162 bf162;

// GEMM tiling
#define BN 128
#define BK 32
#define NSTAGE 3

// Attention tiling
#define AQ  128
#define AKT 64
#define LDV 72
#define NEGINF (-1e30f)

// fp32 scratch
__device__ float g_x[MM * DD];
__device__ float g_q[MM * DD];                                // q (fp32)
// K/V single fp16 (written by qkv GEMM epilogue)
__device__ bf16 g_k[MM * DD], g_v[MM * DD];                   // fp16 payload
// fp16 activation scratch (hi/lo pairs)
__device__ bf16 g_h_hi[MM * DD],     g_h_lo[MM * DD];
__device__ bf16 g_y_hi[MM * DD],     g_y_lo[MM * DD];
__device__ bf16 g_g_hi[MM * 4 * DD], g_g_lo[MM * 4 * DD];
// weights: all single fp16
__device__ bf16 g_qkvw[LL * 3 * DD * DD];
__device__ bf16 g_projw[LL * DD * DD];
__device__ bf16 g_fcw [LL * 4 * DD * DD];
__device__ bf16 g_fc2w[LL * 4 * DD * DD];
__device__ bf16 g_lmw [VV * DD];

// ---------------------------------------------------------------------------
// Small helpers
// ---------------------------------------------------------------------------
__device__ __forceinline__ void split2h(float x, float y, uint32_t& hi, uint32_t& lo) {
    __half2 hp, lp;
    hp.x = __float2half_rn(x); hp.y = __float2half_rn(y);
    lp.x = __float2half_rn(x - __half2float(hp.x));
    lp.y = __float2half_rn(y - __half2float(hp.y));
    hi = *(uint32_t*)&hp; lo = *(uint32_t*)&lp;
}

__device__ __forceinline__ uint32_t pack2h(float x, float y) {
    __half2 p;
    p.x = __float2half_rn(x); p.y = __float2half_rn(y);
    return *(uint32_t*)&p;
}

__device__ __forceinline__ void ldm_x4(uint32_t& r0, uint32_t& r1, uint32_t& r2, uint32_t& r3,
                                       uint32_t addr) {
    asm volatile("ldmatrix.sync.aligned.m8n8.x4.shared.b16 {%0,%1,%2,%3}, [%4];\n"
                 : "=r"(r0), "=r"(r1), "=r"(r2), "=r"(r3) : "r"(addr));
}

__device__ __forceinline__ void ldm_x4_t(uint32_t& r0, uint32_t& r1, uint32_t& r2, uint32_t& r3,
                                         uint32_t addr) {
    asm volatile("ldmatrix.sync.aligned.m8n8.x4.trans.shared.b16 {%0,%1,%2,%3}, [%4];\n"
                 : "=r"(r0), "=r"(r1), "=r"(r2), "=r"(r3) : "r"(addr));
}

__device__ __forceinline__ void mma16816h(float* d, const uint32_t* a, const uint32_t* b) {
    asm volatile(
        "mma.sync.aligned.m16n8k16.row.col.f32.f16.f16.f32 "
        "{%0,%1,%2,%3}, {%4,%5,%6,%7}, {%8,%9}, {%0,%1,%2,%3};\n"
        : "+f"(d[0]), "+f"(d[1]), "+f"(d[2]), "+f"(d[3])
        : "r"(a[0]), "r"(a[1]), "r"(a[2]), "r"(a[3]), "r"(b[0]), "r"(b[1]));
}

__device__ __forceinline__ void cp16(uint32_t dst, const void* src) {
    asm volatile("cp.async.cg.shared.global [%0], [%1], 16;\n" :: "r"(dst), "l"(src));
}

// swizzled byte offset within one Rx32(16-bit) tile: row r, 16B chunk c (0..3)
__device__ __forceinline__ uint32_t swz(int r, int c) {
    return (uint32_t)(r * 64 + ((c ^ ((r >> 1) & 3)) << 4));
}

// ---------------------------------------------------------------------------
// Fused weight cast: all 5 arrays fp32 -> fp16 single
// ---------------------------------------------------------------------------
__global__ void wsplit_all(const float* s0, bf16* d0, int n0,
                           const float* s1, bf16* d1, int n1,
                           const float* s2, bf16* d2, int n2,
                           const float* s3, bf16* d3, int n3,
                           const float* s4, bf16* d4, int n4) {
    const float* src; __half* dst; int n;
    switch (blockIdx.y) {
        case 0: src = s0; dst = (__half*)d0; n = n0; break;
        case 1: src = s1; dst = (__half*)d1; n = n1; break;
        case 2: src = s2; dst = (__half*)d2; n = n2; break;
        case 3: src = s3; dst = (__half*)d3; n = n3; break;
        default: src = s4; dst = (__half*)d4; n = n4; break;
    }
    int i = (blockIdx.x * blockDim.x + threadIdx.x) * 4;
    if (i >= n) return;
    float4 v = *(const float4*)(src + i);
    __half2 p0, p1;
    p0.x = __float2half_rn(v.x); p0.y = __float2half_rn(v.y);
    p1.x = __float2half_rn(v.z); p1.y = __float2half_rn(v.w);
    ((__half2*)(dst + i))[0] = p0;
    ((__half2*)(dst + i))[1] = p1;
}

// ---------------------------------------------------------------------------
// Embedding
// ---------------------------------------------------------------------------
__global__ void embed_kernel(const int* __restrict__ idx,
                             const float* __restrict__ wte,
                             const float* __restrict__ wpe,
                             float* __restrict__ x) {
    int token = blockIdx.x;
    int t = token % TT;
    int id = idx[token];
    const float4* src = (const float4*)(wte + (size_t)id * DD);
    const float4* pos = (const float4*)(wpe + (size_t)t * DD);
    float4* dst = (float4*)(x + (size_t)token * DD);
    for (int i = threadIdx.x; i < DD / 4; i += blockDim.x) {
        float4 a = src[i], b = pos[i];
        dst[i] = make_float4(a.x + b.x, a.y + b.y, a.z + b.z, a.w + b.w);
    }
}

// ---------------------------------------------------------------------------
// LayerNorm over D=1024 -> fp16 hi/lo
// ---------------------------------------------------------------------------
__global__ __launch_bounds__(256) void ln_split_kernel(const float* __restrict__ x,
                                                       const float* __restrict__ sc,
                                                       const float* __restrict__ bi,
                                                       bf16* __restrict__ ohi,
                                                       bf16* __restrict__ olo) {
    int token = blockIdx.x;
    const float4* xp = (const float4*)(x + (size_t)token * DD);
    float4 v = xp[threadIdx.x];
    float s = v.x + v.y + v.z + v.w;
    float q = v.x * v.x + v.y * v.y + v.z * v.z + v.w * v.w;
#pragma unroll
    for (int o = 16; o; o >>= 1) {
        s += __shfl_xor_sync(0xffffffffu, s, o);
        q += __shfl_xor_sync(0xffffffffu, q, o);
    }
    __shared__ float ss[8], sq[8];
    int w = threadIdx.x >> 5, l = threadIdx.x & 31;
    if (l == 0) { ss[w] = s; sq[w] = q; }
    __syncthreads();
    if (w == 0) {
        s = (l < 8) ? ss[l] : 0.f;
        q = (l < 8) ? sq[l] : 0.f;
#pragma unroll
        for (int o = 4; o; o >>= 1) {
            s += __shfl_xor_sync(0xffffffffu, s, o);
            q += __shfl_xor_sync(0xffffffffu, q, o);
        }
        if (l == 0) { ss[0] = s; sq[0] = q; }
    }
    __syncthreads();
    float mu  = ss[0] * (1.f / DD);
    float var = sq[0] * (1.f / DD) - mu * mu;
    float inv = rsqrtf(var + 1e-5f);
    float4 sv = ((const float4*)sc)[threadIdx.x];
    float4 bv = ((const float4*)bi)[threadIdx.x];
    float r0 = (v.x - mu) * inv * sv.x + bv.x;
    float r1 = (v.y - mu) * inv * sv.y + bv.y;
    float r2 = (v.z - mu) * inv * sv.z + bv.z;
    float r3 = (v.w - mu) * inv * sv.w + bv.w;
    size_t o = (size_t)token * DD + threadIdx.x * 4;
    uint32_t hh, ll;
    split2h(r0, r1, hh, ll);
    ((uint32_t*)(ohi + o))[0] = hh; ((uint32_t*)(olo + o))[0] = ll;
    split2h(r2, r3, hh, ll);
    ((uint32_t*)(ohi + o))[1] = hh; ((uint32_t*)(olo + o))[1] = ll;
}

// ---------------------------------------------------------------------------
#define FLAG_BIAS  1
#define FLAG_RES   2
#define FLAG_GELU  4
#define FLAG_SPLIT 8   // write C as fp16 hi/lo
#define FLAG_QKV   16  // qkv epilogue: q fp32, k/v single fp16 (stride DD each)

__device__ __forceinline__ float gelu_exact(float v) {
    return 0.5f * v * (1.f + erff(v * 0.70710678118654752f));
}

// ---------------------------------------------------------------------------
// fp16 2-pass GEMM NT: D = Ah*Bh + Al*Bh  (A split fp16, B single fp16).
// CTA (MF*32)x128, warp (MF*16)x32, BK=32, 3-stage pipeline, swizzled smem.
// ---------------------------------------------------------------------------
template<int MF>
__global__ __launch_bounds__(256) void gemm2h(const __half* __restrict__ Ah,
                                              const __half* __restrict__ Al,
                                              const __half* __restrict__ Bh,
                                              const float* __restrict__ bias,
                                              const float* res,
                                              float* C, __half* Chi, __half* Clo,
                                              __half* Karr, __half* Varr,
                                              int M, int N, int K, int flags) {
    constexpr int BMT   = MF * 32;
    constexpr int TILEA = BMT * 64;
    constexpr int TILEBB = 8192;
    constexpr int BUFB  = 2 * TILEA + TILEBB;
    constexpr int NCHUNK = (2 * BMT * 4 + 512) / 256;

    extern __shared__ __align__(16) bf16 sm[];
    int tid = threadIdx.x;
    int warp = tid >> 5, lane = tid & 31;
    int bm = blockIdx.y * BMT, bn = blockIdx.x * BN;
    int wm = (warp >> 2) * (MF * 16);
    int wn = (warp & 3) * 32;

    uint32_t smbase = (uint32_t)__cvta_generic_to_shared(sm);

    float acc[MF][4][4];
#pragma unroll
    for (int i = 0; i < MF; i++)
#pragma unroll
        for (int j = 0; j < 4; j++)
#pragma unroll
            for (int r = 0; r < 4; r++) acc[i][j][r] = 0.f;

    int a_r = ((lane >> 3) & 1) * 8 + (lane & 7);
    int a_c = (lane >> 4) * 8;
    int b_r = (lane >> 4) * 8 + (lane & 7);
    int b_c = ((lane >> 3) & 1) * 8;

    const __half* srcA[2] = { Ah, Al };

    auto stage = [&](int s_idx, int buf) {
        int k0 = s_idx * BK;
        uint32_t bufoff = smbase + (uint32_t)(buf * BUFB);
#pragma unroll
        for (int i = 0; i < NCHUNK; i++) {
            int cid = tid + i * 256;
            if (cid < 2 * BMT * 4) {
                int arr = cid / (BMT * 4);
                int sub = cid - arr * (BMT * 4);
                int row = sub >> 2;
                int c = sub & 3;
                const __half* src = srcA[arr] + (size_t)(bm + row) * K + k0 + c * 8;
                cp16(bufoff + (uint32_t)(arr * TILEA) + swz(row, c), src);
            } else {
                int sub = cid - 2 * BMT * 4;
                int row = sub >> 2;
                int c = sub & 3;
                const __half* src = Bh + (size_t)(bn + row) * K + k0 + c * 8;
                cp16(bufoff + (uint32_t)(2 * TILEA) + swz(row, c), src);
            }
        }
        asm volatile("cp.async.commit_group;\n");
    };

    int S = K / BK;
    stage(0, 0);
    stage(1, 1);

    for (int s = 0; s < S; s++) {
        int buf = s - (s / NSTAGE) * NSTAGE;
        if (s == S - 1) asm volatile("cp.async.wait_group 0;\n");
        else            asm volatile("cp.async.wait_group 1;\n");
        __syncthreads();
        if (s + 2 < S) stage(s + 2, (s + 2) % NSTAGE);

        uint32_t offAh = smbase + (uint32_t)(buf * BUFB);
        uint32_t offAl = offAh + TILEA;
        uint32_t offB  = offAl + TILEA;

#pragma unroll
        for (int ks = 0; ks < BK; ks += 16) {
            uint32_t ah[MF][4], al[MF][4], bh[4][2];
#pragma unroll
            for (int mf = 0; mf < MF; mf++) {
                int row = wm + mf * 16 + a_r;
                ldm_x4(ah[mf][0], ah[mf][1], ah[mf][2], ah[mf][3],
                       offAh + swz(row, (ks + a_c) >> 3));
            }
#pragma unroll
            for (int p = 0; p < 2; p++) {
                int row = wn + p * 16 + b_r;
                uint32_t r0, r1, r2, r3;
                ldm_x4(r0, r1, r2, r3, offB + swz(row, (ks + b_c) >> 3));
                bh[2 * p][0] = r0; bh[2 * p][1] = r1;
                bh[2 * p + 1][0] = r2; bh[2 * p + 1][1] = r3;
            }
#pragma unroll
            for (int mf = 0; mf < MF; mf++)
#pragma unroll
                for (int nf = 0; nf < 4; nf++)
                    mma16816h(acc[mf][nf], ah[mf], bh[nf]);

#pragma unroll
            for (int mf = 0; mf < MF; mf++) {
                int row = wm + mf * 16 + a_r;
                ldm_x4(al[mf][0], al[mf][1], al[mf][2], al[mf][3],
                       offAl + swz(row, (ks + a_c) >> 3));
            }
#pragma unroll
            for (int mf = 0; mf < MF; mf++)
#pragma unroll
                for (int nf = 0; nf < 4; nf++)
                    mma16816h(acc[mf][nf], al[mf], bh[nf]);
        }
    }

    int gid = lane >> 2, tg = lane & 3;
#pragma unroll
    for (int mf = 0; mf < MF; mf++) {
#pragma unroll
        for (int half = 0; half < 2; half++) {
            int row = bm + wm + mf * 16 + half * 8 + gid;
#pragma unroll
            for (int nf = 0; nf < 4; nf++) {
                int col = bn + wn + nf * 8 + tg * 2;
                float2 o;
                o.x = acc[mf][nf][half * 2 + 0];
                o.y = acc[mf][nf][half * 2 + 1];
                if (flags & FLAG_QKV) {
                    // q fp32 [0,DD); k fp16 [DD,2DD); v fp16 [2DD,3DD)
                    if (col < DD) {
                        *(float2*)(C + (size_t)row * DD + col) = o;
                    } else if (col < 2 * DD) {
                        *(uint32_t*)(Karr + (size_t)row * DD + (col - DD)) = pack2h(o.x, o.y);
                    } else {
                        *(uint32_t*)(Varr + (size_t)row * DD + (col - 2 * DD)) = pack2h(o.x, o.y);
                    }
                    continue;
                }
                if (flags & FLAG_BIAS) { o.x += bias[col]; o.y += bias[col + 1]; }
                if (flags & FLAG_GELU) { o.x = gelu_exact(o.x); o.y = gelu_exact(o.y); }
                if (flags & FLAG_RES) {
                    float2 r = *(const float2*)(res + (size_t)row * N + col);
                    o.x += r.x; o.y += r.y;
                }
                if (flags & FLAG_SPLIT) {
                    size_t off = (size_t)row * N + col;
                    uint32_t hh, ll;
                    split2h(o.x, o.y, hh, ll);
                    *(uint32_t*)(Chi + off) = hh;
                    *(uint32_t*)(Clo + off) = ll;
                } else {
                    *(float2*)(C + (size_t)row * N + col) = o;
                }
            }
        }
    }
}

// Dynamic smem sizes
#define GSM2_MF2 (NSTAGE * (2 * 64 * 64 + 8192))        // 49152
#define GSM2_MF4 (NSTAGE * (2 * 128 * 64 + 8192))       // 73728

// ---------------------------------------------------------------------------
// Causal attention via fp16 mma (2-pass split on Q and P; K,V single fp16).
// K/V staged by pure cp.async. y out fp16 hi/lo.
// ---------------------------------------------------------------------------
__global__ __launch_bounds__(256) void attn_mma(const float* __restrict__ qarr,
                                                const __half* __restrict__ karr,
                                                const __half* __restrict__ varr,
                                                bf16* __restrict__ yhi,
                                                bf16* __restrict__ ylo) {
    int b = blockIdx.z, h = blockIdx.y;
    int bx = gridDim.x - 1 - blockIdx.x;
    int tid = threadIdx.x;
    int warp = tid >> 5, lane = tid & 31;
    int g = lane >> 2, t4 = lane & 3;
    int q0w = bx * AQ + warp * 16;

    __shared__ __align__(16) __half K_s[AKT * LDV];
    __shared__ __align__(16) __half V_s[AKT * LDV];
    uint32_t aK = (uint32_t)__cvta_generic_to_shared(K_s);
    uint32_t aV = (uint32_t)__cvta_generic_to_shared(V_s);
    uint32_t abase[2] = { aK, aV };

    // Q a-frags (scaled by 1/8), fp16 hi/lo
    uint32_t qh[4][4], ql[4][4];
    {
        const float* qbase = qarr + (size_t)(b * TT) * DD + h * HDIM;
        const float* r0p = qbase + (size_t)(q0w + g) * DD;
        const float* r1p = qbase + (size_t)(q0w + g + 8) * DD;
#pragma unroll
        for (int c = 0; c < 4; c++) {
            float2 v00 = *(const float2*)(r0p + c * 16 + 2 * t4);
            float2 v10 = *(const float2*)(r1p + c * 16 + 2 * t4);
            float2 v01 = *(const float2*)(r0p + c * 16 + 2 * t4 + 8);
            float2 v11 = *(const float2*)(r1p + c * 16 + 2 * t4 + 8);
            split2h(v00.x * 0.125f, v00.y * 0.125f, qh[c][0], ql[c][0]);
            split2h(v10.x * 0.125f, v10.y * 0.125f, qh[c][1], ql[c][1]);
            split2h(v01.x * 0.125f, v01.y * 0.125f, qh[c][2], ql[c][2]);
            split2h(v11.x * 0.125f, v11.y * 0.125f, qh[c][3], ql[c][3]);
        }
    }

    float O[8][4];
#pragma unroll
    for (int j = 0; j < 8; j++)
#pragma unroll
        for (int r = 0; r < 4; r++) O[j][r] = 0.f;
    float m0 = NEGINF, m1 = NEGINF, l0 = 0.f, l1 = 0.f;

    int b_r = (lane >> 4) * 8 + (lane & 7);
    int b_c = ((lane >> 3) & 1) * 8;
    int v_r = (lane & 7) + ((lane >> 3) & 1) * 8;
    int v_c = (lane >> 4) * 8;

    const __half* gsrc[2] = {
        karr + (size_t)(b * TT) * DD + h * HDIM,
        varr + (size_t)(b * TT) * DD + h * HDIM
    };

    int ntiles = bx * 2 + 2;
    for (int tile = 0; tile < ntiles; tile++) {
        int kt = tile * AKT;
        __syncthreads();
        // stage K,V tile: 2 arrays x 64 rows x 8 chunks(16B) = 1024 chunks
#pragma unroll
        for (int i = 0; i < 4; i++) {
            int cid = tid + i * 256;       // 0..1023
            int arr = cid >> 9;
            int sub = cid & 511;
            int kk = sub >> 3;
            int c8 = sub & 7;
            const __half* src = gsrc[arr] + (size_t)(kt + kk) * DD + c8 * 8;
            cp16(abase[arr] + (uint32_t)(kk * LDV + c8 * 8) * 2, src);
        }
        asm volatile("cp.async.commit_group;\n" ::: "memory");
        asm volatile("cp.async.wait_group 0;\n" ::: "memory");
        __syncthreads();

        if (kt > q0w + 15) continue;

        // ----- S = Q K^T (2-pass: Qh*K + Ql*K) -----
        float S[8][4];
#pragma unroll
        for (int j = 0; j < 8; j++)
#pragma unroll
            for (int r = 0; r < 4; r++) S[j][r] = 0.f;

#pragma unroll
        for (int c = 0; c < 4; c++) {
            uint32_t kf[8][2];
#pragma unroll
            for (int p = 0; p < 4; p++) {
                uint32_t r0, r1, r2, r3;
                ldm_x4(r0, r1, r2, r3, aK + (uint32_t)((16 * p + b_r) * LDV + 16 * c + b_c) * 2);
                kf[2 * p][0] = r0; kf[2 * p][1] = r1;
                kf[2 * p + 1][0] = r2; kf[2 * p + 1][1] = r3;
            }
#pragma unroll
            for (int j = 0; j < 8; j++) mma16816h(S[j], qh[c], kf[j]);
#pragma unroll
            for (int j = 0; j < 8; j++) mma16816h(S[j], ql[c], kf[j]);
        }

        if (kt + AKT - 1 > q0w) {
            int row0 = q0w + g, row1 = q0w + g + 8;
#pragma unroll
            for (int j = 0; j < 8; j++) {
                int col = kt + 8 * j + 2 * t4;
                if (col > row0)     S[j][0] = NEGINF;
                if (col + 1 > row0) S[j][1] = NEGINF;
                if (col > row1)     S[j][2] = NEGINF;
                if (col + 1 > row1) S[j][3] = NEGINF;
            }
        }

        float mx0 = NEGINF, mx1 = NEGINF;
#pragma unroll
        for (int j = 0; j < 8; j++) {
            mx0 = fmaxf(mx0, fmaxf(S[j][0], S[j][1]));
            mx1 = fmaxf(mx1, fmaxf(S[j][2], S[j][3]));
        }
        mx0 = fmaxf(mx0, __shfl_xor_sync(0xffffffffu, mx0, 1));
        mx0 = fmaxf(mx0, __shfl_xor_sync(0xffffffffu, mx0, 2));
        mx1 = fmaxf(mx1, __shfl_xor_sync(0xffffffffu, mx1, 1));
        mx1 = fmaxf(mx1, __shfl_xor_sync(0xffffffffu, mx1, 2));
        float m0n = fmaxf(m0, mx0), m1n = fmaxf(m1, mx1);
        float c0 = __expf(m0 - m0n), c1 = __expf(m1 - m1n);
        float s0 = 0.f, s1 = 0.f;
#pragma unroll
        for (int j = 0; j < 8; j++) {
            S[j][0] = __expf(S[j][0] - m0n);
            S[j][1] = __expf(S[j][1] - m0n);
            S[j][2] = __expf(S[j][2] - m1n);
            S[j][3] = __expf(S[j][3] - m1n);
            s0 += S[j][0] + S[j][1];
            s1 += S[j][2] + S[j][3];
        }
        s0 += __shfl_xor_sync(0xffffffffu, s0, 1);
        s0 += __shfl_xor_sync(0xffffffffu, s0, 2);
        s1 += __shfl_xor_sync(0xffffffffu, s1, 1);
        s1 += __shfl_xor_sync(0xffffffffu, s1, 2);
        l0 = l0 * c0 + s0;
        l1 = l1 * c1 + s1;
        m0 = m0n; m1 = m1n;
#pragma unroll
        for (int j = 0; j < 8; j++) {
            O[j][0] *= c0; O[j][1] *= c0;
            O[j][2] *= c1; O[j][3] *= c1;
        }

        // ----- O += P V (2-pass: Ph*V + Pl*V) -----
#pragma unroll
        for (int kk = 0; kk < 4; kk++) {
            uint32_t ph[4], pl[4];
            split2h(S[2 * kk][0],     S[2 * kk][1],     ph[0], pl[0]);
            split2h(S[2 * kk][2],     S[2 * kk][3],     ph[1], pl[1]);
            split2h(S[2 * kk + 1][0], S[2 * kk + 1][1], ph[2], pl[2]);
            split2h(S[2 * kk + 1][2], S[2 * kk + 1][3], ph[3], pl[3]);

            uint32_t vf[8][2];
#pragma unroll
            for (int ds = 0; ds < 4; ds++) {
                uint32_t r0, r1, r2, r3;
                ldm_x4_t(r0, r1, r2, r3, aV + (uint32_t)((16 * kk + v_r) * LDV + 16 * ds + v_c) * 2);
                vf[2 * ds][0] = r0; vf[2 * ds][1] = r1;
                vf[2 * ds + 1][0] = r2; vf[2 * ds + 1][1] = r3;
            }
#pragma unroll
            for (int j = 0; j < 8; j++) mma16816h(O[j], ph, vf[j]);
#pragma unroll
            for (int j = 0; j < 8; j++) mma16816h(O[j], pl, vf[j]);
        }
    }

    // epilogue: y as fp16 hi/lo (consumed by fp16 proj GEMM)
    float i0 = 1.f / l0, i1 = 1.f / l1;
    size_t off0 = (size_t)(b * TT + q0w + g) * DD + h * HDIM + 2 * t4;
    size_t off1 = (size_t)(b * TT + q0w + g + 8) * DD + h * HDIM + 2 * t4;
#pragma unroll
    for (int j = 0; j < 8; j++) {
        uint32_t hh, ll;
        split2h(O[j][0] * i0, O[j][1] * i0, hh, ll);
        *(uint32_t*)(yhi + off0 + 8 * j) = hh;
        *(uint32_t*)(ylo + off0 + 8 * j) = ll;
        split2h(O[j][2] * i1, O[j][3] * i1, hh, ll);
        *(uint32_t*)(yhi + off1 + 8 * j) = hh;
        *(uint32_t*)(ylo + off1 + 8 * j) = ll;
    }
}

// ---------------------------------------------------------------------------
// Host launcher
// ---------------------------------------------------------------------------
extern "C" void kernel_launch(void* const* d_in, const int* in_sizes, int n_in,
                              void* d_out, int out_size) {
    const int*   idx    = (const int*)  d_in[0];
    const float* wte    = (const float*)d_in[1];
    const float* wpe    = (const float*)d_in[2];
    const float* ln1_s  = (const float*)d_in[3];
    const float* ln1_b  = (const float*)d_in[4];
    const float* qkv_w  = (const float*)d_in[5];
    const float* proj_w = (const float*)d_in[6];
    const float* ln2_s  = (const float*)d_in[7];
    const float* ln2_b  = (const float*)d_in[8];
    const float* fc_w   = (const float*)d_in[9];
    const float* fc_b   = (const float*)d_in[10];
    const float* fc2_w  = (const float*)d_in[11];
    const float* fc2_b  = (const float*)d_in[12];
    const float* lnf_s  = (const float*)d_in[13];
    const float* lnf_b  = (const float*)d_in[14];
    const float* lm_w   = (const float*)d_in[15];
    float* out = (float*)d_out;

    float *x, *qarr;
    bf16 *karr, *varr;
    bf16 *h_hi, *h_lo, *y_hi, *y_lo, *gg_hi, *gg_lo;
    bf16 *qw, *pw, *fw, *f2w, *lw;
    cudaGetSymbolAddress((void**)&x,     g_x);
    cudaGetSymbolAddress((void**)&qarr,  g_q);
    cudaGetSymbolAddress((void**)&karr,  g_k);
    cudaGetSymbolAddress((void**)&varr,  g_v);
    cudaGetSymbolAddress((void**)&h_hi,  g_h_hi);   cudaGetSymbolAddress((void**)&h_lo,  g_h_lo);
    cudaGetSymbolAddress((void**)&y_hi,  g_y_hi);   cudaGetSymbolAddress((void**)&y_lo,  g_y_lo);
    cudaGetSymbolAddress((void**)&gg_hi, g_g_hi);   cudaGetSymbolAddress((void**)&gg_lo, g_g_lo);
    cudaGetSymbolAddress((void**)&qw,  g_qkvw);
    cudaGetSymbolAddress((void**)&pw,  g_projw);
    cudaGetSymbolAddress((void**)&fw,  g_fcw);
    cudaGetSymbolAddress((void**)&f2w, g_fc2w);
    cudaGetSymbolAddress((void**)&lw,  g_lmw);

    cudaFuncSetAttribute(gemm2h<2>, cudaFuncAttributeMaxDynamicSharedMemorySize, GSM2_MF2);
    cudaFuncSetAttribute(gemm2h<4>, cudaFuncAttributeMaxDynamicSharedMemorySize, GSM2_MF4);

    embed_kernel<<<MM, 256>>>(idx, wte, wpe, x);

    {
        int nq = LL * 3 * DD * DD, np = LL * DD * DD;
        int nf = LL * 4 * DD * DD, n2 = LL * 4 * DD * DD, nl = VV * DD;
        int maxn = nf;
        dim3 grid((maxn / 4 + 255) / 256, 5);
        wsplit_all<<<grid, 256>>>(qkv_w,  qw,  nq,
                                  proj_w, pw,  np,
                                  fc_w,   fw,  nf,
                                  fc2_w,  f2w, n2,
                                  lm_w,   lw,  nl);
    }

    for (int l = 0; l < LL; l++) {
        const __half* qwh = (const __half*)(qw  + (size_t)l * 3 * DD * DD);
        const __half* pwh = (const __half*)(pw  + (size_t)l * DD * DD);
        const __half* fwh = (const __half*)(fw  + (size_t)l * 4 * DD * DD);
        const __half* f2h = (const __half*)(f2w + (size_t)l * 4 * DD * DD);
        const float* fb  = fc_b  + (size_t)l * 4 * DD;
        const float* f2b = fc2_b + (size_t)l * DD;

        ln_split_kernel<<<MM, 256>>>(x, ln1_s + l * DD, ln1_b + l * DD, h_hi, h_lo);
        // qkv: fp16 2-pass, MF=2, grid 24x32 = 768. Epilogue: q fp32, K/V fp16.
        gemm2h<2><<<dim3(3 * DD / BN, MM / 64), 256, GSM2_MF2>>>(
            (const __half*)h_hi, (const __half*)h_lo, qwh,
            nullptr, nullptr, qarr, nullptr, nullptr,
            (__half*)karr, (__half*)varr, MM, 3 * DD, DD, FLAG_QKV);
        attn_mma<<<dim3(TT / AQ, HH, BB), 256>>>(qarr, (const __half*)karr,
                                                 (const __half*)varr, y_hi, y_lo);
        // proj: fp16 2-pass, MF=2, grid 8x32 = 256
        gemm2h<2><<<dim3(DD / BN, MM / 64), 256, GSM2_MF2>>>(
            (const __half*)y_hi, (const __half*)y_lo, pwh,
            nullptr, x, x, nullptr, nullptr,
            nullptr, nullptr, MM, DD, DD, FLAG_RES);
        ln_split_kernel<<<MM, 256>>>(x, ln2_s + l * DD, ln2_b + l * DD, h_hi, h_lo);
        // fc: fp16 2-pass, MF=4, grid 32x16 = 512; gelu + fp16 split out
        gemm2h<4><<<dim3(4 * DD / BN, MM / 128), 256, GSM2_MF4>>>(
            (const __half*)h_hi, (const __half*)h_lo, fwh,
            fb, nullptr, nullptr, (__half*)gg_hi, (__half*)gg_lo,
            nullptr, nullptr, MM, 4 * DD, DD, FLAG_BIAS | FLAG_GELU | FLAG_SPLIT);
        // fc2: fp16 2-pass, MF=2, grid 8x32 = 256
        gemm2h<2><<<dim3(DD / BN, MM / 64), 256, GSM2_MF2>>>(
            (const __half*)gg_hi, (const __half*)gg_lo, f2h,
            f2b, x, x, nullptr, nullptr,
            nullptr, nullptr, MM, DD, 4 * DD, FLAG_BIAS | FLAG_RES);
    }

    // lnf -> fp16 hi/lo
    ln_split_kernel<<<MM, 256>>>(x, lnf_s, lnf_b, h_hi, h_lo);
    // lm: fp16 2-pass, MF=4, grid 250x16 = 4000
    gemm2h<4><<<dim3(VV / BN, MM / 128), 256, GSM2_MF4>>>(
        (const __half*)h_hi, (const __half*)h_lo, (const __half*)lw,
        nullptr, nullptr, out, nullptr, nullptr,
        nullptr, nullptr, MM, VV, DD, 0);
}

// round 16
// speedup vs baseline: 1.7570x; 1.0320x over previous
#include <cuda_runtime.h>
#include <cuda_bf16.h>
#include <cuda_fp16.h>
#include <math.h>
#include <stdint.h>

// Model dims
#define BB   2
#define TT   1024
#define DD   1024
#define HH   16
#define HDIM 64
#define LL   8
#define VV   32000
#define MM   (BB*TT)   // 2048 tokens

typedef __nv_bfloat16 bf16;
typedef __nv_bfloat162 bf162;

// GEMM tiling
#define BN 128
#define BK 32
#define NSTAGE 3

// Attention tiling
#define AQ  128
#define AKT 64
#define LDV 72
#define NEGINF (-1e30f)

// fp32 scratch
__device__ float g_x[MM * DD];
__device__ float g_q[MM * DD];                                // q (fp32)
// K/V single fp16 (written by qkv GEMM epilogue)
__device__ bf16 g_k[MM * DD], g_v[MM * DD];                   // fp16 payload
// fp16 activation scratch (hi/lo pairs)
__device__ bf16 g_h_hi[MM * DD],     g_h_lo[MM * DD];
__device__ bf16 g_y_hi[MM * DD],     g_y_lo[MM * DD];
__device__ bf16 g_g_hi[MM * 4 * DD], g_g_lo[MM * 4 * DD];
// weights: all single fp16
__device__ bf16 g_qkvw[LL * 3 * DD * DD];
__device__ bf16 g_projw[LL * DD * DD];
__device__ bf16 g_fcw [LL * 4 * DD * DD];
__device__ bf16 g_fc2w[LL * 4 * DD * DD];
__device__ bf16 g_lmw [VV * DD];

// ---------------------------------------------------------------------------
// Small helpers
// ---------------------------------------------------------------------------
__device__ __forceinline__ void split2h(float x, float y, uint32_t& hi, uint32_t& lo) {
    __half2 hp, lp;
    hp.x = __float2half_rn(x); hp.y = __float2half_rn(y);
    lp.x = __float2half_rn(x - __half2float(hp.x));
    lp.y = __float2half_rn(y - __half2float(hp.y));
    hi = *(uint32_t*)&hp; lo = *(uint32_t*)&lp;
}

__device__ __forceinline__ uint32_t pack2h(float x, float y) {
    __half2 p;
    p.x = __float2half_rn(x); p.y = __float2half_rn(y);
    return *(uint32_t*)&p;
}

__device__ __forceinline__ void ldm_x4(uint32_t& r0, uint32_t& r1, uint32_t& r2, uint32_t& r3,
                                       uint32_t addr) {
    asm volatile("ldmatrix.sync.aligned.m8n8.x4.shared.b16 {%0,%1,%2,%3}, [%4];\n"
                 : "=r"(r0), "=r"(r1), "=r"(r2), "=r"(r3) : "r"(addr));
}

__device__ __forceinline__ void ldm_x4_t(uint32_t& r0, uint32_t& r1, uint32_t& r2, uint32_t& r3,
                                         uint32_t addr) {
    asm volatile("ldmatrix.sync.aligned.m8n8.x4.trans.shared.b16 {%0,%1,%2,%3}, [%4];\n"
                 : "=r"(r0), "=r"(r1), "=r"(r2), "=r"(r3) : "r"(addr));
}

__device__ __forceinline__ void mma16816h(float* d, const uint32_t* a, const uint32_t* b) {
    asm volatile(
        "mma.sync.aligned.m16n8k16.row.col.f32.f16.f16.f32 "
        "{%0,%1,%2,%3}, {%4,%5,%6,%7}, {%8,%9}, {%0,%1,%2,%3};\n"
        : "+f"(d[0]), "+f"(d[1]), "+f"(d[2]), "+f"(d[3])
        : "r"(a[0]), "r"(a[1]), "r"(a[2]), "r"(a[3]), "r"(b[0]), "r"(b[1]));
}

__device__ __forceinline__ void cp16(uint32_t dst, const void* src) {
    asm volatile("cp.async.cg.shared.global [%0], [%1], 16;\n" :: "r"(dst), "l"(src));
}

// swizzled byte offset within one Rx32(16-bit) tile: row r, 16B chunk c (0..3)
__device__ __forceinline__ uint32_t swz(int r, int c) {
    return (uint32_t)(r * 64 + ((c ^ ((r >> 1) & 3)) << 4));
}

// ---------------------------------------------------------------------------
// Fused weight cast: all 5 arrays fp32 -> fp16 single
// ---------------------------------------------------------------------------
__global__ void wsplit_all(const float* s0, bf16* d0, int n0,
                           const float* s1, bf16* d1, int n1,
                           const float* s2, bf16* d2, int n2,
                           const float* s3, bf16* d3, int n3,
                           const float* s4, bf16* d4, int n4) {
    const float* src; __half* dst; int n;
    switch (blockIdx.y) {
        case 0: src = s0; dst = (__half*)d0; n = n0; break;
        case 1: src = s1; dst = (__half*)d1; n = n1; break;
        case 2: src = s2; dst = (__half*)d2; n = n2; break;
        case 3: src = s3; dst = (__half*)d3; n = n3; break;
        default: src = s4; dst = (__half*)d4; n = n4; break;
    }
    int i = (blockIdx.x * blockDim.x + threadIdx.x) * 4;
    if (i >= n) return;
    float4 v = *(const float4*)(src + i);
    __half2 p0, p1;
    p0.x = __float2half_rn(v.x); p0.y = __float2half_rn(v.y);
    p1.x = __float2half_rn(v.z); p1.y = __float2half_rn(v.w);
    ((__half2*)(dst + i))[0] = p0;
    ((__half2*)(dst + i))[1] = p1;
}

// ---------------------------------------------------------------------------
// Embedding
// ---------------------------------------------------------------------------
__global__ void embed_kernel(const int* __restrict__ idx,
                             const float* __restrict__ wte,
                             const float* __restrict__ wpe,
                             float* __restrict__ x) {
    int token = blockIdx.x;
    int t = token % TT;
    int id = idx[token];
    const float4* src = (const float4*)(wte + (size_t)id * DD);
    const float4* pos = (const float4*)(wpe + (size_t)t * DD);
    float4* dst = (float4*)(x + (size_t)token * DD);
    for (int i = threadIdx.x; i < DD / 4; i += blockDim.x) {
        float4 a = src[i], b = pos[i];
        dst[i] = make_float4(a.x + b.x, a.y + b.y, a.z + b.z, a.w + b.w);
    }
}

// ---------------------------------------------------------------------------
// LayerNorm over D=1024 -> fp16 hi/lo
// ---------------------------------------------------------------------------
__global__ __launch_bounds__(256) void ln_split_kernel(const float* __restrict__ x,
                                                       const float* __restrict__ sc,
                                                       const float* __restrict__ bi,
                                                       bf16* __restrict__ ohi,
                                                       bf16* __restrict__ olo) {
    int token = blockIdx.x;
    const float4* xp = (const float4*)(x + (size_t)token * DD);
    float4 v = xp[threadIdx.x];
    float s = v.x + v.y + v.z + v.w;
    float q = v.x * v.x + v.y * v.y + v.z * v.z + v.w * v.w;
#pragma unroll
    for (int o = 16; o; o >>= 1) {
        s += __shfl_xor_sync(0xffffffffu, s, o);
        q += __shfl_xor_sync(0xffffffffu, q, o);
    }
    __shared__ float ss[8], sq[8];
    int w = threadIdx.x >> 5, l = threadIdx.x & 31;
    if (l == 0) { ss[w] = s; sq[w] = q; }
    __syncthreads();
    if (w == 0) {
        s = (l < 8) ? ss[l] : 0.f;
        q = (l < 8) ? sq[l] : 0.f;
#pragma unroll
        for (int o = 4; o; o >>= 1) {
            s += __shfl_xor_sync(0xffffffffu, s, o);
            q += __shfl_xor_sync(0xffffffffu, q, o);
        }
        if (l == 0) { ss[0] = s; sq[0] = q; }
    }
    __syncthreads();
    float mu  = ss[0] * (1.f / DD);
    float var = sq[0] * (1.f / DD) - mu * mu;
    float inv = rsqrtf(var + 1e-5f);
    float4 sv = ((const float4*)sc)[threadIdx.x];
    float4 bv = ((const float4*)bi)[threadIdx.x];
    float r0 = (v.x - mu) * inv * sv.x + bv.x;
    float r1 = (v.y - mu) * inv * sv.y + bv.y;
    float r2 = (v.z - mu) * inv * sv.z + bv.z;
    float r3 = (v.w - mu) * inv * sv.w + bv.w;
    size_t o = (size_t)token * DD + threadIdx.x * 4;
    uint32_t hh, ll;
    split2h(r0, r1, hh, ll);
    ((uint32_t*)(ohi + o))[0] = hh; ((uint32_t*)(olo + o))[0] = ll;
    split2h(r2, r3, hh, ll);
    ((uint32_t*)(ohi + o))[1] = hh; ((uint32_t*)(olo + o))[1] = ll;
}

// ---------------------------------------------------------------------------
#define FLAG_BIAS  1
#define FLAG_RES   2
#define FLAG_GELU  4
#define FLAG_SPLIT 8   // write C as fp16 hi/lo
#define FLAG_QKV   16  // qkv epilogue: q fp32, k/v single fp16 (stride DD each)

__device__ __forceinline__ float gelu_exact(float v) {
    return 0.5f * v * (1.f + erff(v * 0.70710678118654752f));
}

// ---------------------------------------------------------------------------
// fp16 2-pass GEMM NT: D = Ah*Bh + Al*Bh  (A split fp16, B single fp16).
// CTA (MF*32)x128, warp (MF*16)x32, BK=32, 3-stage pipeline, swizzled smem.
// ---------------------------------------------------------------------------
template<int MF>
__global__ __launch_bounds__(256) void gemm2h(const __half* __restrict__ Ah,
                                              const __half* __restrict__ Al,
                                              const __half* __restrict__ Bh,
                                              const float* __restrict__ bias,
                                              const float* res,
                                              float* C, __half* Chi, __half* Clo,
                                              __half* Karr, __half* Varr,
                                              int M, int N, int K, int flags) {
    constexpr int BMT   = MF * 32;
    constexpr int TILEA = BMT * 64;
    constexpr int TILEBB = 8192;
    constexpr int BUFB  = 2 * TILEA + TILEBB;
    constexpr int NCHUNK = (2 * BMT * 4 + 512) / 256;

    extern __shared__ __align__(16) bf16 sm[];
    int tid = threadIdx.x;
    int warp = tid >> 5, lane = tid & 31;
    int bm = blockIdx.y * BMT, bn = blockIdx.x * BN;
    int wm = (warp >> 2) * (MF * 16);
    int wn = (warp & 3) * 32;

    uint32_t smbase = (uint32_t)__cvta_generic_to_shared(sm);

    float acc[MF][4][4];
#pragma unroll
    for (int i = 0; i < MF; i++)
#pragma unroll
        for (int j = 0; j < 4; j++)
#pragma unroll
            for (int r = 0; r < 4; r++) acc[i][j][r] = 0.f;

    int a_r = ((lane >> 3) & 1) * 8 + (lane & 7);
    int a_c = (lane >> 4) * 8;
    int b_r = (lane >> 4) * 8 + (lane & 7);
    int b_c = ((lane >> 3) & 1) * 8;

    const __half* srcA[2] = { Ah, Al };

    auto stage = [&](int s_idx, int buf) {
        int k0 = s_idx * BK;
        uint32_t bufoff = smbase + (uint32_t)(buf * BUFB);
#pragma unroll
        for (int i = 0; i < NCHUNK; i++) {
            int cid = tid + i * 256;
            if (cid < 2 * BMT * 4) {
                int arr = cid / (BMT * 4);
                int sub = cid - arr * (BMT * 4);
                int row = sub >> 2;
                int c = sub & 3;
                const __half* src = srcA[arr] + (size_t)(bm + row) * K + k0 + c * 8;
                cp16(bufoff + (uint32_t)(arr * TILEA) + swz(row, c), src);
            } else {
                int sub = cid - 2 * BMT * 4;
                int row = sub >> 2;
                int c = sub & 3;
                const __half* src = Bh + (size_t)(bn + row) * K + k0 + c * 8;
                cp16(bufoff + (uint32_t)(2 * TILEA) + swz(row, c), src);
            }
        }
        asm volatile("cp.async.commit_group;\n");
    };

    int S = K / BK;
    stage(0, 0);
    stage(1, 1);

    for (int s = 0; s < S; s++) {
        int buf = s - (s / NSTAGE) * NSTAGE;
        if (s == S - 1) asm volatile("cp.async.wait_group 0;\n");
        else            asm volatile("cp.async.wait_group 1;\n");
        __syncthreads();
        if (s + 2 < S) stage(s + 2, (s + 2) % NSTAGE);

        uint32_t offAh = smbase + (uint32_t)(buf * BUFB);
        uint32_t offAl = offAh + TILEA;
        uint32_t offB  = offAl + TILEA;

#pragma unroll
        for (int ks = 0; ks < BK; ks += 16) {
            uint32_t ah[MF][4], al[MF][4], bh[4][2];
#pragma unroll
            for (int mf = 0; mf < MF; mf++) {
                int row = wm + mf * 16 + a_r;
                ldm_x4(ah[mf][0], ah[mf][1], ah[mf][2], ah[mf][3],
                       offAh + swz(row, (ks + a_c) >> 3));
            }
#pragma unroll
            for (int p = 0; p < 2; p++) {
                int row = wn + p * 16 + b_r;
                uint32_t r0, r1, r2, r3;
                ldm_x4(r0, r1, r2, r3, offB + swz(row, (ks + b_c) >> 3));
                bh[2 * p][0] = r0; bh[2 * p][1] = r1;
                bh[2 * p + 1][0] = r2; bh[2 * p + 1][1] = r3;
            }
#pragma unroll
            for (int mf = 0; mf < MF; mf++)
#pragma unroll
                for (int nf = 0; nf < 4; nf++)
                    mma16816h(acc[mf][nf], ah[mf], bh[nf]);

#pragma unroll
            for (int mf = 0; mf < MF; mf++) {
                int row = wm + mf * 16 + a_r;
                ldm_x4(al[mf][0], al[mf][1], al[mf][2], al[mf][3],
                       offAl + swz(row, (ks + a_c) >> 3));
            }
#pragma unroll
            for (int mf = 0; mf < MF; mf++)
#pragma unroll
                for (int nf = 0; nf < 4; nf++)
                    mma16816h(acc[mf][nf], al[mf], bh[nf]);
        }
    }

    int gid = lane >> 2, tg = lane & 3;
#pragma unroll
    for (int mf = 0; mf < MF; mf++) {
#pragma unroll
        for (int half = 0; half < 2; half++) {
            int row = bm + wm + mf * 16 + half * 8 + gid;
#pragma unroll
            for (int nf = 0; nf < 4; nf++) {
                int col = bn + wn + nf * 8 + tg * 2;
                float2 o;
                o.x = acc[mf][nf][half * 2 + 0];
                o.y = acc[mf][nf][half * 2 + 1];
                if (flags & FLAG_QKV) {
                    // q fp32 [0,DD); k fp16 [DD,2DD); v fp16 [2DD,3DD)
                    if (col < DD) {
                        *(float2*)(C + (size_t)row * DD + col) = o;
                    } else if (col < 2 * DD) {
                        *(uint32_t*)(Karr + (size_t)row * DD + (col - DD)) = pack2h(o.x, o.y);
                    } else {
                        *(uint32_t*)(Varr + (size_t)row * DD + (col - 2 * DD)) = pack2h(o.x, o.y);
                    }
                    continue;
                }
                if (flags & FLAG_BIAS) { o.x += bias[col]; o.y += bias[col + 1]; }
                if (flags & FLAG_GELU) { o.x = gelu_exact(o.x); o.y = gelu_exact(o.y); }
                if (flags & FLAG_RES) {
                    float2 r = *(const float2*)(res + (size_t)row * N + col);
                    o.x += r.x; o.y += r.y;
                }
                if (flags & FLAG_SPLIT) {
                    size_t off = (size_t)row * N + col;
                    uint32_t hh, ll;
                    split2h(o.x, o.y, hh, ll);
                    *(uint32_t*)(Chi + off) = hh;
                    *(uint32_t*)(Clo + off) = ll;
                } else {
                    *(float2*)(C + (size_t)row * N + col) = o;
                }
            }
        }
    }
}

// Dynamic smem sizes
#define GSM2_MF2 (NSTAGE * (2 * 64 * 64 + 8192))        // 49152
#define GSM2_MF4 (NSTAGE * (2 * 128 * 64 + 8192))       // 73728

// ---------------------------------------------------------------------------
// Causal attention via fp16 mma (2-pass split on Q and P; K,V single fp16).
// Double-buffered cp.async K/V staging overlapped with compute.
// ---------------------------------------------------------------------------
__global__ __launch_bounds__(256) void attn_mma(const float* __restrict__ qarr,
                                                const __half* __restrict__ karr,
                                                const __half* __restrict__ varr,
                                                bf16* __restrict__ yhi,
                                                bf16* __restrict__ ylo) {
    int b = blockIdx.z, h = blockIdx.y;
    int bx = gridDim.x - 1 - blockIdx.x;
    int tid = threadIdx.x;
    int warp = tid >> 5, lane = tid & 31;
    int g = lane >> 2, t4 = lane & 3;
    int q0w = bx * AQ + warp * 16;

    __shared__ __align__(16) __half K_s[2][AKT * LDV];
    __shared__ __align__(16) __half V_s[2][AKT * LDV];
    uint32_t aK[2] = { (uint32_t)__cvta_generic_to_shared(K_s[0]),
                       (uint32_t)__cvta_generic_to_shared(K_s[1]) };
    uint32_t aV[2] = { (uint32_t)__cvta_generic_to_shared(V_s[0]),
                       (uint32_t)__cvta_generic_to_shared(V_s[1]) };

    // Q a-frags (scaled by 1/8), fp16 hi/lo
    uint32_t qh[4][4], ql[4][4];
    {
        const float* qbase = qarr + (size_t)(b * TT) * DD + h * HDIM;
        const float* r0p = qbase + (size_t)(q0w + g) * DD;
        const float* r1p = qbase + (size_t)(q0w + g + 8) * DD;
#pragma unroll
        for (int c = 0; c < 4; c++) {
            float2 v00 = *(const float2*)(r0p + c * 16 + 2 * t4);
            float2 v10 = *(const float2*)(r1p + c * 16 + 2 * t4);
            float2 v01 = *(const float2*)(r0p + c * 16 + 2 * t4 + 8);
            float2 v11 = *(const float2*)(r1p + c * 16 + 2 * t4 + 8);
            split2h(v00.x * 0.125f, v00.y * 0.125f, qh[c][0], ql[c][0]);
            split2h(v10.x * 0.125f, v10.y * 0.125f, qh[c][1], ql[c][1]);
            split2h(v01.x * 0.125f, v01.y * 0.125f, qh[c][2], ql[c][2]);
            split2h(v11.x * 0.125f, v11.y * 0.125f, qh[c][3], ql[c][3]);
        }
    }

    float O[8][4];
#pragma unroll
    for (int j = 0; j < 8; j++)
#pragma unroll
        for (int r = 0; r < 4; r++) O[j][r] = 0.f;
    float m0 = NEGINF, m1 = NEGINF, l0 = 0.f, l1 = 0.f;

    int b_r = (lane >> 4) * 8 + (lane & 7);
    int b_c = ((lane >> 3) & 1) * 8;
    int v_r = (lane & 7) + ((lane >> 3) & 1) * 8;
    int v_c = (lane >> 4) * 8;

    const __half* kb = karr + (size_t)(b * TT) * DD + h * HDIM;
    const __half* vb = varr + (size_t)(b * TT) * DD + h * HDIM;

    // stage tile t (keys [t*AKT, t*AKT+64)) into buffer buf
    auto stage = [&](int t, int buf) {
        int kt = t * AKT;
#pragma unroll
        for (int i = 0; i < 4; i++) {
            int cid = tid + i * 256;       // 0..1023
            int arr = cid >> 9;            // 0=K 1=V
            int sub = cid & 511;
            int kk = sub >> 3;
            int c8 = sub & 7;
            const __half* src = (arr ? vb : kb) + (size_t)(kt + kk) * DD + c8 * 8;
            uint32_t dst = (arr ? aV[buf] : aK[buf]) + (uint32_t)(kk * LDV + c8 * 8) * 2;
            cp16(dst, src);
        }
        asm volatile("cp.async.commit_group;\n" ::: "memory");
    };

    int ntiles = bx * 2 + 2;
    stage(0, 0);

    for (int tile = 0; tile < ntiles; tile++) {
        int buf = tile & 1;
        int kt = tile * AKT;
        if (tile + 1 < ntiles) {
            stage(tile + 1, buf ^ 1);
            asm volatile("cp.async.wait_group 1;\n" ::: "memory");
        } else {
            asm volatile("cp.async.wait_group 0;\n" ::: "memory");
        }
        __syncthreads();

        if (kt <= q0w + 15) {
            // ----- S = Q K^T (2-pass: Qh*K + Ql*K) -----
            float S[8][4];
#pragma unroll
            for (int j = 0; j < 8; j++)
#pragma unroll
                for (int r = 0; r < 4; r++) S[j][r] = 0.f;

#pragma unroll
            for (int c = 0; c < 4; c++) {
                uint32_t kf[8][2];
#pragma unroll
                for (int p = 0; p < 4; p++) {
                    uint32_t r0, r1, r2, r3;
                    ldm_x4(r0, r1, r2, r3,
                           aK[buf] + (uint32_t)((16 * p + b_r) * LDV + 16 * c + b_c) * 2);
                    kf[2 * p][0] = r0; kf[2 * p][1] = r1;
                    kf[2 * p + 1][0] = r2; kf[2 * p + 1][1] = r3;
                }
#pragma unroll
                for (int j = 0; j < 8; j++) mma16816h(S[j], qh[c], kf[j]);
#pragma unroll
                for (int j = 0; j < 8; j++) mma16816h(S[j], ql[c], kf[j]);
            }

            if (kt + AKT - 1 > q0w) {
                int row0 = q0w + g, row1 = q0w + g + 8;
#pragma unroll
                for (int j = 0; j < 8; j++) {
                    int col = kt + 8 * j + 2 * t4;
                    if (col > row0)     S[j][0] = NEGINF;
                    if (col + 1 > row0) S[j][1] = NEGINF;
                    if (col > row1)     S[j][2] = NEGINF;
                    if (col + 1 > row1) S[j][3] = NEGINF;
                }
            }

            float mx0 = NEGINF, mx1 = NEGINF;
#pragma unroll
            for (int j = 0; j < 8; j++) {
                mx0 = fmaxf(mx0, fmaxf(S[j][0], S[j][1]));
                mx1 = fmaxf(mx1, fmaxf(S[j][2], S[j][3]));
            }
            mx0 = fmaxf(mx0, __shfl_xor_sync(0xffffffffu, mx0, 1));
            mx0 = fmaxf(mx0, __shfl_xor_sync(0xffffffffu, mx0, 2));
            mx1 = fmaxf(mx1, __shfl_xor_sync(0xffffffffu, mx1, 1));
            mx1 = fmaxf(mx1, __shfl_xor_sync(0xffffffffu, mx1, 2));
            float m0n = fmaxf(m0, mx0), m1n = fmaxf(m1, mx1);
            float c0 = __expf(m0 - m0n), c1 = __expf(m1 - m1n);
            float s0 = 0.f, s1 = 0.f;
#pragma unroll
            for (int j = 0; j < 8; j++) {
                S[j][0] = __expf(S[j][0] - m0n);
                S[j][1] = __expf(S[j][1] - m0n);
                S[j][2] = __expf(S[j][2] - m1n);
                S[j][3] = __expf(S[j][3] - m1n);
                s0 += S[j][0] + S[j][1];
                s1 += S[j][2] + S[j][3];
            }
            s0 += __shfl_xor_sync(0xffffffffu, s0, 1);
            s0 += __shfl_xor_sync(0xffffffffu, s0, 2);
            s1 += __shfl_xor_sync(0xffffffffu, s1, 1);
            s1 += __shfl_xor_sync(0xffffffffu, s1, 2);
            l0 = l0 * c0 + s0;
            l1 = l1 * c1 + s1;
            m0 = m0n; m1 = m1n;
#pragma unroll
            for (int j = 0; j < 8; j++) {
                O[j][0] *= c0; O[j][1] *= c0;
                O[j][2] *= c1; O[j][3] *= c1;
            }

            // ----- O += P V (2-pass: Ph*V + Pl*V) -----
#pragma unroll
            for (int kk = 0; kk < 4; kk++) {
                uint32_t ph[4], pl[4];
                split2h(S[2 * kk][0],     S[2 * kk][1],     ph[0], pl[0]);
                split2h(S[2 * kk][2],     S[2 * kk][3],     ph[1], pl[1]);
                split2h(S[2 * kk + 1][0], S[2 * kk + 1][1], ph[2], pl[2]);
                split2h(S[2 * kk + 1][2], S[2 * kk + 1][3], ph[3], pl[3]);

                uint32_t vf[8][2];
#pragma unroll
                for (int ds = 0; ds < 4; ds++) {
                    uint32_t r0, r1, r2, r3;
                    ldm_x4_t(r0, r1, r2, r3,
                             aV[buf] + (uint32_t)((16 * kk + v_r) * LDV + 16 * ds + v_c) * 2);
                    vf[2 * ds][0] = r0; vf[2 * ds][1] = r1;
                    vf[2 * ds + 1][0] = r2; vf[2 * ds + 1][1] = r3;
                }
#pragma unroll
                for (int j = 0; j < 8; j++) mma16816h(O[j], ph, vf[j]);
#pragma unroll
                for (int j = 0; j < 8; j++) mma16816h(O[j], pl, vf[j]);
            }
        }
        __syncthreads();   // all reads of buf done before tile+2 stages into it
    }

    // epilogue: y as fp16 hi/lo (consumed by fp16 proj GEMM)
    float i0 = 1.f / l0, i1 = 1.f / l1;
    size_t off0 = (size_t)(b * TT + q0w + g) * DD + h * HDIM + 2 * t4;
    size_t off1 = (size_t)(b * TT + q0w + g + 8) * DD + h * HDIM + 2 * t4;
#pragma unroll
    for (int j = 0; j < 8; j++) {
        uint32_t hh, ll;
        split2h(O[j][0] * i0, O[j][1] * i0, hh, ll);
        *(uint32_t*)(yhi + off0 + 8 * j) = hh;
        *(uint32_t*)(ylo + off0 + 8 * j) = ll;
        split2h(O[j][2] * i1, O[j][3] * i1, hh, ll);
        *(uint32_t*)(yhi + off1 + 8 * j) = hh;
        *(uint32_t*)(ylo + off1 + 8 * j) = ll;
    }
}

// ---------------------------------------------------------------------------
// Host launcher
// ---------------------------------------------------------------------------
extern "C" void kernel_launch(void* const* d_in, const int* in_sizes, int n_in,
                              void* d_out, int out_size) {
    const int*   idx    = (const int*)  d_in[0];
    const float* wte    = (const float*)d_in[1];
    const float* wpe    = (const float*)d_in[2];
    const float* ln1_s  = (const float*)d_in[3];
    const float* ln1_b  = (const float*)d_in[4];
    const float* qkv_w  = (const float*)d_in[5];
    const float* proj_w = (const float*)d_in[6];
    const float* ln2_s  = (const float*)d_in[7];
    const float* ln2_b  = (const float*)d_in[8];
    const float* fc_w   = (const float*)d_in[9];
    const float* fc_b   = (const float*)d_in[10];
    const float* fc2_w  = (const float*)d_in[11];
    const float* fc2_b  = (const float*)d_in[12];
    const float* lnf_s  = (const float*)d_in[13];
    const float* lnf_b  = (const float*)d_in[14];
    const float* lm_w   = (const float*)d_in[15];
    float* out = (float*)d_out;

    float *x, *qarr;
    bf16 *karr, *varr;
    bf16 *h_hi, *h_lo, *y_hi, *y_lo, *gg_hi, *gg_lo;
    bf16 *qw, *pw, *fw, *f2w, *lw;
    cudaGetSymbolAddress((void**)&x,     g_x);
    cudaGetSymbolAddress((void**)&qarr,  g_q);
    cudaGetSymbolAddress((void**)&karr,  g_k);
    cudaGetSymbolAddress((void**)&varr,  g_v);
    cudaGetSymbolAddress((void**)&h_hi,  g_h_hi);   cudaGetSymbolAddress((void**)&h_lo,  g_h_lo);
    cudaGetSymbolAddress((void**)&y_hi,  g_y_hi);   cudaGetSymbolAddress((void**)&y_lo,  g_y_lo);
    cudaGetSymbolAddress((void**)&gg_hi, g_g_hi);   cudaGetSymbolAddress((void**)&gg_lo, g_g_lo);
    cudaGetSymbolAddress((void**)&qw,  g_qkvw);
    cudaGetSymbolAddress((void**)&pw,  g_projw);
    cudaGetSymbolAddress((void**)&fw,  g_fcw);
    cudaGetSymbolAddress((void**)&f2w, g_fc2w);
    cudaGetSymbolAddress((void**)&lw,  g_lmw);

    cudaFuncSetAttribute(gemm2h<2>, cudaFuncAttributeMaxDynamicSharedMemorySize, GSM2_MF2);
    cudaFuncSetAttribute(gemm2h<4>, cudaFuncAttributeMaxDynamicSharedMemorySize, GSM2_MF4);

    embed_kernel<<<MM, 256>>>(idx, wte, wpe, x);

    {
        int nq = LL * 3 * DD * DD, np = LL * DD * DD;
        int nf = LL * 4 * DD * DD, n2 = LL * 4 * DD * DD, nl = VV * DD;
        int maxn = nf;
        dim3 grid((maxn / 4 + 255) / 256, 5);
        wsplit_all<<<grid, 256>>>(qkv_w,  qw,  nq,
                                  proj_w, pw,  np,
                                  fc_w,   fw,  nf,
                                  fc2_w,  f2w, n2,
                                  lm_w,   lw,  nl);
    }

    for (int l = 0; l < LL; l++) {
        const __half* qwh = (const __half*)(qw  + (size_t)l * 3 * DD * DD);
        const __half* pwh = (const __half*)(pw  + (size_t)l * DD * DD);
        const __half* fwh = (const __half*)(fw  + (size_t)l * 4 * DD * DD);
        const __half* f2h = (const __half*)(f2w + (size_t)l * 4 * DD * DD);
        const float* fb  = fc_b  + (size_t)l * 4 * DD;
        const float* f2b = fc2_b + (size_t)l * DD;

        ln_split_kernel<<<MM, 256>>>(x, ln1_s + l * DD, ln1_b + l * DD, h_hi, h_lo);
        // qkv: fp16 2-pass, MF=2, grid 24x32 = 768. Epilogue: q fp32, K/V fp16.
        gemm2h<2><<<dim3(3 * DD / BN, MM / 64), 256, GSM2_MF2>>>(
            (const __half*)h_hi, (const __half*)h_lo, qwh,
            nullptr, nullptr, qarr, nullptr, nullptr,
            (__half*)karr, (__half*)varr, MM, 3 * DD, DD, FLAG_QKV);
        attn_mma<<<dim3(TT / AQ, HH, BB), 256>>>(qarr, (const __half*)karr,
                                                 (const __half*)varr, y_hi, y_lo);
        // proj: fp16 2-pass, MF=2, grid 8x32 = 256
        gemm2h<2><<<dim3(DD / BN, MM / 64), 256, GSM2_MF2>>>(
            (const __half*)y_hi, (const __half*)y_lo, pwh,
            nullptr, x, x, nullptr, nullptr,
            nullptr, nullptr, MM, DD, DD, FLAG_RES);
        ln_split_kernel<<<MM, 256>>>(x, ln2_s + l * DD, ln2_b + l * DD, h_hi, h_lo);
        // fc: fp16 2-pass, MF=4, grid 32x16 = 512; gelu + fp16 split out
        gemm2h<4><<<dim3(4 * DD / BN, MM / 128), 256, GSM2_MF4>>>(
            (const __half*)h_hi, (const __half*)h_lo, fwh,
            fb, nullptr, nullptr, (__half*)gg_hi, (__half*)gg_lo,
            nullptr, nullptr, MM, 4 * DD, DD, FLAG_BIAS | FLAG_GELU | FLAG_SPLIT);
        // fc2: fp16 2-pass, MF=2, grid 8x32 = 256
        gemm2h<2><<<dim3(DD / BN, MM / 64), 256, GSM2_MF2>>>(
            (const __half*)gg_hi, (const __half*)gg_lo, f2h,
            f2b, x, x, nullptr, nullptr,
            nullptr, nullptr, MM, DD, 4 * DD, FLAG_BIAS | FLAG_RES);
    }

    // lnf -> fp16 hi/lo
    ln_split_kernel<<<MM, 256>>>(x, lnf_s, lnf_b, h_hi, h_lo);
    // lm: fp16 2-pass, MF=4, grid 250x16 = 4000
    gemm2h<4><<<dim3(VV / BN, MM / 128), 256, GSM2_MF4>>>(
        (const __half*)h_hi, (const __half*)h_lo, (const __half*)lw,
        nullptr, nullptr, out, nullptr, nullptr,
        nullptr, nullptr, MM, VV, DD, 0);
}

// round 17
// speedup vs baseline: 1.8878x; 1.0744x over previous
#include <cuda_runtime.h>
#include <cuda_bf16.h>
#include <cuda_fp16.h>
#include <math.h>
#include <stdint.h>

// Model dims
#define BB   2
#define TT   1024
#define DD   1024
#define HH   16
#define HDIM 64
#define LL   8
#define VV   32000
#define MM   (BB*TT)   // 2048 tokens

typedef __nv_bfloat16 bf16;
typedef __nv_bfloat162 bf162;

// GEMM tiling
#define BN 128
#define BK 32
#define NSTAGE 3

// Attention tiling
#define AQ  128
#define AKT 64
#define LDV 72
#define NEGINF (-1e30f)

// fp32 scratch
__device__ float g_x[MM * DD];
__device__ float g_q[MM * DD];                                // q (fp32)
// K/V single fp16 (written by qkv GEMM epilogue)
__device__ bf16 g_k[MM * DD], g_v[MM * DD];                   // fp16 payload
// fp16 activation scratch (hi/lo pairs)
__device__ bf16 g_h_hi[MM * DD],     g_h_lo[MM * DD];
__device__ bf16 g_y_hi[MM * DD],     g_y_lo[MM * DD];
__device__ bf16 g_g_hi[MM * 4 * DD], g_g_lo[MM * 4 * DD];
// weights: all single fp16
__device__ bf16 g_qkvw[LL * 3 * DD * DD];
__device__ bf16 g_projw[LL * DD * DD];
__device__ bf16 g_fcw [LL * 4 * DD * DD];
__device__ bf16 g_fc2w[LL * 4 * DD * DD];
__device__ bf16 g_lmw [VV * DD];

// ---------------------------------------------------------------------------
// Small helpers
// ---------------------------------------------------------------------------
__device__ __forceinline__ void split2h(float x, float y, uint32_t& hi, uint32_t& lo) {
    __half2 hp, lp;
    hp.x = __float2half_rn(x); hp.y = __float2half_rn(y);
    lp.x = __float2half_rn(x - __half2float(hp.x));
    lp.y = __float2half_rn(y - __half2float(hp.y));
    hi = *(uint32_t*)&hp; lo = *(uint32_t*)&lp;
}

__device__ __forceinline__ uint32_t pack2h(float x, float y) {
    __half2 p;
    p.x = __float2half_rn(x); p.y = __float2half_rn(y);
    return *(uint32_t*)&p;
}

__device__ __forceinline__ void ldm_x4(uint32_t& r0, uint32_t& r1, uint32_t& r2, uint32_t& r3,
                                       uint32_t addr) {
    asm volatile("ldmatrix.sync.aligned.m8n8.x4.shared.b16 {%0,%1,%2,%3}, [%4];\n"
                 : "=r"(r0), "=r"(r1), "=r"(r2), "=r"(r3) : "r"(addr));
}

__device__ __forceinline__ void ldm_x4_t(uint32_t& r0, uint32_t& r1, uint32_t& r2, uint32_t& r3,
                                         uint32_t addr) {
    asm volatile("ldmatrix.sync.aligned.m8n8.x4.trans.shared.b16 {%0,%1,%2,%3}, [%4];\n"
                 : "=r"(r0), "=r"(r1), "=r"(r2), "=r"(r3) : "r"(addr));
}

__device__ __forceinline__ void mma16816h(float* d, const uint32_t* a, const uint32_t* b) {
    asm volatile(
        "mma.sync.aligned.m16n8k16.row.col.f32.f16.f16.f32 "
        "{%0,%1,%2,%3}, {%4,%5,%6,%7}, {%8,%9}, {%0,%1,%2,%3};\n"
        : "+f"(d[0]), "+f"(d[1]), "+f"(d[2]), "+f"(d[3])
        : "r"(a[0]), "r"(a[1]), "r"(a[2]), "r"(a[3]), "r"(b[0]), "r"(b[1]));
}

__device__ __forceinline__ void cp16(uint32_t dst, const void* src) {
    asm volatile("cp.async.cg.shared.global [%0], [%1], 16;\n" :: "r"(dst), "l"(src));
}

// swizzled byte offset within one Rx32(16-bit) tile: row r, 16B chunk c (0..3)
__device__ __forceinline__ uint32_t swz(int r, int c) {
    return (uint32_t)(r * 64 + ((c ^ ((r >> 1) & 3)) << 4));
}

// ---------------------------------------------------------------------------
// Fused weight cast: all 5 arrays fp32 -> fp16 single
// ---------------------------------------------------------------------------
__global__ void wsplit_all(const float* s0, bf16* d0, int n0,
                           const float* s1, bf16* d1, int n1,
                           const float* s2, bf16* d2, int n2,
                           const float* s3, bf16* d3, int n3,
                           const float* s4, bf16* d4, int n4) {
    const float* src; __half* dst; int n;
    switch (blockIdx.y) {
        case 0: src = s0; dst = (__half*)d0; n = n0; break;
        case 1: src = s1; dst = (__half*)d1; n = n1; break;
        case 2: src = s2; dst = (__half*)d2; n = n2; break;
        case 3: src = s3; dst = (__half*)d3; n = n3; break;
        default: src = s4; dst = (__half*)d4; n = n4; break;
    }
    int i = (blockIdx.x * blockDim.x + threadIdx.x) * 4;
    if (i >= n) return;
    float4 v = *(const float4*)(src + i);
    __half2 p0, p1;
    p0.x = __float2half_rn(v.x); p0.y = __float2half_rn(v.y);
    p1.x = __float2half_rn(v.z); p1.y = __float2half_rn(v.w);
    ((__half2*)(dst + i))[0] = p0;
    ((__half2*)(dst + i))[1] = p1;
}

// ---------------------------------------------------------------------------
// Embedding
// ---------------------------------------------------------------------------
__global__ void embed_kernel(const int* __restrict__ idx,
                             const float* __restrict__ wte,
                             const float* __restrict__ wpe,
                             float* __restrict__ x) {
    int token = blockIdx.x;
    int t = token % TT;
    int id = idx[token];
    const float4* src = (const float4*)(wte + (size_t)id * DD);
    const float4* pos = (const float4*)(wpe + (size_t)t * DD);
    float4* dst = (float4*)(x + (size_t)token * DD);
    for (int i = threadIdx.x; i < DD / 4; i += blockDim.x) {
        float4 a = src[i], b = pos[i];
        dst[i] = make_float4(a.x + b.x, a.y + b.y, a.z + b.z, a.w + b.w);
    }
}

// ---------------------------------------------------------------------------
// LayerNorm over D=1024 -> fp16 hi/lo
// ---------------------------------------------------------------------------
__global__ __launch_bounds__(256) void ln_split_kernel(const float* __restrict__ x,
                                                       const float* __restrict__ sc,
                                                       const float* __restrict__ bi,
                                                       bf16* __restrict__ ohi,
                                                       bf16* __restrict__ olo) {
    int token = blockIdx.x;
    const float4* xp = (const float4*)(x + (size_t)token * DD);
    float4 v = xp[threadIdx.x];
    float s = v.x + v.y + v.z + v.w;
    float q = v.x * v.x + v.y * v.y + v.z * v.z + v.w * v.w;
#pragma unroll
    for (int o = 16; o; o >>= 1) {
        s += __shfl_xor_sync(0xffffffffu, s, o);
        q += __shfl_xor_sync(0xffffffffu, q, o);
    }
    __shared__ float ss[8], sq[8];
    int w = threadIdx.x >> 5, l = threadIdx.x & 31;
    if (l == 0) { ss[w] = s; sq[w] = q; }
    __syncthreads();
    if (w == 0) {
        s = (l < 8) ? ss[l] : 0.f;
        q = (l < 8) ? sq[l] : 0.f;
#pragma unroll
        for (int o = 4; o; o >>= 1) {
            s += __shfl_xor_sync(0xffffffffu, s, o);
            q += __shfl_xor_sync(0xffffffffu, q, o);
        }
        if (l == 0) { ss[0] = s; sq[0] = q; }
    }
    __syncthreads();
    float mu  = ss[0] * (1.f / DD);
    float var = sq[0] * (1.f / DD) - mu * mu;
    float inv = rsqrtf(var + 1e-5f);
    float4 sv = ((const float4*)sc)[threadIdx.x];
    float4 bv = ((const float4*)bi)[threadIdx.x];
    float r0 = (v.x - mu) * inv * sv.x + bv.x;
    float r1 = (v.y - mu) * inv * sv.y + bv.y;
    float r2 = (v.z - mu) * inv * sv.z + bv.z;
    float r3 = (v.w - mu) * inv * sv.w + bv.w;
    size_t o = (size_t)token * DD + threadIdx.x * 4;
    uint32_t hh, ll;
    split2h(r0, r1, hh, ll);
    ((uint32_t*)(ohi + o))[0] = hh; ((uint32_t*)(olo + o))[0] = ll;
    split2h(r2, r3, hh, ll);
    ((uint32_t*)(ohi + o))[1] = hh; ((uint32_t*)(olo + o))[1] = ll;
}

// ---------------------------------------------------------------------------
#define FLAG_BIAS  1
#define FLAG_RES   2
#define FLAG_GELU  4
#define FLAG_SPLIT 8   // write C as fp16 hi/lo
#define FLAG_QKV   16  // qkv epilogue: q fp32, k/v single fp16 (stride DD each)

__device__ __forceinline__ float gelu_exact(float v) {
    return 0.5f * v * (1.f + erff(v * 0.70710678118654752f));
}

// ---------------------------------------------------------------------------
// fp16 GEMM NT. TWOPASS: D = Ah*Bh + Al*Bh (A split).  !TWOPASS: D = Ah*Bh.
// CTA (MF*32)x128, warp (MF*16)x32, BK=32, 3-stage pipeline, swizzled smem.
// ---------------------------------------------------------------------------
template<int MF, bool TWOPASS>
__global__ __launch_bounds__(256) void gemm2h(const __half* __restrict__ Ah,
                                              const __half* __restrict__ Al,
                                              const __half* __restrict__ Bh,
                                              const float* __restrict__ bias,
                                              const float* res,
                                              float* C, __half* Chi, __half* Clo,
                                              __half* Karr, __half* Varr,
                                              int M, int N, int K, int flags) {
    constexpr int BMT   = MF * 32;
    constexpr int NA    = TWOPASS ? 2 : 1;
    constexpr int TILEA = BMT * 64;
    constexpr int TILEBB = 8192;
    constexpr int BUFB  = NA * TILEA + TILEBB;
    constexpr int NCHUNK = (NA * BMT * 4 + 512) / 256;

    extern __shared__ __align__(16) bf16 sm[];
    int tid = threadIdx.x;
    int warp = tid >> 5, lane = tid & 31;
    int bm = blockIdx.y * BMT, bn = blockIdx.x * BN;
    int wm = (warp >> 2) * (MF * 16);
    int wn = (warp & 3) * 32;

    uint32_t smbase = (uint32_t)__cvta_generic_to_shared(sm);

    float acc[MF][4][4];
#pragma unroll
    for (int i = 0; i < MF; i++)
#pragma unroll
        for (int j = 0; j < 4; j++)
#pragma unroll
            for (int r = 0; r < 4; r++) acc[i][j][r] = 0.f;

    int a_r = ((lane >> 3) & 1) * 8 + (lane & 7);
    int a_c = (lane >> 4) * 8;
    int b_r = (lane >> 4) * 8 + (lane & 7);
    int b_c = ((lane >> 3) & 1) * 8;

    const __half* srcA[2] = { Ah, TWOPASS ? Al : Ah };

    auto stage = [&](int s_idx, int buf) {
        int k0 = s_idx * BK;
        uint32_t bufoff = smbase + (uint32_t)(buf * BUFB);
#pragma unroll
        for (int i = 0; i < NCHUNK; i++) {
            int cid = tid + i * 256;
            if (cid < NA * BMT * 4) {
                int arr = cid / (BMT * 4);
                int sub = cid - arr * (BMT * 4);
                int row = sub >> 2;
                int c = sub & 3;
                const __half* src = srcA[arr] + (size_t)(bm + row) * K + k0 + c * 8;
                cp16(bufoff + (uint32_t)(arr * TILEA) + swz(row, c), src);
            } else {
                int sub = cid - NA * BMT * 4;
                int row = sub >> 2;
                int c = sub & 3;
                const __half* src = Bh + (size_t)(bn + row) * K + k0 + c * 8;
                cp16(bufoff + (uint32_t)(NA * TILEA) + swz(row, c), src);
            }
        }
        asm volatile("cp.async.commit_group;\n");
    };

    int S = K / BK;
    stage(0, 0);
    stage(1, 1);

    for (int s = 0; s < S; s++) {
        int buf = s - (s / NSTAGE) * NSTAGE;
        if (s == S - 1) asm volatile("cp.async.wait_group 0;\n");
        else            asm volatile("cp.async.wait_group 1;\n");
        __syncthreads();
        if (s + 2 < S) stage(s + 2, (s + 2) % NSTAGE);

        uint32_t offAh = smbase + (uint32_t)(buf * BUFB);
        uint32_t offAl = offAh + TILEA;
        uint32_t offB  = offAh + (uint32_t)(NA * TILEA);

#pragma unroll
        for (int ks = 0; ks < BK; ks += 16) {
            uint32_t ah[MF][4], bh[4][2];
#pragma unroll
            for (int mf = 0; mf < MF; mf++) {
                int row = wm + mf * 16 + a_r;
                ldm_x4(ah[mf][0], ah[mf][1], ah[mf][2], ah[mf][3],
                       offAh + swz(row, (ks + a_c) >> 3));
            }
#pragma unroll
            for (int p = 0; p < 2; p++) {
                int row = wn + p * 16 + b_r;
                uint32_t r0, r1, r2, r3;
                ldm_x4(r0, r1, r2, r3, offB + swz(row, (ks + b_c) >> 3));
                bh[2 * p][0] = r0; bh[2 * p][1] = r1;
                bh[2 * p + 1][0] = r2; bh[2 * p + 1][1] = r3;
            }
#pragma unroll
            for (int mf = 0; mf < MF; mf++)
#pragma unroll
                for (int nf = 0; nf < 4; nf++)
                    mma16816h(acc[mf][nf], ah[mf], bh[nf]);

            if (TWOPASS) {
                uint32_t al[MF][4];
#pragma unroll
                for (int mf = 0; mf < MF; mf++) {
                    int row = wm + mf * 16 + a_r;
                    ldm_x4(al[mf][0], al[mf][1], al[mf][2], al[mf][3],
                           offAl + swz(row, (ks + a_c) >> 3));
                }
#pragma unroll
                for (int mf = 0; mf < MF; mf++)
#pragma unroll
                    for (int nf = 0; nf < 4; nf++)
                        mma16816h(acc[mf][nf], al[mf], bh[nf]);
            }
        }
    }

    int gid = lane >> 2, tg = lane & 3;
#pragma unroll
    for (int mf = 0; mf < MF; mf++) {
#pragma unroll
        for (int half = 0; half < 2; half++) {
            int row = bm + wm + mf * 16 + half * 8 + gid;
#pragma unroll
            for (int nf = 0; nf < 4; nf++) {
                int col = bn + wn + nf * 8 + tg * 2;
                float2 o;
                o.x = acc[mf][nf][half * 2 + 0];
                o.y = acc[mf][nf][half * 2 + 1];
                if (flags & FLAG_QKV) {
                    // q fp32 [0,DD); k fp16 [DD,2DD); v fp16 [2DD,3DD)
                    if (col < DD) {
                        *(float2*)(C + (size_t)row * DD + col) = o;
                    } else if (col < 2 * DD) {
                        *(uint32_t*)(Karr + (size_t)row * DD + (col - DD)) = pack2h(o.x, o.y);
                    } else {
                        *(uint32_t*)(Varr + (size_t)row * DD + (col - 2 * DD)) = pack2h(o.x, o.y);
                    }
                    continue;
                }
                if (flags & FLAG_BIAS) { o.x += bias[col]; o.y += bias[col + 1]; }
                if (flags & FLAG_GELU) { o.x = gelu_exact(o.x); o.y = gelu_exact(o.y); }
                if (flags & FLAG_RES) {
                    float2 r = *(const float2*)(res + (size_t)row * N + col);
                    o.x += r.x; o.y += r.y;
                }
                if (flags & FLAG_SPLIT) {
                    size_t off = (size_t)row * N + col;
                    uint32_t hh, ll;
                    split2h(o.x, o.y, hh, ll);
                    *(uint32_t*)(Chi + off) = hh;
                    *(uint32_t*)(Clo + off) = ll;
                } else {
                    *(float2*)(C + (size_t)row * N + col) = o;
                }
            }
        }
    }
}

// Dynamic smem sizes
#define GSM2_MF2   (NSTAGE * (2 * 64 * 64 + 8192))      // 49152  (MF=2, 2-pass)
#define GSM2_MF4   (NSTAGE * (2 * 128 * 64 + 8192))     // 73728  (MF=4, 2-pass)
#define GSM1_MF4   (NSTAGE * (128 * 64 + 8192))         // 49152  (MF=4, 1-pass)

// ---------------------------------------------------------------------------
// Causal attention via fp16 mma (2-pass split on Q and P; K,V single fp16).
// Double-buffered cp.async K/V staging overlapped with compute.
// ---------------------------------------------------------------------------
__global__ __launch_bounds__(256) void attn_mma(const float* __restrict__ qarr,
                                                const __half* __restrict__ karr,
                                                const __half* __restrict__ varr,
                                                bf16* __restrict__ yhi,
                                                bf16* __restrict__ ylo) {
    int b = blockIdx.z, h = blockIdx.y;
    int bx = gridDim.x - 1 - blockIdx.x;
    int tid = threadIdx.x;
    int warp = tid >> 5, lane = tid & 31;
    int g = lane >> 2, t4 = lane & 3;
    int q0w = bx * AQ + warp * 16;

    __shared__ __align__(16) __half K_s[2][AKT * LDV];
    __shared__ __align__(16) __half V_s[2][AKT * LDV];
    uint32_t aK[2] = { (uint32_t)__cvta_generic_to_shared(K_s[0]),
                       (uint32_t)__cvta_generic_to_shared(K_s[1]) };
    uint32_t aV[2] = { (uint32_t)__cvta_generic_to_shared(V_s[0]),
                       (uint32_t)__cvta_generic_to_shared(V_s[1]) };

    // Q a-frags (scaled by 1/8), fp16 hi/lo
    uint32_t qh[4][4], ql[4][4];
    {
        const float* qbase = qarr + (size_t)(b * TT) * DD + h * HDIM;
        const float* r0p = qbase + (size_t)(q0w + g) * DD;
        const float* r1p = qbase + (size_t)(q0w + g + 8) * DD;
#pragma unroll
        for (int c = 0; c < 4; c++) {
            float2 v00 = *(const float2*)(r0p + c * 16 + 2 * t4);
            float2 v10 = *(const float2*)(r1p + c * 16 + 2 * t4);
            float2 v01 = *(const float2*)(r0p + c * 16 + 2 * t4 + 8);
            float2 v11 = *(const float2*)(r1p + c * 16 + 2 * t4 + 8);
            split2h(v00.x * 0.125f, v00.y * 0.125f, qh[c][0], ql[c][0]);
            split2h(v10.x * 0.125f, v10.y * 0.125f, qh[c][1], ql[c][1]);
            split2h(v01.x * 0.125f, v01.y * 0.125f, qh[c][2], ql[c][2]);
            split2h(v11.x * 0.125f, v11.y * 0.125f, qh[c][3], ql[c][3]);
        }
    }

    float O[8][4];
#pragma unroll
    for (int j = 0; j < 8; j++)
#pragma unroll
        for (int r = 0; r < 4; r++) O[j][r] = 0.f;
    float m0 = NEGINF, m1 = NEGINF, l0 = 0.f, l1 = 0.f;

    int b_r = (lane >> 4) * 8 + (lane & 7);
    int b_c = ((lane >> 3) & 1) * 8;
    int v_r = (lane & 7) + ((lane >> 3) & 1) * 8;
    int v_c = (lane >> 4) * 8;

    const __half* kb = karr + (size_t)(b * TT) * DD + h * HDIM;
    const __half* vb = varr + (size_t)(b * TT) * DD + h * HDIM;

    auto stage = [&](int t, int buf) {
        int kt = t * AKT;
#pragma unroll
        for (int i = 0; i < 4; i++) {
            int cid = tid + i * 256;
            int arr = cid >> 9;
            int sub = cid & 511;
            int kk = sub >> 3;
            int c8 = sub & 7;
            const __half* src = (arr ? vb : kb) + (size_t)(kt + kk) * DD + c8 * 8;
            uint32_t dst = (arr ? aV[buf] : aK[buf]) + (uint32_t)(kk * LDV + c8 * 8) * 2;
            cp16(dst, src);
        }
        asm volatile("cp.async.commit_group;\n" ::: "memory");
    };

    int ntiles = bx * 2 + 2;
    stage(0, 0);

    for (int tile = 0; tile < ntiles; tile++) {
        int buf = tile & 1;
        int kt = tile * AKT;
        if (tile + 1 < ntiles) {
            stage(tile + 1, buf ^ 1);
            asm volatile("cp.async.wait_group 1;\n" ::: "memory");
        } else {
            asm volatile("cp.async.wait_group 0;\n" ::: "memory");
        }
        __syncthreads();

        if (kt <= q0w + 15) {
            float S[8][4];
#pragma unroll
            for (int j = 0; j < 8; j++)
#pragma unroll
                for (int r = 0; r < 4; r++) S[j][r] = 0.f;

#pragma unroll
            for (int c = 0; c < 4; c++) {
                uint32_t kf[8][2];
#pragma unroll
                for (int p = 0; p < 4; p++) {
                    uint32_t r0, r1, r2, r3;
                    ldm_x4(r0, r1, r2, r3,
                           aK[buf] + (uint32_t)((16 * p + b_r) * LDV + 16 * c + b_c) * 2);
                    kf[2 * p][0] = r0; kf[2 * p][1] = r1;
                    kf[2 * p + 1][0] = r2; kf[2 * p + 1][1] = r3;
                }
#pragma unroll
                for (int j = 0; j < 8; j++) mma16816h(S[j], qh[c], kf[j]);
#pragma unroll
                for (int j = 0; j < 8; j++) mma16816h(S[j], ql[c], kf[j]);
            }

            if (kt + AKT - 1 > q0w) {
                int row0 = q0w + g, row1 = q0w + g + 8;
#pragma unroll
                for (int j = 0; j < 8; j++) {
                    int col = kt + 8 * j + 2 * t4;
                    if (col > row0)     S[j][0] = NEGINF;
                    if (col + 1 > row0) S[j][1] = NEGINF;
                    if (col > row1)     S[j][2] = NEGINF;
                    if (col + 1 > row1) S[j][3] = NEGINF;
                }
            }

            float mx0 = NEGINF, mx1 = NEGINF;
#pragma unroll
            for (int j = 0; j < 8; j++) {
                mx0 = fmaxf(mx0, fmaxf(S[j][0], S[j][1]));
                mx1 = fmaxf(mx1, fmaxf(S[j][2], S[j][3]));
            }
            mx0 = fmaxf(mx0, __shfl_xor_sync(0xffffffffu, mx0, 1));
            mx0 = fmaxf(mx0, __shfl_xor_sync(0xffffffffu, mx0, 2));
            mx1 = fmaxf(mx1, __shfl_xor_sync(0xffffffffu, mx1, 1));
            mx1 = fmaxf(mx1, __shfl_xor_sync(0xffffffffu, mx1, 2));
            float m0n = fmaxf(m0, mx0), m1n = fmaxf(m1, mx1);
            float c0 = __expf(m0 - m0n), c1 = __expf(m1 - m1n);
            float s0 = 0.f, s1 = 0.f;
#pragma unroll
            for (int j = 0; j < 8; j++) {
                S[j][0] = __expf(S[j][0] - m0n);
                S[j][1] = __expf(S[j][1] - m0n);
                S[j][2] = __expf(S[j][2] - m1n);
                S[j][3] = __expf(S[j][3] - m1n);
                s0 += S[j][0] + S[j][1];
                s1 += S[j][2] + S[j][3];
            }
            s0 += __shfl_xor_sync(0xffffffffu, s0, 1);
            s0 += __shfl_xor_sync(0xffffffffu, s0, 2);
            s1 += __shfl_xor_sync(0xffffffffu, s1, 1);
            s1 += __shfl_xor_sync(0xffffffffu, s1, 2);
            l0 = l0 * c0 + s0;
            l1 = l1 * c1 + s1;
            m0 = m0n; m1 = m1n;
#pragma unroll
            for (int j = 0; j < 8; j++) {
                O[j][0] *= c0; O[j][1] *= c0;
                O[j][2] *= c1; O[j][3] *= c1;
            }

#pragma unroll
            for (int kk = 0; kk < 4; kk++) {
                uint32_t ph[4], pl[4];
                split2h(S[2 * kk][0],     S[2 * kk][1],     ph[0], pl[0]);
                split2h(S[2 * kk][2],     S[2 * kk][3],     ph[1], pl[1]);
                split2h(S[2 * kk + 1][0], S[2 * kk + 1][1], ph[2], pl[2]);
                split2h(S[2 * kk + 1][2], S[2 * kk + 1][3], ph[3], pl[3]);

                uint32_t vf[8][2];
#pragma unroll
                for (int ds = 0; ds < 4; ds++) {
                    uint32_t r0, r1, r2, r3;
                    ldm_x4_t(r0, r1, r2, r3,
                             aV[buf] + (uint32_t)((16 * kk + v_r) * LDV + 16 * ds + v_c) * 2);
                    vf[2 * ds][0] = r0; vf[2 * ds][1] = r1;
                    vf[2 * ds + 1][0] = r2; vf[2 * ds + 1][1] = r3;
                }
#pragma unroll
                for (int j = 0; j < 8; j++) mma16816h(O[j], ph, vf[j]);
#pragma unroll
                for (int j = 0; j < 8; j++) mma16816h(O[j], pl, vf[j]);
            }
        }
        __syncthreads();   // all reads of buf done before tile+2 stages into it
    }

    // epilogue: y as fp16 hi/lo (consumed by fp16 proj GEMM)
    float i0 = 1.f / l0, i1 = 1.f / l1;
    size_t off0 = (size_t)(b * TT + q0w + g) * DD + h * HDIM + 2 * t4;
    size_t off1 = (size_t)(b * TT + q0w + g + 8) * DD + h * HDIM + 2 * t4;
#pragma unroll
    for (int j = 0; j < 8; j++) {
        uint32_t hh, ll;
        split2h(O[j][0] * i0, O[j][1] * i0, hh, ll);
        *(uint32_t*)(yhi + off0 + 8 * j) = hh;
        *(uint32_t*)(ylo + off0 + 8 * j) = ll;
        split2h(O[j][2] * i1, O[j][3] * i1, hh, ll);
        *(uint32_t*)(yhi + off1 + 8 * j) = hh;
        *(uint32_t*)(ylo + off1 + 8 * j) = ll;
    }
}

// ---------------------------------------------------------------------------
// Host launcher
// ---------------------------------------------------------------------------
extern "C" void kernel_launch(void* const* d_in, const int* in_sizes, int n_in,
                              void* d_out, int out_size) {
    const int*   idx    = (const int*)  d_in[0];
    const float* wte    = (const float*)d_in[1];
    const float* wpe    = (const float*)d_in[2];
    const float* ln1_s  = (const float*)d_in[3];
    const float* ln1_b  = (const float*)d_in[4];
    const float* qkv_w  = (const float*)d_in[5];
    const float* proj_w = (const float*)d_in[6];
    const float* ln2_s  = (const float*)d_in[7];
    const float* ln2_b  = (const float*)d_in[8];
    const float* fc_w   = (const float*)d_in[9];
    const float* fc_b   = (const float*)d_in[10];
    const float* fc2_w  = (const float*)d_in[11];
    const float* fc2_b  = (const float*)d_in[12];
    const float* lnf_s  = (const float*)d_in[13];
    const float* lnf_b  = (const float*)d_in[14];
    const float* lm_w   = (const float*)d_in[15];
    float* out = (float*)d_out;

    float *x, *qarr;
    bf16 *karr, *varr;
    bf16 *h_hi, *h_lo, *y_hi, *y_lo, *gg_hi, *gg_lo;
    bf16 *qw, *pw, *fw, *f2w, *lw;
    cudaGetSymbolAddress((void**)&x,     g_x);
    cudaGetSymbolAddress((void**)&qarr,  g_q);
    cudaGetSymbolAddress((void**)&karr,  g_k);
    cudaGetSymbolAddress((void**)&varr,  g_v);
    cudaGetSymbolAddress((void**)&h_hi,  g_h_hi);   cudaGetSymbolAddress((void**)&h_lo,  g_h_lo);
    cudaGetSymbolAddress((void**)&y_hi,  g_y_hi);   cudaGetSymbolAddress((void**)&y_lo,  g_y_lo);
    cudaGetSymbolAddress((void**)&gg_hi, g_g_hi);   cudaGetSymbolAddress((void**)&gg_lo, g_g_lo);
    cudaGetSymbolAddress((void**)&qw,  g_qkvw);
    cudaGetSymbolAddress((void**)&pw,  g_projw);
    cudaGetSymbolAddress((void**)&fw,  g_fcw);
    cudaGetSymbolAddress((void**)&f2w, g_fc2w);
    cudaGetSymbolAddress((void**)&lw,  g_lmw);

    cudaFuncSetAttribute((const void*)gemm2h<2, true>,
                         cudaFuncAttributeMaxDynamicSharedMemorySize, GSM2_MF2);
    cudaFuncSetAttribute((const void*)gemm2h<4, true>,
                         cudaFuncAttributeMaxDynamicSharedMemorySize, GSM2_MF4);
    cudaFuncSetAttribute((const void*)gemm2h<4, false>,
                         cudaFuncAttributeMaxDynamicSharedMemorySize, GSM1_MF4);

    embed_kernel<<<MM, 256>>>(idx, wte, wpe, x);

    {
        int nq = LL * 3 * DD * DD, np = LL * DD * DD;
        int nf = LL * 4 * DD * DD, n2 = LL * 4 * DD * DD, nl = VV * DD;
        int maxn = nf;
        dim3 grid((maxn / 4 + 255) / 256, 5);
        wsplit_all<<<grid, 256>>>(qkv_w,  qw,  nq,
                                  proj_w, pw,  np,
                                  fc_w,   fw,  nf,
                                  fc2_w,  f2w, n2,
                                  lm_w,   lw,  nl);
    }

    for (int l = 0; l < LL; l++) {
        const __half* qwh = (const __half*)(qw  + (size_t)l * 3 * DD * DD);
        const __half* pwh = (const __half*)(pw  + (size_t)l * DD * DD);
        const __half* fwh = (const __half*)(fw  + (size_t)l * 4 * DD * DD);
        const __half* f2h = (const __half*)(f2w + (size_t)l * 4 * DD * DD);
        const float* fb  = fc_b  + (size_t)l * 4 * DD;
        const float* f2b = fc2_b + (size_t)l * DD;

        ln_split_kernel<<<MM, 256>>>(x, ln1_s + l * DD, ln1_b + l * DD, h_hi, h_lo);
        // qkv: fp16 2-pass, MF=2, grid 24x32 = 768. Epilogue: q fp32, K/V fp16.
        gemm2h<2, true><<<dim3(3 * DD / BN, MM / 64), 256, GSM2_MF2>>>(
            (const __half*)h_hi, (const __half*)h_lo, qwh,
            nullptr, nullptr, qarr, nullptr, nullptr,
            (__half*)karr, (__half*)varr, MM, 3 * DD, DD, FLAG_QKV);
        attn_mma<<<dim3(TT / AQ, HH, BB), 256>>>(qarr, (const __half*)karr,
                                                 (const __half*)varr, y_hi, y_lo);
        // proj: fp16 2-pass, MF=2, grid 8x32 = 256
        gemm2h<2, true><<<dim3(DD / BN, MM / 64), 256, GSM2_MF2>>>(
            (const __half*)y_hi, (const __half*)y_lo, pwh,
            nullptr, x, x, nullptr, nullptr,
            nullptr, nullptr, MM, DD, DD, FLAG_RES);
        ln_split_kernel<<<MM, 256>>>(x, ln2_s + l * DD, ln2_b + l * DD, h_hi, h_lo);
        // fc: fp16 2-pass, MF=4, grid 32x16 = 512; gelu + fp16 split out
        gemm2h<4, true><<<dim3(4 * DD / BN, MM / 128), 256, GSM2_MF4>>>(
            (const __half*)h_hi, (const __half*)h_lo, fwh,
            fb, nullptr, nullptr, (__half*)gg_hi, (__half*)gg_lo,
            nullptr, nullptr, MM, 4 * DD, DD, FLAG_BIAS | FLAG_GELU | FLAG_SPLIT);
        // fc2: fp16 2-pass, MF=2, grid 8x32 = 256
        gemm2h<2, true><<<dim3(DD / BN, MM / 64), 256, GSM2_MF2>>>(
            (const __half*)gg_hi, (const __half*)gg_lo, f2h,
            f2b, x, x, nullptr, nullptr,
            nullptr, nullptr, MM, DD, 4 * DD, FLAG_BIAS | FLAG_RES);
    }

    // lnf -> fp16 hi/lo
    ln_split_kernel<<<MM, 256>>>(x, lnf_s, lnf_b, h_hi, h_lo);
    // lm: fp16 SINGLE-pass A, MF=4, grid 250x16 = 4000
    gemm2h<4, false><<<dim3(VV / BN, MM / 128), 256, GSM1_MF4>>>(
        (const __half*)h_hi, nullptr, (const __half*)lw,
        nullptr, nullptr, out, nullptr, nullptr,
        nullptr, nullptr, MM, VV, DD, 0);
}